// round 10
// baseline (speedup 1.0000x reference)
#include <cuda_runtime.h>
#include <cstdint>

// Problem constants
#define BB 16
#define CIN 1024
#define PP 512
#define NN 2048          // H*W
#define DH 128           // head dim
#define INVF 0.99999500003749969f      // 1/sqrt(1+1e-5)
#define QSCALE 0.08838834764831843f    // 128^-0.5
#define GRID_P 152                      // 76 clusters x 2 CTAs
#define NCL 76

#if defined(__CUDA_ARCH__) && (__CUDA_ARCH__ >= 1000) && \
    (defined(__CUDA_ARCH_FEAT_SM103_ALL) || defined(__CUDA_ARCH_FEAT_SM100_ALL) || \
     defined(__CUDA_ARCH_SPECIFIC__) || defined(__CUDA_ARCH_FAMILY_SPECIFIC__))
#define HAS_TCGEN05 1
#else
#define HAS_TCGEN05 0
#endif

// Scratch (device globals)
__device__ float g_xT [(size_t)BB * CIN * NN];   // [b][hw][c]  (tf32-rounded)
__device__ float g_o1T[(size_t)BB * PP * NN];    // [b][hw][p]  (tf32-rounded)
__device__ float g_qT [(size_t)BB * PP * NN];    // [b][hw][p]  (tf32-rounded)
__device__ float g_kT [(size_t)BB * PP * NN];    // [b][hw][p]  (tf32-rounded)
__device__ float g_v  [(size_t)BB * PP * NN];    // [b][p][hw]  (tf32-rounded)
__device__ float g_o2T[(size_t)BB * PP * NN];    // [b][hw][p]  (tf32-rounded)
// Rounded weights, contiguous: w1 | wq | wk | wv | w3
#define WR_W1 0
#define WR_WQ (512 * 1024)
#define WR_WK (WR_WQ + 512 * 512)
#define WR_WV (WR_WK + 512 * 512)
#define WR_W3 (WR_WV + 512 * 512)
__device__ float g_wr[WR_W3 + 1024 * 512];

// ---------------------------------------------------------------------------
__device__ __forceinline__ uint32_t smem_u32(const void* p) {
    uint32_t a;
    asm("{ .reg .u64 t; cvta.to.shared.u64 t, %1; cvt.u32.u64 %0, t; }"
        : "=r"(a) : "l"(p));
    return a;
}
__device__ __forceinline__ float to_tf32(float x) {
    float r; asm("cvt.rna.tf32.f32 %0, %1;" : "=f"(r) : "f"(x)); return r;
}

#if HAS_TCGEN05
__device__ __forceinline__ uint32_t elect1() {
    uint32_t p;
    asm volatile("{ .reg .pred p; elect.sync _|p, 0xFFFFFFFF; selp.b32 %0,1,0,p; }"
                 : "=r"(p));
    return p;
}
#define SW128(o) ((o) ^ ((((uint32_t)(o)) >> 3) & 0x70))

#define MBAR_INIT(a, c) \
    asm volatile("mbarrier.init.shared.b64 [%0], %1;" :: "r"(a), "r"(c) : "memory")

#define MBAR_ARRIVE(a) \
    asm volatile("mbarrier.arrive.shared::cta.b64 _, [%0];" :: "r"(a) : "memory")

// Arrive on the same-offset barrier in cluster CTA `tr`
#define MBAR_ARRIVE_CL(a, tr) \
    asm volatile("{ .reg .b32 ra; mapa.shared::cluster.u32 ra, %0, %1;\n\t" \
                 "mbarrier.arrive.release.cluster.shared::cluster.b64 _, [ra]; }" \
                 :: "r"(a), "r"(tr) : "memory")

#define MBAR_WAIT(a, ph) do { \
    uint32_t _d; \
    asm volatile("{ .reg .pred p; mbarrier.try_wait.parity.acquire.cta.shared::cta.b64 p,[%1],%2; selp.b32 %0,1,0,p; }" \
                 : "=r"(_d) : "r"(a), "r"((uint32_t)(ph)) : "memory"); \
    if (!_d) { \
        asm volatile("{ .reg .pred P;\nLW_%=:\nmbarrier.try_wait.parity.acquire.cta.shared::cta.b64 P,[%0],%1,0x989680;\n@P bra.uni LD_%=;\nbra.uni LW_%=;\nLD_%=:\n}" \
                     :: "r"(a), "r"((uint32_t)(ph)) : "memory"); \
    } } while (0)

#define CLUSTER_SYNC() do { \
    asm volatile("barrier.cluster.arrive.aligned;" ::: "memory"); \
    asm volatile("barrier.cluster.wait.aligned;" ::: "memory"); } while (0)

#define TM_ALLOC(sa, n) \
    asm volatile("tcgen05.alloc.cta_group::1.sync.aligned.shared::cta.b32 [%0], %1;" \
                 :: "r"(sa), "r"(n) : "memory")
#define TM_DEALLOC(t, n) \
    asm volatile("tcgen05.dealloc.cta_group::1.sync.aligned.b32 %0, %1;" :: "r"(t), "r"(n))
#define TM_ALLOC2(sa, n) \
    asm volatile("tcgen05.alloc.cta_group::2.sync.aligned.shared::cta.b32 [%0], %1;" \
                 :: "r"(sa), "r"(n) : "memory")
#define TM_DEALLOC2(t, n) \
    asm volatile("tcgen05.dealloc.cta_group::2.sync.aligned.b32 %0, %1;" :: "r"(t), "r"(n))
#define TM_COMMIT(mb) \
    asm volatile("tcgen05.commit.cta_group::1.mbarrier::arrive::one.shared::cluster.b64 [%0];" \
                 :: "r"(mb) : "memory")
#define TM_COMMIT2_MC(mb, mask) \
    asm volatile("tcgen05.commit.cta_group::2.mbarrier::arrive::one.shared::cluster.multicast::cluster.b64 [%0], %1;" \
                 :: "r"(mb), "h"((uint16_t)(mask)) : "memory")
#define TM_FENCE_AFTER()  asm volatile("tcgen05.fence::after_thread_sync;" ::: "memory")
#define TM_FENCE_BEFORE() asm volatile("tcgen05.fence::before_thread_sync;" ::: "memory")
#define TM_WAIT_LD()      asm volatile("tcgen05.wait::ld.sync.aligned;" ::: "memory")
#define TM_WAIT_ST()      asm volatile("tcgen05.wait::st.sync.aligned;" ::: "memory")
#define FENCE_ASYNC()     asm volatile("fence.proxy.async.shared::cta;" ::: "memory")

#define CP_ASYNC16(dst, src) \
    asm volatile("cp.async.cg.shared.global [%0], [%1], 16;" \
                 :: "r"(dst), "l"(src) : "memory")
#define CP_MBAR_ARRIVE(mb) \
    asm volatile("cp.async.mbarrier.arrive.noinc.shared::cta.b64 [%0];" \
                 :: "r"(mb) : "memory")

#define TM_LD_X32(r, addr) \
    asm volatile("tcgen05.ld.sync.aligned.32x32b.x32.b32 " \
        "{%0,%1,%2,%3,%4,%5,%6,%7,%8,%9,%10,%11,%12,%13,%14,%15," \
        "%16,%17,%18,%19,%20,%21,%22,%23,%24,%25,%26,%27,%28,%29,%30,%31}, [%32];" \
        : "=r"((r)[0]),"=r"((r)[1]),"=r"((r)[2]),"=r"((r)[3]), \
          "=r"((r)[4]),"=r"((r)[5]),"=r"((r)[6]),"=r"((r)[7]), \
          "=r"((r)[8]),"=r"((r)[9]),"=r"((r)[10]),"=r"((r)[11]), \
          "=r"((r)[12]),"=r"((r)[13]),"=r"((r)[14]),"=r"((r)[15]), \
          "=r"((r)[16]),"=r"((r)[17]),"=r"((r)[18]),"=r"((r)[19]), \
          "=r"((r)[20]),"=r"((r)[21]),"=r"((r)[22]),"=r"((r)[23]), \
          "=r"((r)[24]),"=r"((r)[25]),"=r"((r)[26]),"=r"((r)[27]), \
          "=r"((r)[28]),"=r"((r)[29]),"=r"((r)[30]),"=r"((r)[31]) \
        : "r"(addr))

#define TM_ST_X32(addr, r) \
    asm volatile("tcgen05.st.sync.aligned.32x32b.x32.b32 [%0], " \
        "{%1,%2,%3,%4,%5,%6,%7,%8,%9,%10,%11,%12,%13,%14,%15,%16," \
        "%17,%18,%19,%20,%21,%22,%23,%24,%25,%26,%27,%28,%29,%30,%31,%32};" \
        :: "r"(addr), \
           "r"((r)[0]),"r"((r)[1]),"r"((r)[2]),"r"((r)[3]), \
           "r"((r)[4]),"r"((r)[5]),"r"((r)[6]),"r"((r)[7]), \
           "r"((r)[8]),"r"((r)[9]),"r"((r)[10]),"r"((r)[11]), \
           "r"((r)[12]),"r"((r)[13]),"r"((r)[14]),"r"((r)[15]), \
           "r"((r)[16]),"r"((r)[17]),"r"((r)[18]),"r"((r)[19]), \
           "r"((r)[20]),"r"((r)[21]),"r"((r)[22]),"r"((r)[23]), \
           "r"((r)[24]),"r"((r)[25]),"r"((r)[26]),"r"((r)[27]), \
           "r"((r)[28]),"r"((r)[29]),"r"((r)[30]),"r"((r)[31]) \
        : "memory")

__device__ __forceinline__ uint64_t mkdesc(uint32_t addr) {
    return ((uint64_t)2 << 61) | ((uint64_t)1 << 46) | ((uint64_t)64 << 32) |
           ((uint64_t)1 << 16) | ((addr >> 4) & 0x3FFF);
}
__device__ __forceinline__ void mma_ss(uint32_t d, uint64_t ad, uint64_t bd,
                                       uint32_t id, uint32_t en) {
    asm volatile(
        "{ .reg .pred p; setp.ne.u32 p, %5, 0;\n\t"
        "tcgen05.mma.cta_group::1.kind::tf32 [%0], %1, %2, %3, {%4,%4,%4,%4}, p;\n\t}"
        :: "r"(d), "l"(ad), "l"(bd), "r"(id), "r"(0u), "r"(en) : "memory");
}
__device__ __forceinline__ void mma_ss2(uint32_t d, uint64_t ad, uint64_t bd,
                                        uint32_t id, uint32_t en) {
    asm volatile(
        "{ .reg .pred p; setp.ne.u32 p, %5, 0;\n\t"
        "tcgen05.mma.cta_group::2.kind::tf32 [%0], %1, %2, %3, {%4,%4,%4,%4,%4,%4,%4,%4}, p;\n\t}"
        :: "r"(d), "l"(ad), "l"(bd), "r"(id), "r"(0u), "r"(en) : "memory");
}
__device__ __forceinline__ void mma_ts(uint32_t d, uint32_t a, uint64_t bd,
                                       uint32_t id, uint32_t en) {
    asm volatile(
        "{ .reg .pred p; setp.ne.u32 p, %5, 0;\n\t"
        "tcgen05.mma.cta_group::1.kind::tf32 [%0], [%1], %2, %3, {%4,%4,%4,%4}, p;\n\t}"
        :: "r"(d), "r"(a), "l"(bd), "r"(id), "r"(0u), "r"(en) : "memory");
}
#define IDESC_128 ((1u << 4) | (2u << 7) | (2u << 10) | (16u << 17) | (8u << 24))
#define IDESC_256 ((1u << 4) | (2u << 7) | (2u << 10) | (32u << 17) | (8u << 24))
#define IDESC_CG2 ((1u << 4) | (2u << 7) | (2u << 10) | (32u << 17) | (16u << 24))
#endif  // HAS_TCGEN05

// ---------------------------------------------------------------------------
// Round all 5 weight matrices to tf32 in one launch, into contiguous g_wr
// ---------------------------------------------------------------------------
#define N4_W1 131072
#define N4_P  65536
#define N4_W3 131072
#define N4_TOT (N4_W1 + 3 * N4_P + N4_W3)

__global__ __launch_bounds__(256)
void round_w5(const float* __restrict__ w1, const float* __restrict__ wq,
              const float* __restrict__ wk, const float* __restrict__ wv,
              const float* __restrict__ w3, float* __restrict__ out)
{
    int i = blockIdx.x * 256 + threadIdx.x;
    if (i >= N4_TOT) return;
    const float4* src;
    int j = i;
    if (j < N4_W1) src = (const float4*)w1;
    else if ((j -= N4_W1) < N4_P) src = (const float4*)wq;
    else if ((j -= N4_P) < N4_P) src = (const float4*)wk;
    else if ((j -= N4_P) < N4_P) src = (const float4*)wv;
    else { j -= N4_P; src = (const float4*)w3; }
    float4 v = src[j];
    v.x = to_tf32(v.x); v.y = to_tf32(v.y);
    v.z = to_tf32(v.z); v.w = to_tf32(v.w);
    ((float4*)out)[i] = v;
}

// ---------------------------------------------------------------------------
// Tiled transpose per batch with tf32 rounding: in[b][R][C] -> out[b][C][R]
// ---------------------------------------------------------------------------
__global__ __launch_bounds__(256)
void transpose_k(const float* __restrict__ in, float* __restrict__ out, int R, int C)
{
    __shared__ float tile[32][33];
    const int b = blockIdx.z;
    const float* ip = in + (size_t)b * R * C;
    float* op = out + (size_t)b * R * C;
    const int c0 = blockIdx.x * 32, r0 = blockIdx.y * 32;
    const int tx = threadIdx.x & 31, ty = threadIdx.x >> 5;
#pragma unroll
    for (int i = 0; i < 32; i += 8)
        tile[ty + i][tx] = ip[(size_t)(r0 + ty + i) * C + c0 + tx];
    __syncthreads();
#pragma unroll
    for (int i = 0; i < 32; i += 8)
        op[(size_t)(c0 + ty + i) * R + r0 + tx] = to_tf32(tile[tx][ty + i]);
}

// ---------------------------------------------------------------------------
// cta_group::2 warp-specialized persistent tf32 GEMM (cluster = 2 CTAs).
// 256m x 256n tiles: each CTA loads A-half (its 128 m-rows) + B-half (its 128
// n-rows) = 32KB/chunk (was 48KB) -> chip LTS traffic x 2/3.
// Leader (rank0) issues cg2 MMAs; commit multicasts to both CTAs' mma[s].
// rank1 forwards stage-readiness (fullR) and epilogue-done (peerepi) to the
// leader via cluster arrives. Consumers (warps 4-7) drain local TMEM rows.
// MODE 0: conv1 -> o1T[hw][p] (bn1+relu, rnd)
// MODE 1: qkv: pid<512 -> qT/kT[hw][p] ; pid>=512 (flipped) -> v[p][hw]
// MODE 2: conv3 (flipped) -> out[c][hw] (bn3 + resid + relu)
// ---------------------------------------------------------------------------
#define STAGE_B 32768u
#define GS_BN   (1024u + 4 * STAGE_B)               // 132096
#define GSMEM   (GS_BN + 2 * 1024 * 4)              // 140288 B

template <int MODE>
__device__ __forceinline__ void pair_ab(int pid, int r, const float* W,
                                        const float* ACT,
                                        const float*& A, const float*& B)
{
    if (MODE == 0) {
        int mp = pid & 1, n0 = ((pid >> 1) & 7) << 8, bz = pid >> 4;
        A = W + (size_t)((2 * mp + r) << 7) * 1024;
        B = ACT + ((size_t)bz * NN + n0 + r * 128) * 1024;
    } else if (MODE == 1) {
        if (pid < 512) {
            int mp = pid & 3, n0 = ((pid >> 2) & 7) << 8, bz = pid >> 5;
            A = W + (size_t)((2 * mp + r) << 7) * 512;
            B = ACT + ((size_t)bz * NN + n0 + r * 128) * 512;
        } else {
            int j = pid - 512;
            int mp = j & 7, n0 = ((j >> 3) & 1) << 8, bz = j >> 4;
            A = ACT + ((size_t)bz * NN + ((2 * mp + r) << 7)) * 512;
            B = W + 524288u + (size_t)(n0 + r * 128) * 512;
        }
    } else {
        int mp = pid & 7, n0 = ((pid >> 3) & 3) << 8, bz = pid >> 5;
        A = ACT + ((size_t)bz * NN + ((2 * mp + r) << 7)) * 512;
        B = W + (size_t)(n0 + r * 128) * 512;
    }
}

#if HAS_TCGEN05
// Producer feed: 128 threads load A-half + B-half (32KB) for one chunk
template <int MODE>
__device__ __forceinline__ void issue_chunk(uint32_t sbase, int gc, int cid,
                                            int rank, const float* W,
                                            const float* ACT, int t)
{
    constexpr int NKS = (MODE == 0) ? 5 : 4;
    constexpr int K = (MODE == 0) ? 1024 : 512;
    const int lt = gc >> NKS, c = gc & ((1 << NKS) - 1);
    const float *A, *B;
    pair_ab<MODE>(cid + lt * NCL, rank, W, ACT, A, B);
    const uint32_t st = sbase + 1024u + (uint32_t)(gc & 3) * STAGE_B;
#pragma unroll
    for (int r = 0; r < 8; r++) {               // A-half: 128 x 32
        int idx = t + r * 128, row = idx >> 3, seg = idx & 7;
        CP_ASYNC16(st + SW128(row * 128 + seg * 16),
                   A + (size_t)row * K + c * 32 + seg * 4);
    }
#pragma unroll
    for (int r = 0; r < 8; r++) {               // B-half: 128 x 32
        int idx = t + r * 128, row = idx >> 3, seg = idx & 7;
        CP_ASYNC16(st + 16384u + SW128(row * 128 + seg * 16),
                   B + (size_t)row * K + c * 32 + seg * 4);
    }
    CP_MBAR_ARRIVE(sbase + 16 + 8 * (gc & 3));
}

// Consumer epilogue: 4 warps drain this CTA's 128 rows x 256 cols buffer
template <int MODE>
__device__ __forceinline__ void epi_tile(int pid, int rank, int abuf,
    uint32_t tmem, char* smem,
    float* O0, float* O1, float* O2, const float* resid,
    const float* g, const float* be, const float* cb, int wid, int lane)
{
    float* Ob; const float* Rb = nullptr;
    size_t sN; int n0g = 0, m0;
    float qs = 1.f;
    if (MODE == 0) {
        int mp = pid & 1, n0 = ((pid >> 1) & 7) << 8, bz = pid >> 4;
        m0 = (2 * mp + rank) << 7;
        Ob = O0 + ((size_t)bz * NN + n0) * 512 + m0;  sN = 512;
    } else if (MODE == 1) {
        if (pid < 512) {
            int mp = pid & 3, n0 = ((pid >> 2) & 7) << 8, bz = pid >> 5;
            m0 = (2 * mp + rank) << 7;
            float* T = (m0 < 512) ? O0 : O1;
            if (m0 < 512) qs = QSCALE;
            Ob = T + ((size_t)bz * NN + n0) * 512 + (m0 & 511);  sN = 512;
        } else {
            int j = pid - 512;
            int mp = j & 7, n0 = ((j >> 3) & 1) << 8, bz = j >> 4;
            m0 = (2 * mp + rank) << 7;
            Ob = O2 + ((size_t)bz * 512 + n0) * NN + m0;  sN = NN;
        }
    } else {
        int mp = pid & 7, n0 = ((pid >> 3) & 3) << 8, bz = pid >> 5;
        m0 = (2 * mp + rank) << 7;
        Ob = O0 + ((size_t)bz * 1024 + n0) * NN + m0;
        Rb = resid + ((size_t)bz * 1024 + n0) * NN + m0;
        sN = NN; n0g = n0;
    }
    const int ml = (wid & 3) * 32 + lane;
    float sL = qs, tL = 0.f;
    if (MODE == 0) { int m = m0 + ml; sL = g[m] * INVF; tL = cb[m] * sL + be[m]; }
    const float* bs = (const float*)(smem + GS_BN);
    const float* bt = (const float*)(smem + GS_BN + 4096);

    uint32_t r0[32];
#pragma unroll
    for (int k = 0; k < 8; k++) {
        TM_LD_X32(r0, tmem + abuf * 256 + k * 32);
        TM_WAIT_LD();
#pragma unroll
        for (int i = 0; i < 32; i++) {
            const int n = k * 32 + i;
            float v = __uint_as_float(r0[i]);
            if (MODE == 2)
                v = fmaxf(fmaf(v, bs[n0g + n], bt[n0g + n]) + Rb[(size_t)n * sN + ml], 0.f);
            else if (MODE == 0)
                v = to_tf32(fmaxf(fmaf(v, sL, tL), 0.f));
            else
                v = to_tf32(v * sL);
            Ob[(size_t)n * sN + ml] = v;
        }
    }
}
#endif  // HAS_TCGEN05

template <int MODE>
__global__ __launch_bounds__(256)
void tgp(const float* __restrict__ W, const float* __restrict__ ACT,
         float* __restrict__ O0, float* __restrict__ O1, float* __restrict__ O2,
         const float* __restrict__ resid,
         const float* __restrict__ g, const float* __restrict__ be,
         const float* __restrict__ cb)
{
    constexpr int NPAIR = (MODE == 0) ? 256 : (MODE == 1) ? 768 : 512;
    constexpr int NKS   = (MODE == 0) ? 5 : 4;
    constexpr int NK    = 1 << NKS;
    const int t = threadIdx.x;
    const int rank = blockIdx.x & 1;
    const int cid = blockIdx.x >> 1;
    const int ntl = (NPAIR - cid + NCL - 1) / NCL;   // >= 3 for all modes
    const int totc = ntl * NK;

#if HAS_TCGEN05
    extern __shared__ char smem[];
    const uint32_t sbase = smem_u32(smem);
    const int wid = t >> 5, lane = t & 31;
    // mbar layout: fullL[4]@16(128)  mma[4]@48(1)  tiledone[2]@80(1)
    //              epifree[2]@96(128)  fullR[4]@112(1)  peerepi[2]@144(1)
    if (t < 4)        MBAR_INIT(sbase + 16 + 8 * t, 128);
    else if (t < 8)   MBAR_INIT(sbase + 48 + 8 * (t - 4), 1);
    else if (t < 10)  MBAR_INIT(sbase + 80 + 8 * (t - 8), 1);
    else if (t < 12)  MBAR_INIT(sbase + 96 + 8 * (t - 10), 128);
    else if (t < 16)  MBAR_INIT(sbase + 112 + 8 * (t - 12), 1);
    else if (t < 18)  MBAR_INIT(sbase + 144 + 8 * (t - 16), 1);
    if (wid == 0) TM_ALLOC2(sbase + 0, 512);
    if (MODE == 2) {
        for (int i = t; i < 1024; i += 256) {
            float s = g[i] * INVF;
            ((float*)(smem + GS_BN))[i] = s;
            ((float*)(smem + GS_BN + 4096))[i] = cb[i] * s + be[i];
        }
    }
    __syncthreads();
    CLUSTER_SYNC();   // peer barriers must exist before any cluster arrive/commit
    uint32_t tmem;
    asm volatile("ld.shared.b32 %0, [%1];" : "=r"(tmem) : "r"(sbase + 0));

    if (t < 128) {
        // ----------------- producers (warps 0-3) -----------------
        issue_chunk<MODE>(sbase, 0, cid, rank, W, ACT, t);
        issue_chunk<MODE>(sbase, 1, cid, rank, W, ACT, t);
        issue_chunk<MODE>(sbase, 2, cid, rank, W, ACT, t);

        for (int gc = 0; gc < totc; gc++) {
            const int s = gc & 3, c = gc & (NK - 1), lt = gc >> NKS;
            if (wid == 0 && elect1()) {
                if (rank == 0) {
                    if (c == 0 && lt >= 2) {   // accumulator-buffer WAR (both CTAs)
                        MBAR_WAIT(sbase + 96 + 8 * (lt & 1), ((lt >> 1) - 1) & 1);
                        MBAR_WAIT(sbase + 144 + 8 * (lt & 1), ((lt >> 1) - 1) & 1);
                        TM_FENCE_AFTER();
                    }
                    MBAR_WAIT(sbase + 16 + 8 * s, (gc >> 2) & 1);    // local data
                    MBAR_WAIT(sbase + 112 + 8 * s, (gc >> 2) & 1);   // peer data
                    FENCE_ASYNC();
                    const uint32_t st = sbase + 1024u + (uint32_t)s * STAGE_B;
                    const uint64_t ad = mkdesc(st);
                    const uint64_t bd = mkdesc(st + 16384u);
                    const uint32_t dacc = tmem + (uint32_t)((lt & 1) << 8);
#pragma unroll
                    for (int si = 0; si < 4; si++)
                        mma_ss2(dacc, ad + si * 2, bd + si * 2, IDESC_CG2,
                                (c > 0 || si > 0) ? 1u : 0u);
                    TM_COMMIT2_MC(sbase + 48 + 8 * s, 0x3);
                } else {
                    if (c == 0 && lt >= 2) {   // forward local epilogue-done
                        MBAR_WAIT(sbase + 96 + 8 * (lt & 1), ((lt >> 1) - 1) & 1);
                        MBAR_ARRIVE_CL(sbase + 144 + 8 * (lt & 1), 0);
                    }
                    MBAR_WAIT(sbase + 16 + 8 * s, (gc >> 2) & 1);    // local data
                    FENCE_ASYNC();
                    MBAR_ARRIVE_CL(sbase + 112 + 8 * s, 0);          // tell leader
                }
            }
            if (gc >= 1) {
                MBAR_WAIT(sbase + 48 + 8 * ((gc - 1) & 3), ((gc - 1) >> 2) & 1);
                if (c == 0 && wid == 0 && elect1())
                    MBAR_ARRIVE(sbase + 80 + 8 * ((lt - 1) & 1));    // tile done
            }
            if (gc + 3 < totc) issue_chunk<MODE>(sbase, gc + 3, cid, rank, W, ACT, t);
        }
        MBAR_WAIT(sbase + 48 + 8 * ((totc - 1) & 3), ((totc - 1) >> 2) & 1);
        if (wid == 0 && elect1())
            MBAR_ARRIVE(sbase + 80 + 8 * ((ntl - 1) & 1));
    } else {
        // ----------------- consumers (warps 4-7) -----------------
        for (int lt = 0; lt < ntl; lt++) {
            MBAR_WAIT(sbase + 80 + 8 * (lt & 1), (lt >> 1) & 1);
            TM_FENCE_AFTER();
            epi_tile<MODE>(cid + lt * NCL, rank, lt & 1, tmem, smem,
                           O0, O1, O2, resid, g, be, cb, wid, lane);
            TM_FENCE_BEFORE();
            MBAR_ARRIVE(sbase + 96 + 8 * (lt & 1));
        }
    }
    __syncthreads();
    CLUSTER_SYNC();   // all cross-CTA traffic drained
    if (wid == 0) TM_DEALLOC2(tmem, 512);
    CLUSTER_SYNC();

#else  // ---------------- fp32 fallback (never runs on GB300) ---------------
    constexpr int K = (MODE == 0) ? 1024 : 512;
    for (int lt = 0; lt < ntl; lt++) {
        const int pid = cid + lt * NCL;
        const float *A, *Bb, *dumA, *B0;
        pair_ab<MODE>(pid, rank, W, ACT, A, Bb);     // A for this rank
        pair_ab<MODE>(pid, 0, W, ACT, dumA, B0);     // B base (n0 + 0)
        for (int e = t; e < 128 * 256; e += 256) {
            const int ml = e & 127, n = e >> 7;
            float acc = 0.f;
            for (int k = 0; k < K; k++)
                acc += A[(size_t)ml * K + k] * B0[(size_t)n * K + k];
            // reuse epi_tile's addressing via scalar store
            if (MODE == 0) {
                int mp = pid & 1, n0 = ((pid >> 1) & 7) << 8, bz = pid >> 4;
                int m = ((2 * mp + rank) << 7) + ml;
                float s = g[m] * INVF, tt = cb[m] * s + be[m];
                O0[((size_t)bz * NN + n0 + n) * 512 + m] =
                    to_tf32(fmaxf(fmaf(acc, s, tt), 0.f));
            } else if (MODE == 1) {
                if (pid < 512) {
                    int mp = pid & 3, n0 = ((pid >> 2) & 7) << 8, bz = pid >> 5;
                    int m0 = (2 * mp + rank) << 7;
                    float* T = (m0 < 512) ? O0 : O1;
                    float qsc = (m0 < 512) ? QSCALE : 1.f;
                    T[((size_t)bz * NN + n0 + n) * 512 + ((m0 + ml) & 511)] =
                        to_tf32(acc * qsc);
                } else {
                    int j = pid - 512;
                    int mp = j & 7, n0 = ((j >> 3) & 1) << 8, bz = j >> 4;
                    O2[((size_t)bz * 512 + n0 + n) * NN + ((2 * mp + rank) << 7) + ml] =
                        to_tf32(acc);
                }
            } else {
                int mp = pid & 7, n0 = ((pid >> 3) & 3) << 8, bz = pid >> 5;
                int cch = n0 + n;
                float s = g[cch] * INVF, tt = cb[cch] * s + be[cch];
                size_t off = ((size_t)bz * 1024 + cch) * NN + ((2 * mp + rank) << 7) + ml;
                O0[off] = fmaxf(fmaf(acc, s, tt) + resid[off], 0.f);
            }
        }
    }
#endif
}

// ---------------------------------------------------------------------------
// tcgen05 attention (verified) + tf32-rounded o2T output
// ---------------------------------------------------------------------------
#define AS_Q   2048u
#define AS_KV0 (2048u + 65536u)
#define AS_KV1 (2048u + 65536u + 32768u)
#define ASMEM  133120

__global__ __launch_bounds__(128)
void attn_tc(const float* __restrict__ qT, const float* __restrict__ kT,
             const float* __restrict__ v, const float* __restrict__ o1T,
             const float* __restrict__ g2, const float* __restrict__ be2,
             float* __restrict__ o2T)
{
    extern __shared__ char sm[];
    const int t = threadIdx.x, wid = t >> 5, lane = t & 31;
    const int xt = blockIdx.x;
    const int sp = blockIdx.y >> 2, hh = blockIdx.y & 3;
    const int b = blockIdx.z;

    const size_t qrow = (size_t)b * NN + sp * 256 + xt * 128;
    const float* qp  = qT  + qrow * PP + hh * DH;
    const float* kp  = kT  + ((size_t)b * NN + sp * 256) * PP + hh * DH;
    const float* vp  = v   + ((size_t)b * PP + hh * DH) * NN + sp * 256;
    const float* o1p = o1T + qrow * PP + hh * DH;
    float* o2p       = o2T + qrow * PP + hh * DH;

#if HAS_TCGEN05
    const uint32_t sbase = smem_u32(sm);
    if (t == 0) { MBAR_INIT(sbase + 16, 1); MBAR_INIT(sbase + 24, 1); }
    if (wid == 0) TM_ALLOC(sbase + 0, 512);
    ((float*)(sm + 1024))[t] = g2[hh * DH + t] * INVF;
    ((float*)(sm + 1536))[t] = be2[hh * DH + t];
    __syncthreads();
    uint32_t tmem;
    asm volatile("ld.shared.b32 %0, [%1];" : "=r"(tmem) : "r"(sbase + 0));
    const uint32_t kvoff[2] = {AS_KV0, AS_KV1};

#pragma unroll
    for (int r = 0; r < 32; r++) {
        int i = t + r * 128;
        int row = i >> 5, rem = i & 31, j = rem >> 3, seg = rem & 7;
        float4 vq = *(const float4*)(qp + (size_t)row * PP + j * 32 + seg * 4);
        *(float4*)(sm + AS_Q + j * 16384 + SW128(row * 128 + seg * 16)) = vq;
    }

    float4 kv[16];
#pragma unroll
    for (int r = 0; r < 16; r++) {
        int i = t + r * 128, row = i >> 3, seg = i & 7;
        kv[r] = *(const float4*)(kp + (size_t)row * PP + seg * 4);
    }
    for (int c = 0; c < 4; c++) {
        const int buf = c & 1;
        const uint32_t mb = sbase + 16 + 8 * buf;
        if (c >= 2) MBAR_WAIT(mb, 0);
#pragma unroll
        for (int r = 0; r < 16; r++) {
            int i = t + r * 128, row = i >> 3, seg = i & 7;
            *(float4*)(sm + kvoff[buf] + SW128(row * 128 + seg * 16)) = kv[r];
        }
        if (c < 3) {
#pragma unroll
            for (int r = 0; r < 16; r++) {
                int i = t + r * 128, row = i >> 3, seg = i & 7;
                kv[r] = *(const float4*)(kp + (size_t)row * PP + (c + 1) * 32 + seg * 4);
            }
        }
        __syncthreads();
        if (wid == 0 && elect1()) {
            FENCE_ASYNC();
            uint64_t qd = mkdesc(sbase + AS_Q + c * 16384);
            uint64_t kd = mkdesc(sbase + kvoff[buf]);
#pragma unroll
            for (int s = 0; s < 4; s++)
                mma_ss(tmem, qd + s * 2, kd + s * 2, IDESC_256,
                       (c > 0 || s > 0) ? 1u : 0u);
            TM_COMMIT(mb);
        }
    }
    MBAR_WAIT(sbase + 24, 1);
    TM_FENCE_AFTER();

    uint32_t rs[32];
    float mx = -1e30f;
#pragma unroll
    for (int cc = 0; cc < 8; cc++) {
        TM_LD_X32(rs, tmem + cc * 32);
        TM_WAIT_LD();
#pragma unroll
        for (int i = 0; i < 32; i++) mx = fmaxf(mx, __uint_as_float(rs[i]));
    }
    float ssum = 0.f;
#pragma unroll
    for (int cc = 0; cc < 8; cc++) {
        TM_LD_X32(rs, tmem + cc * 32);
        TM_WAIT_LD();
#pragma unroll
        for (int i = 0; i < 32; i++) {
            float e = __expf(__uint_as_float(rs[i]) - mx);
            ssum += e;
            rs[i] = __float_as_uint(e);
        }
        TM_ST_X32(tmem + cc * 32, rs);
    }
    TM_WAIT_ST();
    const float sinv = 1.f / ssum;
    TM_FENCE_BEFORE();

#pragma unroll
    for (int r = 0; r < 16; r++) {
        int i = t + r * 128, row = i >> 4, seg = i & 15;
        kv[r] = *(const float4*)(vp + (size_t)row * NN + seg * 4);
    }
    for (int j = 0; j < 4; j++) {
        const int buf = j & 1;
        const uint32_t mb = sbase + 16 + 8 * buf;
        if (j >= 2) MBAR_WAIT(mb, 0);
#pragma unroll
        for (int r = 0; r < 16; r++) {
            int i = t + r * 128, row = i >> 4, seg = i & 15;
            *(float4*)(sm + kvoff[buf] + (seg >> 3) * 16384 +
                       SW128(row * 128 + (seg & 7) * 16)) = kv[r];
        }
        if (j < 3) {
#pragma unroll
            for (int r = 0; r < 16; r++) {
                int i = t + r * 128, row = i >> 4, seg = i & 15;
                kv[r] = *(const float4*)(vp + (size_t)row * NN + (j + 1) * 64 + seg * 4);
            }
        }
        __syncthreads();
        if (wid == 0 && elect1()) {
            FENCE_ASYNC();
            TM_FENCE_AFTER();
            uint64_t vd = mkdesc(sbase + kvoff[buf]);
#pragma unroll
            for (int s = 0; s < 8; s++)
                mma_ts(tmem + 256, tmem + j * 64 + s * 8,
                       vd + (s >> 2) * 1024 + (s & 3) * 2, IDESC_128,
                       (j > 0 || s > 0) ? 1u : 0u);
            TM_COMMIT(mb);
        }
    }
    MBAR_WAIT(sbase + 24, 1);
    TM_FENCE_AFTER();

    const float* g2s  = (const float*)(sm + 1024);
    const float* be2s = (const float*)(sm + 1536);
    const float* myo1 = o1p + (size_t)(wid * 32 + lane) * PP;
    float* myo2       = o2p + (size_t)(wid * 32 + lane) * PP;
#pragma unroll
    for (int k = 0; k < 4; k++) {
        TM_LD_X32(rs, tmem + 256 + k * 32);
        TM_WAIT_LD();
#pragma unroll
        for (int i = 0; i < 32; i += 4) {
            int d = k * 32 + i;
            float4 r1 = *(const float4*)(myo1 + d);
            float4 o;
            o.x = to_tf32(fmaxf(fmaf(fmaf(__uint_as_float(rs[i + 0]), sinv, r1.x), g2s[d + 0], be2s[d + 0]), 0.f));
            o.y = to_tf32(fmaxf(fmaf(fmaf(__uint_as_float(rs[i + 1]), sinv, r1.y), g2s[d + 1], be2s[d + 1]), 0.f));
            o.z = to_tf32(fmaxf(fmaf(fmaf(__uint_as_float(rs[i + 2]), sinv, r1.z), g2s[d + 2], be2s[d + 2]), 0.f));
            o.w = to_tf32(fmaxf(fmaf(fmaf(__uint_as_float(rs[i + 3]), sinv, r1.w), g2s[d + 3], be2s[d + 3]), 0.f));
            *(float4*)(myo2 + d) = o;
        }
    }
    __syncthreads();
    if (wid == 0) TM_DEALLOC(tmem, 512);

#else  // ---------------- fp32 fallback (never runs on GB300) ---------------
    const int x = t;
    float sb[256];
    float mx = -1e30f;
    for (int y = 0; y < 256; y++) {
        float s = 0.f;
        for (int d = 0; d < DH; d++)
            s += qp[(size_t)x * PP + d] * kp[(size_t)y * PP + d];
        sb[y] = s;
        mx = fmaxf(mx, s);
    }
    float ssum = 0.f;
    for (int y = 0; y < 256; y++) { sb[y] = __expf(sb[y] - mx); ssum += sb[y]; }
    float sinv = 1.f / ssum;
    for (int d = 0; d < DH; d++) {
        float o = 0.f;
        for (int y = 0; y < 256; y++) o += sb[y] * vp[(size_t)d * NN + y];
        float val = (o * sinv + o1p[(size_t)x * PP + d]) * (g2[hh * DH + d] * INVF)
                    + be2[hh * DH + d];
        o2p[(size_t)x * PP + d] = to_tf32(fmaxf(val, 0.f));
    }
#endif
}

// ---------------------------------------------------------------------------
extern "C" void kernel_launch(void* const* d_in, const int* in_sizes, int n_in,
                              void* d_out, int out_size)
{
    const float* x   = (const float*)d_in[0];
    const float* w1  = (const float*)d_in[1];
    const float* b1  = (const float*)d_in[2];
    const float* g1  = (const float*)d_in[3];
    const float* be1 = (const float*)d_in[4];
    const float* wq  = (const float*)d_in[5];
    const float* wk  = (const float*)d_in[6];
    const float* wv  = (const float*)d_in[7];
    const float* g2  = (const float*)d_in[8];
    const float* be2 = (const float*)d_in[9];
    const float* w3  = (const float*)d_in[10];
    const float* b3  = (const float*)d_in[11];
    const float* g3  = (const float*)d_in[12];
    const float* be3 = (const float*)d_in[13];
    float* out = (float*)d_out;

    float *xT, *o1T, *qT, *kT, *vb, *o2T, *wr;
    cudaGetSymbolAddress((void**)&xT,  g_xT);
    cudaGetSymbolAddress((void**)&o1T, g_o1T);
    cudaGetSymbolAddress((void**)&qT,  g_qT);
    cudaGetSymbolAddress((void**)&kT,  g_kT);
    cudaGetSymbolAddress((void**)&vb,  g_v);
    cudaGetSymbolAddress((void**)&o2T, g_o2T);
    cudaGetSymbolAddress((void**)&wr,  g_wr);

    cudaFuncSetAttribute((const void*)tgp<0>, cudaFuncAttributeMaxDynamicSharedMemorySize, GSMEM);
    cudaFuncSetAttribute((const void*)tgp<1>, cudaFuncAttributeMaxDynamicSharedMemorySize, GSMEM);
    cudaFuncSetAttribute((const void*)tgp<2>, cudaFuncAttributeMaxDynamicSharedMemorySize, GSMEM);
    cudaFuncSetAttribute((const void*)attn_tc, cudaFuncAttributeMaxDynamicSharedMemorySize, ASMEM);

    cudaLaunchConfig_t cfg = {};
    cfg.gridDim = dim3(GRID_P, 1, 1);
    cfg.blockDim = dim3(256, 1, 1);
    cfg.dynamicSmemBytes = GSMEM;
    cfg.stream = 0;
    cudaLaunchAttribute at[1];
    at[0].id = cudaLaunchAttributeClusterDimension;
    at[0].val.clusterDim.x = 2; at[0].val.clusterDim.y = 1; at[0].val.clusterDim.z = 1;
    cfg.attrs = at; cfg.numAttrs = 1;

    // 0a) round all weights to tf32
    round_w5<<<(N4_TOT + 255) / 256, 256>>>(w1, wq, wk, wv, w3, wr);
    // 0b) xT[b][hw][c] (tf32-rounded)
    transpose_k<<<dim3(64, 32, BB), 256>>>(x, xT, CIN, NN);
    // 1) conv1 -> o1T (cg2 cluster persistent)
    cudaLaunchKernelEx(&cfg, tgp<0>, wr + (size_t)WR_W1, (const float*)xT,
                       o1T, (float*)nullptr, (float*)nullptr,
                       (const float*)nullptr, g1, be1, b1);
    // 2) fused qkv (cg2): qT (scaled), kT, v (flipped)
    cudaLaunchKernelEx(&cfg, tgp<1>, wr + (size_t)WR_WQ, (const float*)o1T,
                       qT, kT, vb, (const float*)nullptr,
                       (const float*)nullptr, (const float*)nullptr,
                       (const float*)nullptr);
    // 3) attention + residual + bn2 + relu -> o2T
    attn_tc<<<dim3(2, 32, BB), 128, ASMEM>>>(qT, kT, vb, o1T, g2, be2, o2T);
    // 4) conv3 -> out (cg2, flipped, bn3 + resid + relu)
    cudaLaunchKernelEx(&cfg, tgp<2>, wr + (size_t)WR_W3, (const float*)o2T,
                       out, (float*)nullptr, (float*)nullptr,
                       (const float*)x, g3, be3, b3);
}

// round 11
// speedup vs baseline: 1.5746x; 1.5746x over previous
#include <cuda_runtime.h>
#include <cstdint>

// Problem constants
#define BB 16
#define CIN 1024
#define PP 512
#define NN 2048          // H*W
#define DH 128           // head dim
#define INVF 0.99999500003749969f      // 1/sqrt(1+1e-5)
#define QSCALE 0.08838834764831843f    // 128^-0.5
#define GRID_P 152                      // persistent grid = SM count

#if defined(__CUDA_ARCH__) && (__CUDA_ARCH__ >= 1000) && \
    (defined(__CUDA_ARCH_FEAT_SM103_ALL) || defined(__CUDA_ARCH_FEAT_SM100_ALL) || \
     defined(__CUDA_ARCH_SPECIFIC__) || defined(__CUDA_ARCH_FAMILY_SPECIFIC__))
#define HAS_TCGEN05 1
#else
#define HAS_TCGEN05 0
#endif

// Scratch (device globals)
__device__ float g_xT [(size_t)BB * CIN * NN];   // [b][hw][c]  (tf32-rounded)
__device__ float g_o1T[(size_t)BB * PP * NN];    // [b][hw][p]  (tf32-rounded)
__device__ float g_qT [(size_t)BB * PP * NN];    // [b][hw][p]  (tf32-rounded)
__device__ float g_kT [(size_t)BB * PP * NN];    // [b][hw][p]  (tf32-rounded)
__device__ float g_v  [(size_t)BB * PP * NN];    // [b][p][hw]  (tf32-rounded)
__device__ float g_o2T[(size_t)BB * PP * NN];    // [b][hw][p]  (tf32-rounded)
// Rounded weights, contiguous: w1 | wq | wk | wv | w3
#define WR_W1 0
#define WR_WQ (512 * 1024)
#define WR_WK (WR_WQ + 512 * 512)
#define WR_WV (WR_WK + 512 * 512)
#define WR_W3 (WR_WV + 512 * 512)
__device__ float g_wr[WR_W3 + 1024 * 512];

// ---------------------------------------------------------------------------
__device__ __forceinline__ uint32_t smem_u32(const void* p) {
    uint32_t a;
    asm("{ .reg .u64 t; cvta.to.shared.u64 t, %1; cvt.u32.u64 %0, t; }"
        : "=r"(a) : "l"(p));
    return a;
}
__device__ __forceinline__ float to_tf32(float x) {
    float r; asm("cvt.rna.tf32.f32 %0, %1;" : "=f"(r) : "f"(x)); return r;
}

#if HAS_TCGEN05
__device__ __forceinline__ uint32_t elect1() {
    uint32_t p;
    asm volatile("{ .reg .pred p; elect.sync _|p, 0xFFFFFFFF; selp.b32 %0,1,0,p; }"
                 : "=r"(p));
    return p;
}
#define SW128(o) ((o) ^ ((((uint32_t)(o)) >> 3) & 0x70))

#define MBAR_INIT(a, c) \
    asm volatile("mbarrier.init.shared.b64 [%0], %1;" :: "r"(a), "r"(c) : "memory")

#define MBAR_ARRIVE(a) \
    asm volatile("mbarrier.arrive.shared::cta.b64 _, [%0];" :: "r"(a) : "memory")

#define MBAR_WAIT(a, ph) do { \
    uint32_t _d; \
    asm volatile("{ .reg .pred p; mbarrier.try_wait.parity.acquire.cta.shared::cta.b64 p,[%1],%2; selp.b32 %0,1,0,p; }" \
                 : "=r"(_d) : "r"(a), "r"((uint32_t)(ph)) : "memory"); \
    if (!_d) { \
        asm volatile("{ .reg .pred P;\nLW_%=:\nmbarrier.try_wait.parity.acquire.cta.shared::cta.b64 P,[%0],%1,0x989680;\n@P bra.uni LD_%=;\nbra.uni LW_%=;\nLD_%=:\n}" \
                     :: "r"(a), "r"((uint32_t)(ph)) : "memory"); \
    } } while (0)

#define TM_ALLOC(sa, n) \
    asm volatile("tcgen05.alloc.cta_group::1.sync.aligned.shared::cta.b32 [%0], %1;" \
                 :: "r"(sa), "r"(n) : "memory")
#define TM_DEALLOC(t, n) \
    asm volatile("tcgen05.dealloc.cta_group::1.sync.aligned.b32 %0, %1;" :: "r"(t), "r"(n))
#define TM_COMMIT(mb) \
    asm volatile("tcgen05.commit.cta_group::1.mbarrier::arrive::one.shared::cluster.b64 [%0];" \
                 :: "r"(mb) : "memory")
#define TM_FENCE_AFTER()  asm volatile("tcgen05.fence::after_thread_sync;" ::: "memory")
#define TM_FENCE_BEFORE() asm volatile("tcgen05.fence::before_thread_sync;" ::: "memory")
#define TM_WAIT_LD()      asm volatile("tcgen05.wait::ld.sync.aligned;" ::: "memory")
#define TM_WAIT_ST()      asm volatile("tcgen05.wait::st.sync.aligned;" ::: "memory")
#define FENCE_ASYNC()     asm volatile("fence.proxy.async.shared::cta;" ::: "memory")

#define CP_ASYNC16(dst, src) \
    asm volatile("cp.async.cg.shared.global [%0], [%1], 16;" \
                 :: "r"(dst), "l"(src) : "memory")
#define CP_MBAR_ARRIVE(mb) \
    asm volatile("cp.async.mbarrier.arrive.noinc.shared::cta.b64 [%0];" \
                 :: "r"(mb) : "memory")

#define TM_LD_X32(r, addr) \
    asm volatile("tcgen05.ld.sync.aligned.32x32b.x32.b32 " \
        "{%0,%1,%2,%3,%4,%5,%6,%7,%8,%9,%10,%11,%12,%13,%14,%15," \
        "%16,%17,%18,%19,%20,%21,%22,%23,%24,%25,%26,%27,%28,%29,%30,%31}, [%32];" \
        : "=r"((r)[0]),"=r"((r)[1]),"=r"((r)[2]),"=r"((r)[3]), \
          "=r"((r)[4]),"=r"((r)[5]),"=r"((r)[6]),"=r"((r)[7]), \
          "=r"((r)[8]),"=r"((r)[9]),"=r"((r)[10]),"=r"((r)[11]), \
          "=r"((r)[12]),"=r"((r)[13]),"=r"((r)[14]),"=r"((r)[15]), \
          "=r"((r)[16]),"=r"((r)[17]),"=r"((r)[18]),"=r"((r)[19]), \
          "=r"((r)[20]),"=r"((r)[21]),"=r"((r)[22]),"=r"((r)[23]), \
          "=r"((r)[24]),"=r"((r)[25]),"=r"((r)[26]),"=r"((r)[27]), \
          "=r"((r)[28]),"=r"((r)[29]),"=r"((r)[30]),"=r"((r)[31]) \
        : "r"(addr))

#define TM_ST_X32(addr, r) \
    asm volatile("tcgen05.st.sync.aligned.32x32b.x32.b32 [%0], " \
        "{%1,%2,%3,%4,%5,%6,%7,%8,%9,%10,%11,%12,%13,%14,%15,%16," \
        "%17,%18,%19,%20,%21,%22,%23,%24,%25,%26,%27,%28,%29,%30,%31,%32};" \
        :: "r"(addr), \
           "r"((r)[0]),"r"((r)[1]),"r"((r)[2]),"r"((r)[3]), \
           "r"((r)[4]),"r"((r)[5]),"r"((r)[6]),"r"((r)[7]), \
           "r"((r)[8]),"r"((r)[9]),"r"((r)[10]),"r"((r)[11]), \
           "r"((r)[12]),"r"((r)[13]),"r"((r)[14]),"r"((r)[15]), \
           "r"((r)[16]),"r"((r)[17]),"r"((r)[18]),"r"((r)[19]), \
           "r"((r)[20]),"r"((r)[21]),"r"((r)[22]),"r"((r)[23]), \
           "r"((r)[24]),"r"((r)[25]),"r"((r)[26]),"r"((r)[27]), \
           "r"((r)[28]),"r"((r)[29]),"r"((r)[30]),"r"((r)[31]) \
        : "memory")

__device__ __forceinline__ uint64_t mkdesc(uint32_t addr) {
    return ((uint64_t)2 << 61) | ((uint64_t)1 << 46) | ((uint64_t)64 << 32) |
           ((uint64_t)1 << 16) | ((addr >> 4) & 0x3FFF);
}
__device__ __forceinline__ void mma_ss(uint32_t d, uint64_t ad, uint64_t bd,
                                       uint32_t id, uint32_t en) {
    asm volatile(
        "{ .reg .pred p; setp.ne.u32 p, %5, 0;\n\t"
        "tcgen05.mma.cta_group::1.kind::tf32 [%0], %1, %2, %3, {%4,%4,%4,%4}, p;\n\t}"
        :: "r"(d), "l"(ad), "l"(bd), "r"(id), "r"(0u), "r"(en) : "memory");
}
__device__ __forceinline__ void mma_ts(uint32_t d, uint32_t a, uint64_t bd,
                                       uint32_t id, uint32_t en) {
    asm volatile(
        "{ .reg .pred p; setp.ne.u32 p, %5, 0;\n\t"
        "tcgen05.mma.cta_group::1.kind::tf32 [%0], [%1], %2, %3, {%4,%4,%4,%4}, p;\n\t}"
        :: "r"(d), "r"(a), "l"(bd), "r"(id), "r"(0u), "r"(en) : "memory");
}
#define IDESC_128 ((1u << 4) | (2u << 7) | (2u << 10) | (16u << 17) | (8u << 24))
#define IDESC_256 ((1u << 4) | (2u << 7) | (2u << 10) | (32u << 17) | (8u << 24))
#endif  // HAS_TCGEN05

// ---------------------------------------------------------------------------
// Round all 5 weight matrices to tf32 in one launch, into contiguous g_wr
// ---------------------------------------------------------------------------
#define N4_W1 131072
#define N4_P  65536
#define N4_W3 131072
#define N4_TOT (N4_W1 + 3 * N4_P + N4_W3)

__global__ __launch_bounds__(256)
void round_w5(const float* __restrict__ w1, const float* __restrict__ wq,
              const float* __restrict__ wk, const float* __restrict__ wv,
              const float* __restrict__ w3, float* __restrict__ out)
{
    int i = blockIdx.x * 256 + threadIdx.x;
    if (i >= N4_TOT) return;
    const float4* src;
    int j = i;
    if (j < N4_W1) src = (const float4*)w1;
    else if ((j -= N4_W1) < N4_P) src = (const float4*)wq;
    else if ((j -= N4_P) < N4_P) src = (const float4*)wk;
    else if ((j -= N4_P) < N4_P) src = (const float4*)wv;
    else { j -= N4_P; src = (const float4*)w3; }
    float4 v = src[j];
    v.x = to_tf32(v.x); v.y = to_tf32(v.y);
    v.z = to_tf32(v.z); v.w = to_tf32(v.w);
    ((float4*)out)[i] = v;
}

// ---------------------------------------------------------------------------
// Tiled transpose per batch with tf32 rounding: in[b][R][C] -> out[b][C][R]
// ---------------------------------------------------------------------------
__global__ __launch_bounds__(256)
void transpose_k(const float* __restrict__ in, float* __restrict__ out, int R, int C)
{
    __shared__ float tile[32][33];
    const int b = blockIdx.z;
    const float* ip = in + (size_t)b * R * C;
    float* op = out + (size_t)b * R * C;
    const int c0 = blockIdx.x * 32, r0 = blockIdx.y * 32;
    const int tx = threadIdx.x & 31, ty = threadIdx.x >> 5;
#pragma unroll
    for (int i = 0; i < 32; i += 8)
        tile[ty + i][tx] = ip[(size_t)(r0 + ty + i) * C + c0 + tx];
    __syncthreads();
#pragma unroll
    for (int i = 0; i < 32; i += 8)
        op[(size_t)(c0 + ty + i) * R + r0 + tx] = to_tf32(tile[tx][ty + i]);
}

// ---------------------------------------------------------------------------
// Warp-specialized persistent tf32 GEMM, 256m x 256n tiles (single CTA).
// Two M=128 halves share one B load: 64KB/chunk covers 256x256 output
// -> per-output LTS traffic x 2/3 vs 128x256 tiles, NO cross-CTA sync.
// TMEM: half h accumulates in cols [h*256, h*256+256) -> single-buffered;
// tile-boundary epilogue stalls only warp0's MMA issue (producers keep
// prefetching into the 3 x 64KB stages).
// MODE 0: conv1 -> o1T[hw][p] (bn1+relu, rnd)         NPID=256, K=1024
// MODE 1: qkv: pid<512 qk -> qT/kT[hw][p] (q scaled); pid>=512 (flipped)
//              -> v[p][hw]                            NPID=768, K=512
// MODE 2: conv3 (flipped) -> out[c][hw] (bn3+resid+relu) NPID=512, K=512
// ---------------------------------------------------------------------------
#define STAGE_B 65536u
#define GS_BN   (1024u + 3 * STAGE_B)               // 197632
#define GSMEM   (GS_BN + 2 * 1024 * 4)              // 205824 B

template <int MODE>
__device__ __forceinline__ void tile_ab(int pid, const float* W, const float* ACT,
                                        const float*& A, const float*& B)
{
    if (MODE == 0) {
        int mp = pid & 1, n0 = ((pid >> 1) & 7) << 8, bz = pid >> 4;
        A = W + (size_t)(mp * 256) * 1024;
        B = ACT + ((size_t)bz * NN + n0) * 1024;
    } else if (MODE == 1) {
        if (pid < 512) {
            int mp = pid & 3, n0 = ((pid >> 2) & 7) << 8, bz = pid >> 5;
            A = W + (size_t)(mp * 256) * 512;
            B = ACT + ((size_t)bz * NN + n0) * 512;
        } else {
            int j = pid - 512;
            int m0 = (j & 7) * 256, n0 = ((j >> 3) & 1) << 8, bz = j >> 4;
            A = ACT + ((size_t)bz * NN + m0) * 512;   // activations on M side
            B = W + 524288u + (size_t)n0 * 512;       // wv
        }
    } else {
        int m0 = (pid & 7) * 256, n0 = ((pid >> 3) & 3) << 8, bz = pid >> 5;
        A = ACT + ((size_t)bz * NN + m0) * 512;       // o2T rows (hw)
        B = W + (size_t)n0 * 512;                     // w3 rows (c)
    }
}

#if HAS_TCGEN05
// Producer feed: 128 threads load A(256x32)=32KB + B(256x32)=32KB
template <int MODE>
__device__ __forceinline__ void issue_chunk(uint32_t sbase, int gc, int cta,
                                            const float* W, const float* ACT, int t)
{
    constexpr int NKS = (MODE == 0) ? 5 : 4;
    constexpr int K = (MODE == 0) ? 1024 : 512;
    const int lt = gc >> NKS, c = gc & ((1 << NKS) - 1);
    const float *A, *B;
    tile_ab<MODE>(cta + lt * GRID_P, W, ACT, A, B);
    const uint32_t st = sbase + 1024u + (uint32_t)(gc % 3) * STAGE_B;
#pragma unroll
    for (int r = 0; r < 16; r++) {              // A: 256 x 32
        int idx = t + r * 128, row = idx >> 3, seg = idx & 7;
        CP_ASYNC16(st + SW128(row * 128 + seg * 16),
                   A + (size_t)row * K + c * 32 + seg * 4);
    }
#pragma unroll
    for (int r = 0; r < 16; r++) {              // B: 256 x 32
        int idx = t + r * 128, row = idx >> 3, seg = idx & 7;
        CP_ASYNC16(st + 32768u + SW128(row * 128 + seg * 16),
                   B + (size_t)row * K + c * 32 + seg * 4);
    }
    CP_MBAR_ARRIVE(sbase + 16 + 8 * (gc % 3));
}

// Consumer epilogue: warps 4-7 drain both 256-col halves (512 TMEM cols)
template <int MODE>
__device__ __forceinline__ void epi_tile(int pid, uint32_t tmem, char* smem,
    float* O0, float* O1, float* O2, const float* resid,
    const float* g, const float* be, const float* cb, int wid, int lane)
{
    const int ml = (wid & 3) * 32 + lane;
    const float* bs = (const float*)(smem + GS_BN);
    const float* bt = (const float*)(smem + GS_BN + 4096);

#pragma unroll
    for (int h = 0; h < 2; h++) {
        float* Ob; const float* Rb = nullptr;
        size_t sN; int n0g = 0;
        float sL = 1.f, tL = 0.f;
        int rnd = (MODE != 2);
        if (MODE == 0) {
            int mp = pid & 1, n0 = ((pid >> 1) & 7) << 8, bz = pid >> 4;
            int m = mp * 256 + h * 128 + ml;
            sL = g[m] * INVF; tL = cb[m] * sL + be[m];
            Ob = O0 + ((size_t)bz * NN + n0) * 512 + m;  sN = 512;
        } else if (MODE == 1) {
            if (pid < 512) {
                int mp = pid & 3, n0 = ((pid >> 2) & 7) << 8, bz = pid >> 5;
                int mg = mp * 256 + h * 128;
                float* T = (mg < 512) ? O0 : O1;
                sL = (mg < 512) ? QSCALE : 1.f;
                Ob = T + ((size_t)bz * NN + n0) * 512 + ((mg + ml) & 511);  sN = 512;
            } else {
                int j = pid - 512;
                int m0 = (j & 7) * 256, n0 = ((j >> 3) & 1) << 8, bz = j >> 4;
                Ob = O2 + ((size_t)bz * 512 + n0) * NN + m0 + h * 128 + ml;  sN = NN;
            }
        } else {
            int m0 = (pid & 7) * 256, n0 = ((pid >> 3) & 3) << 8, bz = pid >> 5;
            size_t base = ((size_t)bz * 1024 + n0) * NN + m0 + h * 128 + ml;
            Ob = O0 + base;  Rb = resid + base;
            sN = NN; n0g = n0;
        }

        uint32_t r0[32];
#pragma unroll
        for (int k = 0; k < 8; k++) {
            TM_LD_X32(r0, tmem + h * 256 + k * 32);
            TM_WAIT_LD();
#pragma unroll
            for (int i = 0; i < 32; i++) {
                const int n = k * 32 + i;
                float v = __uint_as_float(r0[i]);
                if (MODE == 2)
                    v = fmaxf(fmaf(v, bs[n0g + n], bt[n0g + n]) + Rb[(size_t)n * sN], 0.f);
                else if (MODE == 0)
                    v = to_tf32(fmaxf(fmaf(v, sL, tL), 0.f));
                else
                    v = to_tf32(v * sL);
                Ob[(size_t)n * sN] = v;
            }
        }
    }
}
#endif  // HAS_TCGEN05

template <int MODE>
__global__ __launch_bounds__(256)
void tgp(const float* __restrict__ W, const float* __restrict__ ACT,
         float* __restrict__ O0, float* __restrict__ O1, float* __restrict__ O2,
         const float* __restrict__ resid,
         const float* __restrict__ g, const float* __restrict__ be,
         const float* __restrict__ cb)
{
    constexpr int NPID  = (MODE == 0) ? 256 : (MODE == 1) ? 768 : 512;
    constexpr int NKS   = (MODE == 0) ? 5 : 4;
    constexpr int NK    = 1 << NKS;
    const int cta = blockIdx.x;
    const int t = threadIdx.x;
    const int ntl = (NPID - cta + GRID_P - 1) / GRID_P;
    if (ntl <= 0) return;
    const int totc = ntl * NK;

#if HAS_TCGEN05
    extern __shared__ char smem[];
    const uint32_t sbase = smem_u32(smem);
    const int wid = t >> 5, lane = t & 31;
    // mbar layout: full[3]@16(128)  mma[3]@48(1)  tiledone@80(1)  epifree@88(128)
    if (t < 3)        MBAR_INIT(sbase + 16 + 8 * t, 128);
    else if (t < 6)   MBAR_INIT(sbase + 48 + 8 * (t - 3), 1);
    else if (t == 6)  MBAR_INIT(sbase + 80, 1);
    else if (t == 7)  MBAR_INIT(sbase + 88, 128);
    if (wid == 0) TM_ALLOC(sbase + 0, 512);
    if (MODE == 2) {
        for (int i = t; i < 1024; i += 256) {
            float s = g[i] * INVF;
            ((float*)(smem + GS_BN))[i] = s;
            ((float*)(smem + GS_BN + 4096))[i] = cb[i] * s + be[i];
        }
    }
    __syncthreads();
    uint32_t tmem;
    asm volatile("ld.shared.b32 %0, [%1];" : "=r"(tmem) : "r"(sbase + 0));

    if (t < 128) {
        // ----------------- producers (warps 0-3) -----------------
        issue_chunk<MODE>(sbase, 0, cta, W, ACT, t);
        issue_chunk<MODE>(sbase, 1, cta, W, ACT, t);

        for (int gc = 0; gc < totc; gc++) {
            const int s = gc % 3, c = gc & (NK - 1), lt = gc >> NKS;
            // 1) WAR gate + tile-done signal (BEFORE this tile's first MMA)
            if (gc >= 1) {
                MBAR_WAIT(sbase + 48 + 8 * ((gc - 1) % 3), ((gc - 1) / 3) & 1);
                if (c == 0 && wid == 0 && elect1())
                    MBAR_ARRIVE(sbase + 80);            // tile lt-1 fully done
            }
            // 2) MMA issue (warp0 elect)
            if (wid == 0 && elect1()) {
                if (c == 0 && lt >= 1) {                // accumulator reuse WAR
                    MBAR_WAIT(sbase + 88, (lt - 1) & 1);
                    TM_FENCE_AFTER();
                }
                MBAR_WAIT(sbase + 16 + 8 * s, (gc / 3) & 1);   // chunk data ready
                FENCE_ASYNC();
                const uint32_t st = sbase + 1024u + (uint32_t)s * STAGE_B;
                const uint64_t bd = mkdesc(st + 32768u);
#pragma unroll
                for (int h = 0; h < 2; h++) {
                    const uint64_t ad = mkdesc(st + h * 16384u);
#pragma unroll
                    for (int si = 0; si < 4; si++)
                        mma_ss(tmem + (h << 8), ad + si * 2, bd + si * 2, IDESC_256,
                               (c > 0 || si > 0) ? 1u : 0u);
                }
                TM_COMMIT(sbase + 48 + 8 * s);
            }
            // 3) prefetch chunk gc+2 (stage freed by the mma[gc-1] wait above)
            if (gc + 2 < totc) issue_chunk<MODE>(sbase, gc + 2, cta, W, ACT, t);
        }
        MBAR_WAIT(sbase + 48 + 8 * ((totc - 1) % 3), ((totc - 1) / 3) & 1);
        if (wid == 0 && elect1()) MBAR_ARRIVE(sbase + 80);     // last tile done
    } else {
        // ----------------- consumers (warps 4-7) -----------------
        for (int lt = 0; lt < ntl; lt++) {
            MBAR_WAIT(sbase + 80, lt & 1);
            TM_FENCE_AFTER();
            epi_tile<MODE>(cta + lt * GRID_P, tmem, smem,
                           O0, O1, O2, resid, g, be, cb, wid, lane);
            TM_FENCE_BEFORE();
            MBAR_ARRIVE(sbase + 88);
        }
    }
    __syncthreads();
    if (wid == 0) TM_DEALLOC(tmem, 512);

#else  // ---------------- fp32 fallback (never runs on GB300) ---------------
    constexpr int K = (MODE == 0) ? 1024 : 512;
    for (int lt = 0; lt < ntl; lt++) {
        const int pid = cta + lt * GRID_P;
        const float *A, *B;
        tile_ab<MODE>(pid, W, ACT, A, B);
        for (int e = t; e < 256 * 256; e += 256) {
            const int mi = e & 255, n = e >> 8;   // mi = half*128 + ml
            float acc = 0.f;
            for (int k = 0; k < K; k++)
                acc += A[(size_t)mi * K + k] * B[(size_t)n * K + k];
            if (MODE == 0) {
                int mp = pid & 1, n0 = ((pid >> 1) & 7) << 8, bz = pid >> 4;
                int m = mp * 256 + mi;
                float s = g[m] * INVF, tt = cb[m] * s + be[m];
                O0[((size_t)bz * NN + n0 + n) * 512 + m] =
                    to_tf32(fmaxf(fmaf(acc, s, tt), 0.f));
            } else if (MODE == 1) {
                if (pid < 512) {
                    int mp = pid & 3, n0 = ((pid >> 2) & 7) << 8, bz = pid >> 5;
                    int mg = mp * 256 + mi;
                    float* T = (mg < 512) ? O0 : O1;
                    float qsc = (mg < 512) ? QSCALE : 1.f;
                    T[((size_t)bz * NN + n0 + n) * 512 + (mg & 511)] =
                        to_tf32(acc * qsc);
                } else {
                    int j = pid - 512;
                    int m0 = (j & 7) * 256, n0 = ((j >> 3) & 1) << 8, bz = j >> 4;
                    O2[((size_t)bz * 512 + n0 + n) * NN + m0 + mi] = to_tf32(acc);
                }
            } else {
                int m0 = (pid & 7) * 256, n0 = ((pid >> 3) & 3) << 8, bz = pid >> 5;
                int cch = n0 + n;
                float s = g[cch] * INVF, tt = cb[cch] * s + be[cch];
                size_t off = ((size_t)bz * 1024 + cch) * NN + m0 + mi;
                O0[off] = fmaxf(fmaf(acc, s, tt) + resid[off], 0.f);
            }
        }
    }
#endif
}

// ---------------------------------------------------------------------------
// tcgen05 attention (verified) + tf32-rounded o2T output
// ---------------------------------------------------------------------------
#define AS_Q   2048u
#define AS_KV0 (2048u + 65536u)
#define AS_KV1 (2048u + 65536u + 32768u)
#define ASMEM  133120

__global__ __launch_bounds__(128)
void attn_tc(const float* __restrict__ qT, const float* __restrict__ kT,
             const float* __restrict__ v, const float* __restrict__ o1T,
             const float* __restrict__ g2, const float* __restrict__ be2,
             float* __restrict__ o2T)
{
    extern __shared__ char sm[];
    const int t = threadIdx.x, wid = t >> 5, lane = t & 31;
    const int xt = blockIdx.x;
    const int sp = blockIdx.y >> 2, hh = blockIdx.y & 3;
    const int b = blockIdx.z;

    const size_t qrow = (size_t)b * NN + sp * 256 + xt * 128;
    const float* qp  = qT  + qrow * PP + hh * DH;
    const float* kp  = kT  + ((size_t)b * NN + sp * 256) * PP + hh * DH;
    const float* vp  = v   + ((size_t)b * PP + hh * DH) * NN + sp * 256;
    const float* o1p = o1T + qrow * PP + hh * DH;
    float* o2p       = o2T + qrow * PP + hh * DH;

#if HAS_TCGEN05
    const uint32_t sbase = smem_u32(sm);
    if (t == 0) { MBAR_INIT(sbase + 16, 1); MBAR_INIT(sbase + 24, 1); }
    if (wid == 0) TM_ALLOC(sbase + 0, 512);
    ((float*)(sm + 1024))[t] = g2[hh * DH + t] * INVF;
    ((float*)(sm + 1536))[t] = be2[hh * DH + t];
    __syncthreads();
    uint32_t tmem;
    asm volatile("ld.shared.b32 %0, [%1];" : "=r"(tmem) : "r"(sbase + 0));
    const uint32_t kvoff[2] = {AS_KV0, AS_KV1};

#pragma unroll
    for (int r = 0; r < 32; r++) {
        int i = t + r * 128;
        int row = i >> 5, rem = i & 31, j = rem >> 3, seg = rem & 7;
        float4 vq = *(const float4*)(qp + (size_t)row * PP + j * 32 + seg * 4);
        *(float4*)(sm + AS_Q + j * 16384 + SW128(row * 128 + seg * 16)) = vq;
    }

    float4 kv[16];
#pragma unroll
    for (int r = 0; r < 16; r++) {
        int i = t + r * 128, row = i >> 3, seg = i & 7;
        kv[r] = *(const float4*)(kp + (size_t)row * PP + seg * 4);
    }
    for (int c = 0; c < 4; c++) {
        const int buf = c & 1;
        const uint32_t mb = sbase + 16 + 8 * buf;
        if (c >= 2) MBAR_WAIT(mb, 0);
#pragma unroll
        for (int r = 0; r < 16; r++) {
            int i = t + r * 128, row = i >> 3, seg = i & 7;
            *(float4*)(sm + kvoff[buf] + SW128(row * 128 + seg * 16)) = kv[r];
        }
        if (c < 3) {
#pragma unroll
            for (int r = 0; r < 16; r++) {
                int i = t + r * 128, row = i >> 3, seg = i & 7;
                kv[r] = *(const float4*)(kp + (size_t)row * PP + (c + 1) * 32 + seg * 4);
            }
        }
        __syncthreads();
        if (wid == 0 && elect1()) {
            FENCE_ASYNC();
            uint64_t qd = mkdesc(sbase + AS_Q + c * 16384);
            uint64_t kd = mkdesc(sbase + kvoff[buf]);
#pragma unroll
            for (int s = 0; s < 4; s++)
                mma_ss(tmem, qd + s * 2, kd + s * 2, IDESC_256,
                       (c > 0 || s > 0) ? 1u : 0u);
            TM_COMMIT(mb);
        }
    }
    MBAR_WAIT(sbase + 24, 1);
    TM_FENCE_AFTER();

    uint32_t rs[32];
    float mx = -1e30f;
#pragma unroll
    for (int cc = 0; cc < 8; cc++) {
        TM_LD_X32(rs, tmem + cc * 32);
        TM_WAIT_LD();
#pragma unroll
        for (int i = 0; i < 32; i++) mx = fmaxf(mx, __uint_as_float(rs[i]));
    }
    float ssum = 0.f;
#pragma unroll
    for (int cc = 0; cc < 8; cc++) {
        TM_LD_X32(rs, tmem + cc * 32);
        TM_WAIT_LD();
#pragma unroll
        for (int i = 0; i < 32; i++) {
            float e = __expf(__uint_as_float(rs[i]) - mx);
            ssum += e;
            rs[i] = __float_as_uint(e);
        }
        TM_ST_X32(tmem + cc * 32, rs);
    }
    TM_WAIT_ST();
    const float sinv = 1.f / ssum;
    TM_FENCE_BEFORE();

#pragma unroll
    for (int r = 0; r < 16; r++) {
        int i = t + r * 128, row = i >> 4, seg = i & 15;
        kv[r] = *(const float4*)(vp + (size_t)row * NN + seg * 4);
    }
    for (int j = 0; j < 4; j++) {
        const int buf = j & 1;
        const uint32_t mb = sbase + 16 + 8 * buf;
        if (j >= 2) MBAR_WAIT(mb, 0);
#pragma unroll
        for (int r = 0; r < 16; r++) {
            int i = t + r * 128, row = i >> 4, seg = i & 15;
            *(float4*)(sm + kvoff[buf] + (seg >> 3) * 16384 +
                       SW128(row * 128 + (seg & 7) * 16)) = kv[r];
        }
        if (j < 3) {
#pragma unroll
            for (int r = 0; r < 16; r++) {
                int i = t + r * 128, row = i >> 4, seg = i & 15;
                kv[r] = *(const float4*)(vp + (size_t)row * NN + (j + 1) * 64 + seg * 4);
            }
        }
        __syncthreads();
        if (wid == 0 && elect1()) {
            FENCE_ASYNC();
            TM_FENCE_AFTER();
            uint64_t vd = mkdesc(sbase + kvoff[buf]);
#pragma unroll
            for (int s = 0; s < 8; s++)
                mma_ts(tmem + 256, tmem + j * 64 + s * 8,
                       vd + (s >> 2) * 1024 + (s & 3) * 2, IDESC_128,
                       (j > 0 || s > 0) ? 1u : 0u);
            TM_COMMIT(mb);
        }
    }
    MBAR_WAIT(sbase + 24, 1);
    TM_FENCE_AFTER();

    const float* g2s  = (const float*)(sm + 1024);
    const float* be2s = (const float*)(sm + 1536);
    const float* myo1 = o1p + (size_t)(wid * 32 + lane) * PP;
    float* myo2       = o2p + (size_t)(wid * 32 + lane) * PP;
#pragma unroll
    for (int k = 0; k < 4; k++) {
        TM_LD_X32(rs, tmem + 256 + k * 32);
        TM_WAIT_LD();
#pragma unroll
        for (int i = 0; i < 32; i += 4) {
            int d = k * 32 + i;
            float4 r1 = *(const float4*)(myo1 + d);
            float4 o;
            o.x = to_tf32(fmaxf(fmaf(fmaf(__uint_as_float(rs[i + 0]), sinv, r1.x), g2s[d + 0], be2s[d + 0]), 0.f));
            o.y = to_tf32(fmaxf(fmaf(fmaf(__uint_as_float(rs[i + 1]), sinv, r1.y), g2s[d + 1], be2s[d + 1]), 0.f));
            o.z = to_tf32(fmaxf(fmaf(fmaf(__uint_as_float(rs[i + 2]), sinv, r1.z), g2s[d + 2], be2s[d + 2]), 0.f));
            o.w = to_tf32(fmaxf(fmaf(fmaf(__uint_as_float(rs[i + 3]), sinv, r1.w), g2s[d + 3], be2s[d + 3]), 0.f));
            *(float4*)(myo2 + d) = o;
        }
    }
    __syncthreads();
    if (wid == 0) TM_DEALLOC(tmem, 512);

#else  // ---------------- fp32 fallback (never runs on GB300) ---------------
    const int x = t;
    float sb[256];
    float mx = -1e30f;
    for (int y = 0; y < 256; y++) {
        float s = 0.f;
        for (int d = 0; d < DH; d++)
            s += qp[(size_t)x * PP + d] * kp[(size_t)y * PP + d];
        sb[y] = s;
        mx = fmaxf(mx, s);
    }
    float ssum = 0.f;
    for (int y = 0; y < 256; y++) { sb[y] = __expf(sb[y] - mx); ssum += sb[y]; }
    float sinv = 1.f / ssum;
    for (int d = 0; d < DH; d++) {
        float o = 0.f;
        for (int y = 0; y < 256; y++) o += sb[y] * vp[(size_t)d * NN + y];
        float val = (o * sinv + o1p[(size_t)x * PP + d]) * (g2[hh * DH + d] * INVF)
                    + be2[hh * DH + d];
        o2p[(size_t)x * PP + d] = to_tf32(fmaxf(val, 0.f));
    }
#endif
}

// ---------------------------------------------------------------------------
extern "C" void kernel_launch(void* const* d_in, const int* in_sizes, int n_in,
                              void* d_out, int out_size)
{
    const float* x   = (const float*)d_in[0];
    const float* w1  = (const float*)d_in[1];
    const float* b1  = (const float*)d_in[2];
    const float* g1  = (const float*)d_in[3];
    const float* be1 = (const float*)d_in[4];
    const float* wq  = (const float*)d_in[5];
    const float* wk  = (const float*)d_in[6];
    const float* wv  = (const float*)d_in[7];
    const float* g2  = (const float*)d_in[8];
    const float* be2 = (const float*)d_in[9];
    const float* w3  = (const float*)d_in[10];
    const float* b3  = (const float*)d_in[11];
    const float* g3  = (const float*)d_in[12];
    const float* be3 = (const float*)d_in[13];
    float* out = (float*)d_out;

    float *xT, *o1T, *qT, *kT, *vb, *o2T, *wr;
    cudaGetSymbolAddress((void**)&xT,  g_xT);
    cudaGetSymbolAddress((void**)&o1T, g_o1T);
    cudaGetSymbolAddress((void**)&qT,  g_qT);
    cudaGetSymbolAddress((void**)&kT,  g_kT);
    cudaGetSymbolAddress((void**)&vb,  g_v);
    cudaGetSymbolAddress((void**)&o2T, g_o2T);
    cudaGetSymbolAddress((void**)&wr,  g_wr);

    cudaFuncSetAttribute((const void*)tgp<0>, cudaFuncAttributeMaxDynamicSharedMemorySize, GSMEM);
    cudaFuncSetAttribute((const void*)tgp<1>, cudaFuncAttributeMaxDynamicSharedMemorySize, GSMEM);
    cudaFuncSetAttribute((const void*)tgp<2>, cudaFuncAttributeMaxDynamicSharedMemorySize, GSMEM);
    cudaFuncSetAttribute((const void*)attn_tc, cudaFuncAttributeMaxDynamicSharedMemorySize, ASMEM);

    // 0a) round all weights to tf32 (single launch, contiguous g_wr)
    round_w5<<<(N4_TOT + 255) / 256, 256>>>(w1, wq, wk, wv, w3, wr);
    // 0b) xT[b][hw][c] (tf32-rounded)
    transpose_k<<<dim3(64, 32, BB), 256>>>(x, xT, CIN, NN);
    // 1) conv1 -> o1T (persistent WS, 256x256 tiles)
    tgp<0><<<GRID_P, 256, GSMEM>>>(wr + WR_W1, xT, o1T, nullptr, nullptr,
                                   nullptr, g1, be1, b1);
    // 2) fused qkv: qT (scaled, trans), kT (trans), v (flipped)
    tgp<1><<<GRID_P, 256, GSMEM>>>(wr + WR_WQ, o1T, qT, kT, vb,
                                   nullptr, nullptr, nullptr, nullptr);
    // 3) attention + residual + bn2 + relu -> o2T
    attn_tc<<<dim3(2, 32, BB), 128, ASMEM>>>(qT, kT, vb, o1T, g2, be2, o2T);
    // 4) conv3 -> out (flipped, bn3 + resid + relu)
    tgp<2><<<GRID_P, 256, GSMEM>>>(wr + WR_W3, o2T, out, nullptr, nullptr,
                                   x, g3, be3, b3);
}

// round 13
// speedup vs baseline: 1.6637x; 1.0566x over previous
#include <cuda_runtime.h>
#include <cstdint>

// Problem constants
#define BB 16
#define CIN 1024
#define PP 512
#define NN 2048          // H*W
#define DH 128           // head dim
#define INVF 0.99999500003749969f      // 1/sqrt(1+1e-5)
#define QSCALE 0.08838834764831843f    // 128^-0.5
#define GRID_P 152                      // GB300 SM count (persistent grid)

#if defined(__CUDA_ARCH__) && (__CUDA_ARCH__ >= 1000) && \
    (defined(__CUDA_ARCH_FEAT_SM103_ALL) || defined(__CUDA_ARCH_FEAT_SM100_ALL) || \
     defined(__CUDA_ARCH_SPECIFIC__) || defined(__CUDA_ARCH_FAMILY_SPECIFIC__))
#define HAS_TCGEN05 1
#else
#define HAS_TCGEN05 0
#endif

// Scratch (device globals)
__device__ float g_xT [(size_t)BB * CIN * NN];   // [b][hw][c]  (tf32-rounded)
__device__ float g_o1T[(size_t)BB * PP * NN];    // [b][hw][p]  (tf32-rounded)
__device__ float g_qT [(size_t)BB * PP * NN];    // [b][hw][p]  (tf32-rounded)
__device__ float g_kT [(size_t)BB * PP * NN];    // [b][hw][p]  (tf32-rounded)
__device__ float g_v  [(size_t)BB * PP * NN];    // [b][p][hw]  (tf32-rounded)
__device__ float g_o2T[(size_t)BB * PP * NN];    // [b][hw][p]  (tf32-rounded)
// Rounded weights, contiguous: w1 | wq | wk | wv | w3
#define WR_W1 0
#define WR_WQ (512 * 1024)
#define WR_WK (WR_WQ + 512 * 512)
#define WR_WV (WR_WK + 512 * 512)
#define WR_W3 (WR_WV + 512 * 512)
__device__ float g_wr[WR_W3 + 1024 * 512];

// ---------------------------------------------------------------------------
__device__ __forceinline__ uint32_t smem_u32(const void* p) {
    uint32_t a;
    asm("{ .reg .u64 t; cvta.to.shared.u64 t, %1; cvt.u32.u64 %0, t; }"
        : "=r"(a) : "l"(p));
    return a;
}
__device__ __forceinline__ float to_tf32(float x) {
    float r; asm("cvt.rna.tf32.f32 %0, %1;" : "=f"(r) : "f"(x)); return r;
}

#if HAS_TCGEN05
__device__ __forceinline__ uint32_t elect1() {
    uint32_t p;
    asm volatile("{ .reg .pred p; elect.sync _|p, 0xFFFFFFFF; selp.b32 %0,1,0,p; }"
                 : "=r"(p));
    return p;
}
#define SW128(o) ((o) ^ ((((uint32_t)(o)) >> 3) & 0x70))

#define MBAR_INIT(a, c) \
    asm volatile("mbarrier.init.shared.b64 [%0], %1;" :: "r"(a), "r"(c) : "memory")

#define MBAR_ARRIVE(a) \
    asm volatile("mbarrier.arrive.shared::cta.b64 _, [%0];" :: "r"(a) : "memory")

#define MBAR_WAIT(a, ph) do { \
    uint32_t _d; \
    asm volatile("{ .reg .pred p; mbarrier.try_wait.parity.acquire.cta.shared::cta.b64 p,[%1],%2; selp.b32 %0,1,0,p; }" \
                 : "=r"(_d) : "r"(a), "r"((uint32_t)(ph)) : "memory"); \
    if (!_d) { \
        asm volatile("{ .reg .pred P;\nLW_%=:\nmbarrier.try_wait.parity.acquire.cta.shared::cta.b64 P,[%0],%1,0x989680;\n@P bra.uni LD_%=;\nbra.uni LW_%=;\nLD_%=:\n}" \
                     :: "r"(a), "r"((uint32_t)(ph)) : "memory"); \
    } } while (0)

#define TM_ALLOC(sa, n) \
    asm volatile("tcgen05.alloc.cta_group::1.sync.aligned.shared::cta.b32 [%0], %1;" \
                 :: "r"(sa), "r"(n) : "memory")
#define TM_DEALLOC(t, n) \
    asm volatile("tcgen05.dealloc.cta_group::1.sync.aligned.b32 %0, %1;" :: "r"(t), "r"(n))
#define TM_COMMIT(mb) \
    asm volatile("tcgen05.commit.cta_group::1.mbarrier::arrive::one.shared::cluster.b64 [%0];" \
                 :: "r"(mb) : "memory")
#define TM_FENCE_AFTER()  asm volatile("tcgen05.fence::after_thread_sync;" ::: "memory")
#define TM_FENCE_BEFORE() asm volatile("tcgen05.fence::before_thread_sync;" ::: "memory")
#define TM_WAIT_LD()      asm volatile("tcgen05.wait::ld.sync.aligned;" ::: "memory")
#define TM_WAIT_ST()      asm volatile("tcgen05.wait::st.sync.aligned;" ::: "memory")
#define FENCE_ASYNC()     asm volatile("fence.proxy.async.shared::cta;" ::: "memory")

#define CP_ASYNC16(dst, src) \
    asm volatile("cp.async.cg.shared.global [%0], [%1], 16;" \
                 :: "r"(dst), "l"(src) : "memory")
#define CP_MBAR_ARRIVE(mb) \
    asm volatile("cp.async.mbarrier.arrive.noinc.shared::cta.b64 [%0];" \
                 :: "r"(mb) : "memory")

#define TM_LD_X32(r, addr) \
    asm volatile("tcgen05.ld.sync.aligned.32x32b.x32.b32 " \
        "{%0,%1,%2,%3,%4,%5,%6,%7,%8,%9,%10,%11,%12,%13,%14,%15," \
        "%16,%17,%18,%19,%20,%21,%22,%23,%24,%25,%26,%27,%28,%29,%30,%31}, [%32];" \
        : "=r"((r)[0]),"=r"((r)[1]),"=r"((r)[2]),"=r"((r)[3]), \
          "=r"((r)[4]),"=r"((r)[5]),"=r"((r)[6]),"=r"((r)[7]), \
          "=r"((r)[8]),"=r"((r)[9]),"=r"((r)[10]),"=r"((r)[11]), \
          "=r"((r)[12]),"=r"((r)[13]),"=r"((r)[14]),"=r"((r)[15]), \
          "=r"((r)[16]),"=r"((r)[17]),"=r"((r)[18]),"=r"((r)[19]), \
          "=r"((r)[20]),"=r"((r)[21]),"=r"((r)[22]),"=r"((r)[23]), \
          "=r"((r)[24]),"=r"((r)[25]),"=r"((r)[26]),"=r"((r)[27]), \
          "=r"((r)[28]),"=r"((r)[29]),"=r"((r)[30]),"=r"((r)[31]) \
        : "r"(addr))

#define TM_ST_X32(addr, r) \
    asm volatile("tcgen05.st.sync.aligned.32x32b.x32.b32 [%0], " \
        "{%1,%2,%3,%4,%5,%6,%7,%8,%9,%10,%11,%12,%13,%14,%15,%16," \
        "%17,%18,%19,%20,%21,%22,%23,%24,%25,%26,%27,%28,%29,%30,%31,%32};" \
        :: "r"(addr), \
           "r"((r)[0]),"r"((r)[1]),"r"((r)[2]),"r"((r)[3]), \
           "r"((r)[4]),"r"((r)[5]),"r"((r)[6]),"r"((r)[7]), \
           "r"((r)[8]),"r"((r)[9]),"r"((r)[10]),"r"((r)[11]), \
           "r"((r)[12]),"r"((r)[13]),"r"((r)[14]),"r"((r)[15]), \
           "r"((r)[16]),"r"((r)[17]),"r"((r)[18]),"r"((r)[19]), \
           "r"((r)[20]),"r"((r)[21]),"r"((r)[22]),"r"((r)[23]), \
           "r"((r)[24]),"r"((r)[25]),"r"((r)[26]),"r"((r)[27]), \
           "r"((r)[28]),"r"((r)[29]),"r"((r)[30]),"r"((r)[31]) \
        : "memory")

__device__ __forceinline__ uint64_t mkdesc(uint32_t addr) {
    return ((uint64_t)2 << 61) | ((uint64_t)1 << 46) | ((uint64_t)64 << 32) |
           ((uint64_t)1 << 16) | ((addr >> 4) & 0x3FFF);
}
__device__ __forceinline__ void mma_ss(uint32_t d, uint64_t ad, uint64_t bd,
                                       uint32_t id, uint32_t en) {
    asm volatile(
        "{ .reg .pred p; setp.ne.u32 p, %5, 0;\n\t"
        "tcgen05.mma.cta_group::1.kind::tf32 [%0], %1, %2, %3, {%4,%4,%4,%4}, p;\n\t}"
        :: "r"(d), "l"(ad), "l"(bd), "r"(id), "r"(0u), "r"(en) : "memory");
}
__device__ __forceinline__ void mma_ts(uint32_t d, uint32_t a, uint64_t bd,
                                       uint32_t id, uint32_t en) {
    asm volatile(
        "{ .reg .pred p; setp.ne.u32 p, %5, 0;\n\t"
        "tcgen05.mma.cta_group::1.kind::tf32 [%0], [%1], %2, %3, {%4,%4,%4,%4}, p;\n\t}"
        :: "r"(d), "r"(a), "l"(bd), "r"(id), "r"(0u), "r"(en) : "memory");
}
#define IDESC_128 ((1u << 4) | (2u << 7) | (2u << 10) | (16u << 17) | (8u << 24))
#define IDESC_256 ((1u << 4) | (2u << 7) | (2u << 10) | (32u << 17) | (8u << 24))
#endif  // HAS_TCGEN05

// ---------------------------------------------------------------------------
// Round all 5 weight matrices to tf32 in one launch, into contiguous g_wr
// ---------------------------------------------------------------------------
#define N4_W1 131072
#define N4_P  65536
#define N4_W3 131072
#define N4_TOT (N4_W1 + 3 * N4_P + N4_W3)

__global__ __launch_bounds__(256)
void round_w5(const float* __restrict__ w1, const float* __restrict__ wq,
              const float* __restrict__ wk, const float* __restrict__ wv,
              const float* __restrict__ w3, float* __restrict__ out)
{
    int i = blockIdx.x * 256 + threadIdx.x;
    if (i >= N4_TOT) return;
    const float4* src;
    int j = i;
    if (j < N4_W1) src = (const float4*)w1;
    else if ((j -= N4_W1) < N4_P) src = (const float4*)wq;
    else if ((j -= N4_P) < N4_P) src = (const float4*)wk;
    else if ((j -= N4_P) < N4_P) src = (const float4*)wv;
    else { j -= N4_P; src = (const float4*)w3; }
    float4 v = src[j];
    v.x = to_tf32(v.x); v.y = to_tf32(v.y);
    v.z = to_tf32(v.z); v.w = to_tf32(v.w);
    ((float4*)out)[i] = v;
}

// ---------------------------------------------------------------------------
// Tiled transpose per batch with tf32 rounding: in[b][R][C] -> out[b][C][R]
// ---------------------------------------------------------------------------
__global__ __launch_bounds__(256)
void transpose_k(const float* __restrict__ in, float* __restrict__ out, int R, int C)
{
    __shared__ float tile[32][33];
    const int b = blockIdx.z;
    const float* ip = in + (size_t)b * R * C;
    float* op = out + (size_t)b * R * C;
    const int c0 = blockIdx.x * 32, r0 = blockIdx.y * 32;
    const int tx = threadIdx.x & 31, ty = threadIdx.x >> 5;
#pragma unroll
    for (int i = 0; i < 32; i += 8)
        tile[ty + i][tx] = ip[(size_t)(r0 + ty + i) * C + c0 + tx];
    __syncthreads();
#pragma unroll
    for (int i = 0; i < 32; i += 8)
        op[(size_t)(c0 + ty + i) * R + r0 + tx] = to_tf32(tile[tx][ty + i]);
}

// ---------------------------------------------------------------------------
// Warp-specialized persistent tcgen05 tf32 GEMM (exact R9 structure, 463us).
// ---------------------------------------------------------------------------
#define NSTAGE 4
#define STAGE_B 49152u
#define GS_BN   (1024u + NSTAGE * STAGE_B)
#define GSMEM   (GS_BN + 2 * 1024 * 4)

template <int MODE>
__device__ __forceinline__ void tile_ab(int id, const float* W, const float* ACT,
                                        const float*& A, const float*& B)
{
    if (MODE == 0) {
        int m0 = (id & 3) << 7, n0 = ((id >> 2) & 7) << 8, bz = id >> 5;
        A = W + (size_t)m0 * 1024;
        B = ACT + ((size_t)bz * NN + n0) * 1024;
    } else if (MODE == 1) {
        if (id < 1024) {
            int m0 = (id & 7) << 7, n0 = ((id >> 3) & 7) << 8, bz = id >> 6;
            A = W + (size_t)m0 * 512;
            B = ACT + ((size_t)bz * NN + n0) * 512;
        } else {
            int j = id - 1024;
            int m0 = (j & 15) << 7, n0 = ((j >> 4) & 1) << 8, bz = j >> 5;
            A = ACT + ((size_t)bz * NN + m0) * 512;
            B = W + 524288u + (size_t)n0 * 512;
        }
    } else {
        int m0 = (id & 15) << 7, n0 = ((id >> 4) & 3) << 8, bz = id >> 6;
        A = ACT + ((size_t)bz * NN + m0) * 512;
        B = W + (size_t)n0 * 512;
    }
}

template <int MODE>
__device__ __forceinline__ void epi_scalar(int id, int ml, int n, float acc,
    float* O0, float* O1, float* O2, const float* resid,
    const float* g, const float* be, const float* cb)
{
    if (MODE == 0) {
        int m0 = (id & 3) << 7, n0 = ((id >> 2) & 7) << 8, bz = id >> 5;
        int m = m0 + ml;
        float s = g[m] * INVF, tt = cb[m] * s + be[m];
        O0[((size_t)bz * NN + n0 + n) * 512 + m] = to_tf32(fmaxf(fmaf(acc, s, tt), 0.f));
    } else if (MODE == 1) {
        if (id < 1024) {
            int m0 = (id & 7) << 7, n0 = ((id >> 3) & 7) << 8, bz = id >> 6;
            float* T = (m0 < 512) ? O0 : O1;
            float qs = (m0 < 512) ? QSCALE : 1.f;
            T[((size_t)bz * NN + n0 + n) * 512 + ((m0 + ml) & 511)] = to_tf32(acc * qs);
        } else {
            int j = id - 1024;
            int m0 = (j & 15) << 7, n0 = ((j >> 4) & 1) << 8, bz = j >> 5;
            O2[((size_t)bz * 512 + n0 + n) * NN + m0 + ml] = to_tf32(acc);
        }
    } else {
        int m0 = (id & 15) << 7, n0 = ((id >> 4) & 3) << 8, bz = id >> 6;
        int c = n0 + n;
        float s = g[c] * INVF, tt = cb[c] * s + be[c];
        size_t off = ((size_t)bz * 1024 + c) * NN + m0 + ml;
        O0[off] = fmaxf(fmaf(acc, s, tt) + resid[off], 0.f);
    }
}

#if HAS_TCGEN05
template <int MODE>
__device__ __forceinline__ void issue_chunk(uint32_t sbase, int gc, int cta,
                                            const float* W, const float* ACT, int t)
{
    constexpr int NKS = (MODE == 0) ? 5 : 4;
    constexpr int K = (MODE == 0) ? 1024 : 512;
    const int lt = gc >> NKS, c = gc & ((1 << NKS) - 1);
    const float *A, *B;
    tile_ab<MODE>(cta + lt * GRID_P, W, ACT, A, B);
    const uint32_t st = sbase + 1024u + (uint32_t)(gc & 3) * STAGE_B;
#pragma unroll
    for (int r = 0; r < 8; r++) {
        int idx = t + r * 128, row = idx >> 3, seg = idx & 7;
        CP_ASYNC16(st + SW128(row * 128 + seg * 16),
                   A + (size_t)row * K + c * 32 + seg * 4);
    }
#pragma unroll
    for (int r = 0; r < 16; r++) {
        int idx = t + r * 128, row = idx >> 3, seg = idx & 7;
        CP_ASYNC16(st + 16384u + SW128(row * 128 + seg * 16),
                   B + (size_t)row * K + c * 32 + seg * 4);
    }
    CP_MBAR_ARRIVE(sbase + 16 + 8 * (gc & 3));
}

template <int MODE>
__device__ __forceinline__ void epi_tile(int id, int abuf, uint32_t tmem, char* smem,
    float* O0, float* O1, float* O2, const float* resid,
    const float* g, const float* be, const float* cb, int wid, int lane)
{
    float* Ob; const float* Rb = nullptr;
    size_t sN; int n0g = 0, m0;
    float qs = 1.f;
    if (MODE == 0) {
        m0 = (id & 3) << 7; int n0 = ((id >> 2) & 7) << 8; int bz = id >> 5;
        Ob = O0 + ((size_t)bz * NN + n0) * 512 + m0;  sN = 512;
    } else if (MODE == 1) {
        if (id < 1024) {
            m0 = (id & 7) << 7; int n0 = ((id >> 3) & 7) << 8; int bz = id >> 6;
            float* T = (m0 < 512) ? O0 : O1;
            if (m0 < 512) qs = QSCALE;
            Ob = T + ((size_t)bz * NN + n0) * 512 + (m0 & 511);  sN = 512;
        } else {
            int j = id - 1024;
            m0 = (j & 15) << 7; int n0 = ((j >> 4) & 1) << 8; int bz = j >> 5;
            Ob = O2 + ((size_t)bz * 512 + n0) * NN + m0;  sN = NN;
        }
    } else {
        m0 = (id & 15) << 7; int n0 = ((id >> 4) & 3) << 8; int bz = id >> 6;
        Ob = O0 + ((size_t)bz * 1024 + n0) * NN + m0;
        Rb = resid + ((size_t)bz * 1024 + n0) * NN + m0;
        sN = NN; n0g = n0;
    }
    const int ml = (wid & 3) * 32 + lane;
    float sL = qs, tL = 0.f;
    if (MODE == 0) { int m = m0 + ml; sL = g[m] * INVF; tL = cb[m] * sL + be[m]; }
    const float* bs = (const float*)(smem + GS_BN);
    const float* bt = (const float*)(smem + GS_BN + 4096);

    uint32_t r0[32];
#pragma unroll
    for (int k = 0; k < 8; k++) {
        TM_LD_X32(r0, tmem + abuf * 256 + k * 32);
        TM_WAIT_LD();
#pragma unroll
        for (int i = 0; i < 32; i++) {
            const int n = k * 32 + i;
            float v = __uint_as_float(r0[i]);
            if (MODE == 2)
                v = fmaxf(fmaf(v, bs[n0g + n], bt[n0g + n]) + Rb[(size_t)n * sN + ml], 0.f);
            else if (MODE == 0)
                v = to_tf32(fmaxf(fmaf(v, sL, tL), 0.f));
            else
                v = to_tf32(v * sL);
            Ob[(size_t)n * sN + ml] = v;
        }
    }
}
#endif  // HAS_TCGEN05

template <int MODE>
__global__ __launch_bounds__(256)
void tgp(const float* __restrict__ W, const float* __restrict__ ACT,
         float* __restrict__ O0, float* __restrict__ O1, float* __restrict__ O2,
         const float* __restrict__ resid,
         const float* __restrict__ g, const float* __restrict__ be,
         const float* __restrict__ cb)
{
    constexpr int TOT   = (MODE == 0) ? 512 : (MODE == 1) ? 1536 : 1024;
    constexpr int NKS   = (MODE == 0) ? 5 : 4;
    constexpr int NK    = 1 << NKS;
    const int cta = blockIdx.x;
    const int t = threadIdx.x;
    const int ntl = (TOT - cta + GRID_P - 1) / GRID_P;
    if (ntl <= 0) return;
    const int totc = ntl * NK;

#if HAS_TCGEN05
    extern __shared__ char smem[];
    const uint32_t sbase = smem_u32(smem);
    const int wid = t >> 5, lane = t & 31;
    if (t < 4)                MBAR_INIT(sbase + 16 + 8 * t, 128);
    else if (t < 8)           MBAR_INIT(sbase + 48 + 8 * (t - 4), 1);
    else if (t < 10)          MBAR_INIT(sbase + 80 + 8 * (t - 8), 1);
    else if (t < 12)          MBAR_INIT(sbase + 96 + 8 * (t - 10), 128);
    if (wid == 0) TM_ALLOC(sbase + 0, 512);
    if (MODE == 2) {
        for (int i = t; i < 1024; i += 256) {
            float s = g[i] * INVF;
            ((float*)(smem + GS_BN))[i] = s;
            ((float*)(smem + GS_BN + 4096))[i] = cb[i] * s + be[i];
        }
    }
    __syncthreads();
    uint32_t tmem;
    asm volatile("ld.shared.b32 %0, [%1];" : "=r"(tmem) : "r"(sbase + 0));

    if (t < 128) {
        issue_chunk<MODE>(sbase, 0, cta, W, ACT, t);
        if (totc > 1) issue_chunk<MODE>(sbase, 1, cta, W, ACT, t);
        if (totc > 2) issue_chunk<MODE>(sbase, 2, cta, W, ACT, t);

        for (int gc = 0; gc < totc; gc++) {
            const int s = gc & 3, c = gc & (NK - 1), lt = gc >> NKS;
            if (wid == 0 && elect1()) {
                if (c == 0 && lt >= 2) {
                    MBAR_WAIT(sbase + 96 + 8 * (lt & 1), ((lt >> 1) - 1) & 1);
                    TM_FENCE_AFTER();
                }
                MBAR_WAIT(sbase + 16 + 8 * s, (gc >> 2) & 1);
                FENCE_ASYNC();
                const uint32_t st = sbase + 1024u + (uint32_t)s * STAGE_B;
                const uint64_t ad = mkdesc(st);
                const uint64_t bd = mkdesc(st + 16384u);
                const uint32_t dacc = tmem + (uint32_t)((lt & 1) << 8);
#pragma unroll
                for (int si = 0; si < 4; si++)
                    mma_ss(dacc, ad + si * 2, bd + si * 2, IDESC_256,
                           (c > 0 || si > 0) ? 1u : 0u);
                TM_COMMIT(sbase + 48 + 8 * s);
            }
            if (gc >= 1) {
                MBAR_WAIT(sbase + 48 + 8 * ((gc - 1) & 3), ((gc - 1) >> 2) & 1);
                if (c == 0 && wid == 0 && elect1())
                    MBAR_ARRIVE(sbase + 80 + 8 * ((lt - 1) & 1));
            }
            if (gc + 3 < totc) issue_chunk<MODE>(sbase, gc + 3, cta, W, ACT, t);
        }
        MBAR_WAIT(sbase + 48 + 8 * ((totc - 1) & 3), ((totc - 1) >> 2) & 1);
        if (wid == 0 && elect1())
            MBAR_ARRIVE(sbase + 80 + 8 * ((ntl - 1) & 1));
    } else {
        for (int lt = 0; lt < ntl; lt++) {
            MBAR_WAIT(sbase + 80 + 8 * (lt & 1), (lt >> 1) & 1);
            TM_FENCE_AFTER();
            epi_tile<MODE>(cta + lt * GRID_P, lt & 1, tmem, smem,
                           O0, O1, O2, resid, g, be, cb, wid, lane);
            TM_FENCE_BEFORE();
            MBAR_ARRIVE(sbase + 96 + 8 * (lt & 1));
        }
    }
    __syncthreads();
    if (wid == 0) TM_DEALLOC(tmem, 512);

#else  // fp32 fallback
    constexpr int K = (MODE == 0) ? 1024 : 512;
    for (int lt = 0; lt < ntl; lt++) {
        const int id = cta + lt * GRID_P;
        const float *A, *B;
        tile_ab<MODE>(id, W, ACT, A, B);
        for (int e = t; e < 128 * 256; e += 256) {
            const int ml = e & 127, n = e >> 7;
            float acc = 0.f;
            for (int k = 0; k < K; k++)
                acc += A[(size_t)ml * K + k] * B[(size_t)n * K + k];
            epi_scalar<MODE>(id, ml, n, acc, O0, O1, O2, resid, g, be, cb);
        }
    }
#endif
}

// ---------------------------------------------------------------------------
// tcgen05 attention (R6 verified flow) + cp.async V preload into dedicated
// buffers. V0/V1 -> KV2/KV3 issued at kernel start; V2/V3 -> KV0/KV1 issued
// right after S completes (K buffers provably free). One single-use mbarrier
// per V chunk (vb[0..3], parity 0, one event each) + one pvmb for PV done.
// ---------------------------------------------------------------------------
#define AS_Q   2048u
#define AS_KV0 (2048u + 65536u)
#define AS_KV1 (AS_KV0 + 32768u)
#define AS_KV2 (AS_KV1 + 32768u)
#define AS_KV3 (AS_KV2 + 32768u)
#define ASMEM  (2048 + 65536 + 4 * 32768)   // 198656

__global__ __launch_bounds__(128)
void attn_tc(const float* __restrict__ qT, const float* __restrict__ kT,
             const float* __restrict__ v, const float* __restrict__ o1T,
             const float* __restrict__ g2, const float* __restrict__ be2,
             float* __restrict__ o2T)
{
    extern __shared__ char sm[];
    const int t = threadIdx.x, wid = t >> 5, lane = t & 31;
    const int xt = blockIdx.x;
    const int sp = blockIdx.y >> 2, hh = blockIdx.y & 3;
    const int b = blockIdx.z;

    const size_t qrow = (size_t)b * NN + sp * 256 + xt * 128;
    const float* qp  = qT  + qrow * PP + hh * DH;
    const float* kp  = kT  + ((size_t)b * NN + sp * 256) * PP + hh * DH;
    const float* vp  = v   + ((size_t)b * PP + hh * DH) * NN + sp * 256;
    const float* o1p = o1T + qrow * PP + hh * DH;
    float* o2p       = o2T + qrow * PP + hh * DH;

#if HAS_TCGEN05
    const uint32_t sbase = smem_u32(sm);
    // mbars: mb0@16 mb1@24 (count1, K/S as R6)  vb[4]@32..63 (count128)
    //        pvmb@64 (count1)
    if (t == 0) { MBAR_INIT(sbase + 16, 1); MBAR_INIT(sbase + 24, 1);
                  MBAR_INIT(sbase + 64, 1); }
    if (t >= 8 && t < 12) MBAR_INIT(sbase + 32 + 8 * (t - 8), 128);
    if (wid == 0) TM_ALLOC(sbase + 0, 512);
    ((float*)(sm + 1024))[t] = g2[hh * DH + t] * INVF;
    ((float*)(sm + 1536))[t] = be2[hh * DH + t];
    __syncthreads();
    uint32_t tmem;
    asm volatile("ld.shared.b32 %0, [%1];" : "=r"(tmem) : "r"(sbase + 0));
    const uint32_t kvoff[2] = {AS_KV0, AS_KV1};

    // ---- preload V chunks 0,1 into KV2,KV3 (overlaps Q/K/S/softmax) ----
#pragma unroll
    for (int j = 0; j < 2; j++) {
        const uint32_t dst = sbase + ((j == 0) ? AS_KV2 : AS_KV3);
#pragma unroll
        for (int r = 0; r < 16; r++) {
            int i = t + r * 128, row = i >> 4, seg = i & 15;
            CP_ASYNC16(dst + (seg >> 3) * 16384 + SW128(row * 128 + (seg & 7) * 16),
                       vp + (size_t)row * NN + j * 64 + seg * 4);
        }
        CP_MBAR_ARRIVE(sbase + 32 + 8 * j);
    }

    // ---- load Q tile [128 x][128 d] into 4 d-chunk atoms (as R6) ----
#pragma unroll
    for (int r = 0; r < 32; r++) {
        int i = t + r * 128;
        int row = i >> 5, rem = i & 31, j = rem >> 3, seg = rem & 7;
        float4 vq = *(const float4*)(qp + (size_t)row * PP + j * 32 + seg * 4);
        *(float4*)(sm + AS_Q + j * 16384 + SW128(row * 128 + seg * 16)) = vq;
    }

    // ---- S = Q.K^T over 4 d-chunks, double-buffered K (exact R6) ----
    float4 kv[16];
#pragma unroll
    for (int r = 0; r < 16; r++) {
        int i = t + r * 128, row = i >> 3, seg = i & 7;
        kv[r] = *(const float4*)(kp + (size_t)row * PP + seg * 4);
    }
    for (int c = 0; c < 4; c++) {
        const int buf = c & 1;
        const uint32_t mb = sbase + 16 + 8 * buf;
        if (c >= 2) MBAR_WAIT(mb, 0);
#pragma unroll
        for (int r = 0; r < 16; r++) {
            int i = t + r * 128, row = i >> 3, seg = i & 7;
            *(float4*)(sm + kvoff[buf] + SW128(row * 128 + seg * 16)) = kv[r];
        }
        if (c < 3) {
#pragma unroll
            for (int r = 0; r < 16; r++) {
                int i = t + r * 128, row = i >> 3, seg = i & 7;
                kv[r] = *(const float4*)(kp + (size_t)row * PP + (c + 1) * 32 + seg * 4);
            }
        }
        __syncthreads();
        if (wid == 0 && elect1()) {
            FENCE_ASYNC();
            uint64_t qd = mkdesc(sbase + AS_Q + c * 16384);
            uint64_t kd = mkdesc(sbase + kvoff[buf]);
#pragma unroll
            for (int s = 0; s < 4; s++)
                mma_ss(tmem, qd + s * 2, kd + s * 2, IDESC_256,
                       (c > 0 || s > 0) ? 1u : 0u);
            TM_COMMIT(mb);
        }
    }
    MBAR_WAIT(sbase + 24, 1);     // all S MMAs complete (2nd commit on mb1)
    TM_FENCE_AFTER();

    // ---- issue V chunks 2,3 into KV0,KV1 (K buffers now free; overlaps
    //      the softmax below) ----
#pragma unroll
    for (int j = 2; j < 4; j++) {
        const uint32_t dst = sbase + kvoff[j - 2];
#pragma unroll
        for (int r = 0; r < 16; r++) {
            int i = t + r * 128, row = i >> 4, seg = i & 15;
            CP_ASYNC16(dst + (seg >> 3) * 16384 + SW128(row * 128 + (seg & 7) * 16),
                       vp + (size_t)row * NN + j * 64 + seg * 4);
        }
        CP_MBAR_ARRIVE(sbase + 32 + 8 * j);
    }

    // ---- softmax over 256 keys; lane = query row; P unnormalized ----
    uint32_t rs[32];
    float mx = -1e30f;
#pragma unroll
    for (int cc = 0; cc < 8; cc++) {
        TM_LD_X32(rs, tmem + cc * 32);
        TM_WAIT_LD();
#pragma unroll
        for (int i = 0; i < 32; i++) mx = fmaxf(mx, __uint_as_float(rs[i]));
    }
    float ssum = 0.f;
#pragma unroll
    for (int cc = 0; cc < 8; cc++) {
        TM_LD_X32(rs, tmem + cc * 32);
        TM_WAIT_LD();
#pragma unroll
        for (int i = 0; i < 32; i++) {
            float e = __expf(__uint_as_float(rs[i]) - mx);
            ssum += e;
            rs[i] = __float_as_uint(e);
        }
        TM_ST_X32(tmem + cc * 32, rs);
    }
    TM_WAIT_ST();
    const float sinv = 1.f / ssum;
    TM_FENCE_BEFORE();
    __syncthreads();              // all P stores visible before PV issue

    // ---- PV: no loads in loop; V buffers preloaded. Single commit. ----
    if (wid == 0 && elect1()) {
        TM_FENCE_AFTER();
        const uint32_t vbuf[4] = {AS_KV2, AS_KV3, AS_KV0, AS_KV1};
#pragma unroll
        for (int j = 0; j < 4; j++) {
            MBAR_WAIT(sbase + 32 + 8 * j, 0);     // single-use, parity 0
            FENCE_ASYNC();
            uint64_t vd = mkdesc(sbase + vbuf[j]);
#pragma unroll
            for (int s = 0; s < 8; s++)
                mma_ts(tmem + 256, tmem + j * 64 + s * 8,
                       vd + (s >> 2) * 1024 + (s & 3) * 2, IDESC_128,
                       (j > 0 || s > 0) ? 1u : 0u);
        }
        TM_COMMIT(sbase + 64);
    }
    MBAR_WAIT(sbase + 64, 0);     // PV complete (single-use pvmb)
    TM_FENCE_AFTER();

    // ---- epilogue: (O*sinv + o1)*g2' + be2, relu, tf32-round -> o2T ----
    const float* g2s  = (const float*)(sm + 1024);
    const float* be2s = (const float*)(sm + 1536);
    const float* myo1 = o1p + (size_t)(wid * 32 + lane) * PP;
    float* myo2       = o2p + (size_t)(wid * 32 + lane) * PP;
#pragma unroll
    for (int k = 0; k < 4; k++) {
        TM_LD_X32(rs, tmem + 256 + k * 32);
        TM_WAIT_LD();
#pragma unroll
        for (int i = 0; i < 32; i += 4) {
            int d = k * 32 + i;
            float4 r1 = *(const float4*)(myo1 + d);
            float4 o;
            o.x = to_tf32(fmaxf(fmaf(fmaf(__uint_as_float(rs[i + 0]), sinv, r1.x), g2s[d + 0], be2s[d + 0]), 0.f));
            o.y = to_tf32(fmaxf(fmaf(fmaf(__uint_as_float(rs[i + 1]), sinv, r1.y), g2s[d + 1], be2s[d + 1]), 0.f));
            o.z = to_tf32(fmaxf(fmaf(fmaf(__uint_as_float(rs[i + 2]), sinv, r1.z), g2s[d + 2], be2s[d + 2]), 0.f));
            o.w = to_tf32(fmaxf(fmaf(fmaf(__uint_as_float(rs[i + 3]), sinv, r1.w), g2s[d + 3], be2s[d + 3]), 0.f));
            *(float4*)(myo2 + d) = o;
        }
    }
    __syncthreads();
    if (wid == 0) TM_DEALLOC(tmem, 512);

#else  // fp32 fallback
    const int x = t;
    float sb[256];
    float mx = -1e30f;
    for (int y = 0; y < 256; y++) {
        float s = 0.f;
        for (int d = 0; d < DH; d++)
            s += qp[(size_t)x * PP + d] * kp[(size_t)y * PP + d];
        sb[y] = s;
        mx = fmaxf(mx, s);
    }
    float ssum = 0.f;
    for (int y = 0; y < 256; y++) { sb[y] = __expf(sb[y] - mx); ssum += sb[y]; }
    float sinv = 1.f / ssum;
    for (int d = 0; d < DH; d++) {
        float o = 0.f;
        for (int y = 0; y < 256; y++) o += sb[y] * vp[(size_t)d * NN + y];
        float val = (o * sinv + o1p[(size_t)x * PP + d]) * (g2[hh * DH + d] * INVF)
                    + be2[hh * DH + d];
        o2p[(size_t)x * PP + d] = to_tf32(fmaxf(val, 0.f));
    }
#endif
}

// ---------------------------------------------------------------------------
extern "C" void kernel_launch(void* const* d_in, const int* in_sizes, int n_in,
                              void* d_out, int out_size)
{
    const float* x   = (const float*)d_in[0];
    const float* w1  = (const float*)d_in[1];
    const float* b1  = (const float*)d_in[2];
    const float* g1  = (const float*)d_in[3];
    const float* be1 = (const float*)d_in[4];
    const float* wq  = (const float*)d_in[5];
    const float* wk  = (const float*)d_in[6];
    const float* wv  = (const float*)d_in[7];
    const float* g2  = (const float*)d_in[8];
    const float* be2 = (const float*)d_in[9];
    const float* w3  = (const float*)d_in[10];
    const float* b3  = (const float*)d_in[11];
    const float* g3  = (const float*)d_in[12];
    const float* be3 = (const float*)d_in[13];
    float* out = (float*)d_out;

    float *xT, *o1T, *qT, *kT, *vb, *o2T, *wr;
    cudaGetSymbolAddress((void**)&xT,  g_xT);
    cudaGetSymbolAddress((void**)&o1T, g_o1T);
    cudaGetSymbolAddress((void**)&qT,  g_qT);
    cudaGetSymbolAddress((void**)&kT,  g_kT);
    cudaGetSymbolAddress((void**)&vb,  g_v);
    cudaGetSymbolAddress((void**)&o2T, g_o2T);
    cudaGetSymbolAddress((void**)&wr,  g_wr);

    cudaFuncSetAttribute((const void*)tgp<0>, cudaFuncAttributeMaxDynamicSharedMemorySize, GSMEM);
    cudaFuncSetAttribute((const void*)tgp<1>, cudaFuncAttributeMaxDynamicSharedMemorySize, GSMEM);
    cudaFuncSetAttribute((const void*)tgp<2>, cudaFuncAttributeMaxDynamicSharedMemorySize, GSMEM);
    cudaFuncSetAttribute((const void*)attn_tc, cudaFuncAttributeMaxDynamicSharedMemorySize, ASMEM);

    // 0a) round all weights to tf32
    round_w5<<<(N4_TOT + 255) / 256, 256>>>(w1, wq, wk, wv, w3, wr);
    // 0b) xT[b][hw][c] (tf32-rounded)
    transpose_k<<<dim3(64, 32, BB), 256>>>(x, xT, CIN, NN);
    // 1) conv1 -> o1T (persistent WS, R9)
    tgp<0><<<GRID_P, 256, GSMEM>>>(wr + WR_W1, xT, o1T, nullptr, nullptr,
                                   nullptr, g1, be1, b1);
    // 2) fused qkv (persistent WS, R9)
    tgp<1><<<GRID_P, 256, GSMEM>>>(wr + WR_WQ, o1T, qT, kT, vb,
                                   nullptr, nullptr, nullptr, nullptr);
    // 3) attention (V preloaded via cp.async) -> o2T
    attn_tc<<<dim3(2, 32, BB), 128, ASMEM>>>(qT, kT, vb, o1T, g2, be2, o2T);
    // 4) conv3 -> out (persistent WS, R9)
    tgp<2><<<GRID_P, 256, GSMEM>>>(wr + WR_W3, o2T, out, nullptr, nullptr,
                                   x, g3, be3, b3);
}

// round 14
// speedup vs baseline: 2.0900x; 1.2562x over previous
#include <cuda_runtime.h>
#include <cuda_fp16.h>
#include <cstdint>

// Problem constants
#define BB 16
#define CIN 1024
#define PP 512
#define NN 2048          // H*W
#define DH 128           // head dim
#define INVF 0.99999500003749969f      // 1/sqrt(1+1e-5)
#define QSCALE 0.08838834764831843f    // 128^-0.5
#define GRID_P 152                      // GB300 SM count (persistent grid)

#if defined(__CUDA_ARCH__) && (__CUDA_ARCH__ >= 1000) && \
    (defined(__CUDA_ARCH_FEAT_SM103_ALL) || defined(__CUDA_ARCH_FEAT_SM100_ALL) || \
     defined(__CUDA_ARCH_SPECIFIC__) || defined(__CUDA_ARCH_FAMILY_SPECIFIC__))
#define HAS_TCGEN05 1
#else
#define HAS_TCGEN05 0
#endif

// Scratch (device globals)
__device__ __half g_xT [(size_t)BB * CIN * NN];   // [b][hw][c]  fp16
__device__ __half g_o1T[(size_t)BB * PP * NN];    // [b][hw][p]  fp16
__device__ float  g_qT [(size_t)BB * PP * NN];    // [b][hw][p]  fp32 (tf32-rnd)
__device__ float  g_kT [(size_t)BB * PP * NN];    // [b][hw][p]  fp32 (tf32-rnd)
__device__ float  g_v  [(size_t)BB * PP * NN];    // [b][p][hw]  fp32 (tf32-rnd)
__device__ __half g_o2T[(size_t)BB * PP * NN];    // [b][hw][p]  fp16
// fp16 weights, contiguous: w1 | wq | wk | wv | w3
#define WR_W1 0
#define WR_WQ (512 * 1024)
#define WR_WK (WR_WQ + 512 * 512)
#define WR_WV (WR_WK + 512 * 512)
#define WR_W3 (WR_WV + 512 * 512)
__device__ __half g_wr[WR_W3 + 1024 * 512];

// ---------------------------------------------------------------------------
__device__ __forceinline__ uint32_t smem_u32(const void* p) {
    uint32_t a;
    asm("{ .reg .u64 t; cvta.to.shared.u64 t, %1; cvt.u32.u64 %0, t; }"
        : "=r"(a) : "l"(p));
    return a;
}
__device__ __forceinline__ float to_tf32(float x) {
    float r; asm("cvt.rna.tf32.f32 %0, %1;" : "=f"(r) : "f"(x)); return r;
}

#if HAS_TCGEN05
__device__ __forceinline__ uint32_t elect1() {
    uint32_t p;
    asm volatile("{ .reg .pred p; elect.sync _|p, 0xFFFFFFFF; selp.b32 %0,1,0,p; }"
                 : "=r"(p));
    return p;
}
#define SW128(o) ((o) ^ ((((uint32_t)(o)) >> 3) & 0x70))

#define MBAR_INIT(a, c) \
    asm volatile("mbarrier.init.shared.b64 [%0], %1;" :: "r"(a), "r"(c) : "memory")

#define MBAR_ARRIVE(a) \
    asm volatile("mbarrier.arrive.shared::cta.b64 _, [%0];" :: "r"(a) : "memory")

#define MBAR_WAIT(a, ph) do { \
    uint32_t _d; \
    asm volatile("{ .reg .pred p; mbarrier.try_wait.parity.acquire.cta.shared::cta.b64 p,[%1],%2; selp.b32 %0,1,0,p; }" \
                 : "=r"(_d) : "r"(a), "r"((uint32_t)(ph)) : "memory"); \
    if (!_d) { \
        asm volatile("{ .reg .pred P;\nLW_%=:\nmbarrier.try_wait.parity.acquire.cta.shared::cta.b64 P,[%0],%1,0x989680;\n@P bra.uni LD_%=;\nbra.uni LW_%=;\nLD_%=:\n}" \
                     :: "r"(a), "r"((uint32_t)(ph)) : "memory"); \
    } } while (0)

#define TM_ALLOC(sa, n) \
    asm volatile("tcgen05.alloc.cta_group::1.sync.aligned.shared::cta.b32 [%0], %1;" \
                 :: "r"(sa), "r"(n) : "memory")
#define TM_DEALLOC(t, n) \
    asm volatile("tcgen05.dealloc.cta_group::1.sync.aligned.b32 %0, %1;" :: "r"(t), "r"(n))
#define TM_COMMIT(mb) \
    asm volatile("tcgen05.commit.cta_group::1.mbarrier::arrive::one.shared::cluster.b64 [%0];" \
                 :: "r"(mb) : "memory")
#define TM_FENCE_AFTER()  asm volatile("tcgen05.fence::after_thread_sync;" ::: "memory")
#define TM_FENCE_BEFORE() asm volatile("tcgen05.fence::before_thread_sync;" ::: "memory")
#define TM_WAIT_LD()      asm volatile("tcgen05.wait::ld.sync.aligned;" ::: "memory")
#define TM_WAIT_ST()      asm volatile("tcgen05.wait::st.sync.aligned;" ::: "memory")
#define FENCE_ASYNC()     asm volatile("fence.proxy.async.shared::cta;" ::: "memory")

#define CP_ASYNC16(dst, src) \
    asm volatile("cp.async.cg.shared.global [%0], [%1], 16;" \
                 :: "r"(dst), "l"(src) : "memory")
#define CP_MBAR_ARRIVE(mb) \
    asm volatile("cp.async.mbarrier.arrive.noinc.shared::cta.b64 [%0];" \
                 :: "r"(mb) : "memory")

#define TM_LD_X32(r, addr) \
    asm volatile("tcgen05.ld.sync.aligned.32x32b.x32.b32 " \
        "{%0,%1,%2,%3,%4,%5,%6,%7,%8,%9,%10,%11,%12,%13,%14,%15," \
        "%16,%17,%18,%19,%20,%21,%22,%23,%24,%25,%26,%27,%28,%29,%30,%31}, [%32];" \
        : "=r"((r)[0]),"=r"((r)[1]),"=r"((r)[2]),"=r"((r)[3]), \
          "=r"((r)[4]),"=r"((r)[5]),"=r"((r)[6]),"=r"((r)[7]), \
          "=r"((r)[8]),"=r"((r)[9]),"=r"((r)[10]),"=r"((r)[11]), \
          "=r"((r)[12]),"=r"((r)[13]),"=r"((r)[14]),"=r"((r)[15]), \
          "=r"((r)[16]),"=r"((r)[17]),"=r"((r)[18]),"=r"((r)[19]), \
          "=r"((r)[20]),"=r"((r)[21]),"=r"((r)[22]),"=r"((r)[23]), \
          "=r"((r)[24]),"=r"((r)[25]),"=r"((r)[26]),"=r"((r)[27]), \
          "=r"((r)[28]),"=r"((r)[29]),"=r"((r)[30]),"=r"((r)[31]) \
        : "r"(addr))

#define TM_ST_X32(addr, r) \
    asm volatile("tcgen05.st.sync.aligned.32x32b.x32.b32 [%0], " \
        "{%1,%2,%3,%4,%5,%6,%7,%8,%9,%10,%11,%12,%13,%14,%15,%16," \
        "%17,%18,%19,%20,%21,%22,%23,%24,%25,%26,%27,%28,%29,%30,%31,%32};" \
        :: "r"(addr), \
           "r"((r)[0]),"r"((r)[1]),"r"((r)[2]),"r"((r)[3]), \
           "r"((r)[4]),"r"((r)[5]),"r"((r)[6]),"r"((r)[7]), \
           "r"((r)[8]),"r"((r)[9]),"r"((r)[10]),"r"((r)[11]), \
           "r"((r)[12]),"r"((r)[13]),"r"((r)[14]),"r"((r)[15]), \
           "r"((r)[16]),"r"((r)[17]),"r"((r)[18]),"r"((r)[19]), \
           "r"((r)[20]),"r"((r)[21]),"r"((r)[22]),"r"((r)[23]), \
           "r"((r)[24]),"r"((r)[25]),"r"((r)[26]),"r"((r)[27]), \
           "r"((r)[28]),"r"((r)[29]),"r"((r)[30]),"r"((r)[31]) \
        : "memory")

__device__ __forceinline__ uint64_t mkdesc(uint32_t addr) {
    return ((uint64_t)2 << 61) | ((uint64_t)1 << 46) | ((uint64_t)64 << 32) |
           ((uint64_t)1 << 16) | ((addr >> 4) & 0x3FFF);
}
__device__ __forceinline__ void mma_ss(uint32_t d, uint64_t ad, uint64_t bd,
                                       uint32_t id, uint32_t en) {
    asm volatile(
        "{ .reg .pred p; setp.ne.u32 p, %5, 0;\n\t"
        "tcgen05.mma.cta_group::1.kind::tf32 [%0], %1, %2, %3, {%4,%4,%4,%4}, p;\n\t}"
        :: "r"(d), "l"(ad), "l"(bd), "r"(id), "r"(0u), "r"(en) : "memory");
}
__device__ __forceinline__ void mma_ss_f16(uint32_t d, uint64_t ad, uint64_t bd,
                                           uint32_t id, uint32_t en) {
    asm volatile(
        "{ .reg .pred p; setp.ne.u32 p, %5, 0;\n\t"
        "tcgen05.mma.cta_group::1.kind::f16 [%0], %1, %2, %3, {%4,%4,%4,%4}, p;\n\t}"
        :: "r"(d), "l"(ad), "l"(bd), "r"(id), "r"(0u), "r"(en) : "memory");
}
__device__ __forceinline__ void mma_ts(uint32_t d, uint32_t a, uint64_t bd,
                                       uint32_t id, uint32_t en) {
    asm volatile(
        "{ .reg .pred p; setp.ne.u32 p, %5, 0;\n\t"
        "tcgen05.mma.cta_group::1.kind::tf32 [%0], [%1], %2, %3, {%4,%4,%4,%4}, p;\n\t}"
        :: "r"(d), "r"(a), "l"(bd), "r"(id), "r"(0u), "r"(en) : "memory");
}
#define IDESC_128 ((1u << 4) | (2u << 7) | (2u << 10) | (16u << 17) | (8u << 24))
#define IDESC_256 ((1u << 4) | (2u << 7) | (2u << 10) | (32u << 17) | (8u << 24))
// f16 (atype=btype=FP16=0), F32 accum, N=256, M=128
#define IDESC_H256 ((1u << 4) | (32u << 17) | (8u << 24))
#endif  // HAS_TCGEN05

// ---------------------------------------------------------------------------
// Round all 5 weight matrices to fp16 in one launch, into contiguous g_wr
// ---------------------------------------------------------------------------
#define N4_W1 131072
#define N4_P  65536
#define N4_W3 131072
#define N4_TOT (N4_W1 + 3 * N4_P + N4_W3)

__global__ __launch_bounds__(256)
void round_w5(const float* __restrict__ w1, const float* __restrict__ wq,
              const float* __restrict__ wk, const float* __restrict__ wv,
              const float* __restrict__ w3, __half* __restrict__ out)
{
    int i = blockIdx.x * 256 + threadIdx.x;
    if (i >= N4_TOT) return;
    const float4* src;
    int j = i;
    if (j < N4_W1) src = (const float4*)w1;
    else if ((j -= N4_W1) < N4_P) src = (const float4*)wq;
    else if ((j -= N4_P) < N4_P) src = (const float4*)wk;
    else if ((j -= N4_P) < N4_P) src = (const float4*)wv;
    else { j -= N4_P; src = (const float4*)w3; }
    float4 v = src[j];
    __half2* o = (__half2*)(out + (size_t)i * 4);
    o[0] = __floats2half2_rn(v.x, v.y);
    o[1] = __floats2half2_rn(v.z, v.w);
}

// ---------------------------------------------------------------------------
// Tiled transpose per batch, fp32 in -> fp16 out: in[b][R][C] -> out[b][C][R]
// ---------------------------------------------------------------------------
__global__ __launch_bounds__(256)
void transpose_k(const float* __restrict__ in, __half* __restrict__ out, int R, int C)
{
    __shared__ float tile[32][33];
    const int b = blockIdx.z;
    const float* ip = in + (size_t)b * R * C;
    __half* op = out + (size_t)b * R * C;
    const int c0 = blockIdx.x * 32, r0 = blockIdx.y * 32;
    const int tx = threadIdx.x & 31, ty = threadIdx.x >> 5;
#pragma unroll
    for (int i = 0; i < 32; i += 8)
        tile[ty + i][tx] = ip[(size_t)(r0 + ty + i) * C + c0 + tx];
    __syncthreads();
#pragma unroll
    for (int i = 0; i < 32; i += 8)
        op[(size_t)(c0 + ty + i) * R + r0 + tx] = __float2half_rn(tile[tx][ty + i]);
}

// ---------------------------------------------------------------------------
// Warp-specialized persistent tcgen05 GEMM, fp16 operands (kind::f16),
// R9 pipeline structure (4 stages, 48KB: A 128x64h=16KB + B 256x64h=32KB),
// K64 chunks (4 mma steps of K16 each, desc +2/step).
// MODE 0: conv1  K=1024 (16 chunks) -> o1T[hw][p] fp16 (bn1+relu)
// MODE 1: qkv    K=512  (8 chunks): id<1024 -> qT/kT[hw][p] fp32 (q scaled,
//                tf32-rnd); id>=1024 (flipped) -> v[p][hw] fp32 (tf32-rnd)
// MODE 2: conv3  K=512  (8 chunks, flipped) -> out[c][hw] fp32 (bn3+resid+relu)
// ---------------------------------------------------------------------------
#define NSTAGE 4
#define STAGE_B 49152u
#define GS_BN   (1024u + NSTAGE * STAGE_B)
#define GSMEM   (GS_BN + 2 * 1024 * 4)

template <int MODE>
__device__ __forceinline__ void tile_ab(int id, const __half* W, const __half* ACT,
                                        const __half*& A, const __half*& B)
{
    if (MODE == 0) {
        int m0 = (id & 3) << 7, n0 = ((id >> 2) & 7) << 8, bz = id >> 5;
        A = W + (size_t)m0 * 1024;
        B = ACT + ((size_t)bz * NN + n0) * 1024;
    } else if (MODE == 1) {
        if (id < 1024) {
            int m0 = (id & 7) << 7, n0 = ((id >> 3) & 7) << 8, bz = id >> 6;
            A = W + (size_t)m0 * 512;
            B = ACT + ((size_t)bz * NN + n0) * 512;
        } else {
            int j = id - 1024;
            int m0 = (j & 15) << 7, n0 = ((j >> 4) & 1) << 8, bz = j >> 5;
            A = ACT + ((size_t)bz * NN + m0) * 512;
            B = W + 524288u + (size_t)n0 * 512;
        }
    } else {
        int m0 = (id & 15) << 7, n0 = ((id >> 4) & 3) << 8, bz = id >> 6;
        A = ACT + ((size_t)bz * NN + m0) * 512;
        B = W + (size_t)n0 * 512;
    }
}

// Scalar epilogue (fp32 fallback only)
template <int MODE>
__device__ __forceinline__ void epi_scalar(int id, int ml, int n, float acc,
    void* O0v, float* O1, float* O2, const float* resid,
    const float* g, const float* be, const float* cb)
{
    if (MODE == 0) {
        int m0 = (id & 3) << 7, n0 = ((id >> 2) & 7) << 8, bz = id >> 5;
        int m = m0 + ml;
        float s = g[m] * INVF, tt = cb[m] * s + be[m];
        ((__half*)O0v)[((size_t)bz * NN + n0 + n) * 512 + m] =
            __float2half_rn(fmaxf(fmaf(acc, s, tt), 0.f));
    } else if (MODE == 1) {
        if (id < 1024) {
            int m0 = (id & 7) << 7, n0 = ((id >> 3) & 7) << 8, bz = id >> 6;
            float* T = (m0 < 512) ? (float*)O0v : O1;
            float qs = (m0 < 512) ? QSCALE : 1.f;
            T[((size_t)bz * NN + n0 + n) * 512 + ((m0 + ml) & 511)] = to_tf32(acc * qs);
        } else {
            int j = id - 1024;
            int m0 = (j & 15) << 7, n0 = ((j >> 4) & 1) << 8, bz = j >> 5;
            O2[((size_t)bz * 512 + n0 + n) * NN + m0 + ml] = to_tf32(acc);
        }
    } else {
        int m0 = (id & 15) << 7, n0 = ((id >> 4) & 3) << 8, bz = id >> 6;
        int c = n0 + n;
        float s = g[c] * INVF, tt = cb[c] * s + be[c];
        size_t off = ((size_t)bz * 1024 + c) * NN + m0 + ml;
        ((float*)O0v)[off] = fmaxf(fmaf(acc, s, tt) + resid[off], 0.f);
    }
}

#if HAS_TCGEN05
// Producer feed: 128 threads load A(128x64h)=16KB + B(256x64h)=32KB
template <int MODE>
__device__ __forceinline__ void issue_chunk(uint32_t sbase, int gc, int cta,
                                            const __half* W, const __half* ACT, int t)
{
    constexpr int NKS = (MODE == 0) ? 4 : 3;
    constexpr int K = (MODE == 0) ? 1024 : 512;
    const int lt = gc >> NKS, c = gc & ((1 << NKS) - 1);
    const __half *A, *B;
    tile_ab<MODE>(cta + lt * GRID_P, W, ACT, A, B);
    const uint32_t st = sbase + 1024u + (uint32_t)(gc & 3) * STAGE_B;
#pragma unroll
    for (int r = 0; r < 8; r++) {               // A: 128 rows x 128B
        int idx = t + r * 128, row = idx >> 3, seg = idx & 7;
        CP_ASYNC16(st + SW128(row * 128 + seg * 16),
                   A + (size_t)row * K + c * 64 + seg * 8);
    }
#pragma unroll
    for (int r = 0; r < 16; r++) {              // B: 256 rows x 128B
        int idx = t + r * 128, row = idx >> 3, seg = idx & 7;
        CP_ASYNC16(st + 16384u + SW128(row * 128 + seg * 16),
                   B + (size_t)row * K + c * 64 + seg * 8);
    }
    CP_MBAR_ARRIVE(sbase + 16 + 8 * (gc & 3));
}

// Consumer epilogue: 4 warps drain one 128x256 TMEM buffer
template <int MODE>
__device__ __forceinline__ void epi_tile(int id, int abuf, uint32_t tmem, char* smem,
    void* O0v, float* O1, float* O2, const float* resid,
    const float* g, const float* be, const float* cb, int wid, int lane)
{
    __half* Oh = nullptr; float* Of = nullptr;
    const float* Rb = nullptr;
    size_t sN; int n0g = 0, m0;
    float qs = 1.f;
    if (MODE == 0) {
        m0 = (id & 3) << 7; int n0 = ((id >> 2) & 7) << 8; int bz = id >> 5;
        Oh = (__half*)O0v + ((size_t)bz * NN + n0) * 512 + m0;  sN = 512;
    } else if (MODE == 1) {
        if (id < 1024) {
            m0 = (id & 7) << 7; int n0 = ((id >> 3) & 7) << 8; int bz = id >> 6;
            float* T = (m0 < 512) ? (float*)O0v : O1;
            if (m0 < 512) qs = QSCALE;
            Of = T + ((size_t)bz * NN + n0) * 512 + (m0 & 511);  sN = 512;
        } else {
            int j = id - 1024;
            m0 = (j & 15) << 7; int n0 = ((j >> 4) & 1) << 8; int bz = j >> 5;
            Of = O2 + ((size_t)bz * 512 + n0) * NN + m0;  sN = NN;
        }
    } else {
        m0 = (id & 15) << 7; int n0 = ((id >> 4) & 3) << 8; int bz = id >> 6;
        Of = (float*)O0v + ((size_t)bz * 1024 + n0) * NN + m0;
        Rb = resid + ((size_t)bz * 1024 + n0) * NN + m0;
        sN = NN; n0g = n0;
    }
    const int ml = (wid & 3) * 32 + lane;
    float sL = qs, tL = 0.f;
    if (MODE == 0) { int m = m0 + ml; sL = g[m] * INVF; tL = cb[m] * sL + be[m]; }
    const float* bs = (const float*)(smem + GS_BN);
    const float* bt = (const float*)(smem + GS_BN + 4096);

    uint32_t r0[32];
#pragma unroll
    for (int k = 0; k < 8; k++) {
        TM_LD_X32(r0, tmem + abuf * 256 + k * 32);
        TM_WAIT_LD();
#pragma unroll
        for (int i = 0; i < 32; i++) {
            const int n = k * 32 + i;
            float v = __uint_as_float(r0[i]);
            if (MODE == 2) {
                v = fmaxf(fmaf(v, bs[n0g + n], bt[n0g + n]) + Rb[(size_t)n * sN + ml], 0.f);
                Of[(size_t)n * sN + ml] = v;
            } else if (MODE == 0) {
                Oh[(size_t)n * sN + ml] =
                    __float2half_rn(fmaxf(fmaf(v, sL, tL), 0.f));
            } else {
                Of[(size_t)n * sN + ml] = to_tf32(v * sL);
            }
        }
    }
}
#endif  // HAS_TCGEN05

template <int MODE>
__global__ __launch_bounds__(256)
void tgp(const __half* __restrict__ W, const __half* __restrict__ ACT,
         void* __restrict__ O0v, float* __restrict__ O1, float* __restrict__ O2,
         const float* __restrict__ resid,
         const float* __restrict__ g, const float* __restrict__ be,
         const float* __restrict__ cb)
{
    constexpr int TOT   = (MODE == 0) ? 512 : (MODE == 1) ? 1536 : 1024;
    constexpr int NKS   = (MODE == 0) ? 4 : 3;
    constexpr int NK    = 1 << NKS;
    const int cta = blockIdx.x;
    const int t = threadIdx.x;
    const int ntl = (TOT - cta + GRID_P - 1) / GRID_P;
    if (ntl <= 0) return;
    const int totc = ntl * NK;

#if HAS_TCGEN05
    extern __shared__ char smem[];
    const uint32_t sbase = smem_u32(smem);
    const int wid = t >> 5, lane = t & 31;
    if (t < 4)                MBAR_INIT(sbase + 16 + 8 * t, 128);
    else if (t < 8)           MBAR_INIT(sbase + 48 + 8 * (t - 4), 1);
    else if (t < 10)          MBAR_INIT(sbase + 80 + 8 * (t - 8), 1);
    else if (t < 12)          MBAR_INIT(sbase + 96 + 8 * (t - 10), 128);
    if (wid == 0) TM_ALLOC(sbase + 0, 512);
    if (MODE == 2) {
        for (int i = t; i < 1024; i += 256) {
            float s = g[i] * INVF;
            ((float*)(smem + GS_BN))[i] = s;
            ((float*)(smem + GS_BN + 4096))[i] = cb[i] * s + be[i];
        }
    }
    __syncthreads();
    uint32_t tmem;
    asm volatile("ld.shared.b32 %0, [%1];" : "=r"(tmem) : "r"(sbase + 0));

    if (t < 128) {
        issue_chunk<MODE>(sbase, 0, cta, W, ACT, t);
        if (totc > 1) issue_chunk<MODE>(sbase, 1, cta, W, ACT, t);
        if (totc > 2) issue_chunk<MODE>(sbase, 2, cta, W, ACT, t);

        for (int gc = 0; gc < totc; gc++) {
            const int s = gc & 3, c = gc & (NK - 1), lt = gc >> NKS;
            if (wid == 0 && elect1()) {
                if (c == 0 && lt >= 2) {
                    MBAR_WAIT(sbase + 96 + 8 * (lt & 1), ((lt >> 1) - 1) & 1);
                    TM_FENCE_AFTER();
                }
                MBAR_WAIT(sbase + 16 + 8 * s, (gc >> 2) & 1);
                FENCE_ASYNC();
                const uint32_t st = sbase + 1024u + (uint32_t)s * STAGE_B;
                const uint64_t ad = mkdesc(st);
                const uint64_t bd = mkdesc(st + 16384u);
                const uint32_t dacc = tmem + (uint32_t)((lt & 1) << 8);
#pragma unroll
                for (int si = 0; si < 4; si++)      // 4 x K16 f16 steps
                    mma_ss_f16(dacc, ad + si * 2, bd + si * 2, IDESC_H256,
                               (c > 0 || si > 0) ? 1u : 0u);
                TM_COMMIT(sbase + 48 + 8 * s);
            }
            if (gc >= 1) {
                MBAR_WAIT(sbase + 48 + 8 * ((gc - 1) & 3), ((gc - 1) >> 2) & 1);
                if (c == 0 && wid == 0 && elect1())
                    MBAR_ARRIVE(sbase + 80 + 8 * ((lt - 1) & 1));
            }
            if (gc + 3 < totc) issue_chunk<MODE>(sbase, gc + 3, cta, W, ACT, t);
        }
        MBAR_WAIT(sbase + 48 + 8 * ((totc - 1) & 3), ((totc - 1) >> 2) & 1);
        if (wid == 0 && elect1())
            MBAR_ARRIVE(sbase + 80 + 8 * ((ntl - 1) & 1));
    } else {
        for (int lt = 0; lt < ntl; lt++) {
            MBAR_WAIT(sbase + 80 + 8 * (lt & 1), (lt >> 1) & 1);
            TM_FENCE_AFTER();
            epi_tile<MODE>(cta + lt * GRID_P, lt & 1, tmem, smem,
                           O0v, O1, O2, resid, g, be, cb, wid, lane);
            TM_FENCE_BEFORE();
            MBAR_ARRIVE(sbase + 96 + 8 * (lt & 1));
        }
    }
    __syncthreads();
    if (wid == 0) TM_DEALLOC(tmem, 512);

#else  // fp32 fallback
    constexpr int K = (MODE == 0) ? 1024 : 512;
    for (int lt = 0; lt < ntl; lt++) {
        const int id = cta + lt * GRID_P;
        const __half *A, *B;
        tile_ab<MODE>(id, W, ACT, A, B);
        for (int e = t; e < 128 * 256; e += 256) {
            const int ml = e & 127, n = e >> 7;
            float acc = 0.f;
            for (int k = 0; k < K; k++)
                acc += __half2float(A[(size_t)ml * K + k]) *
                       __half2float(B[(size_t)n * K + k]);
            epi_scalar<MODE>(id, ml, n, acc, O0v, O1, O2, resid, g, be, cb);
        }
    }
#endif
}

// ---------------------------------------------------------------------------
// tcgen05 attention (R13 verified) — qT/kT/v fp32 unchanged; o1T read as
// fp16, o2T written as fp16.
// ---------------------------------------------------------------------------
#define AS_Q   2048u
#define AS_KV0 (2048u + 65536u)
#define AS_KV1 (AS_KV0 + 32768u)
#define AS_KV2 (AS_KV1 + 32768u)
#define AS_KV3 (AS_KV2 + 32768u)
#define ASMEM  (2048 + 65536 + 4 * 32768)   // 198656

__global__ __launch_bounds__(128)
void attn_tc(const float* __restrict__ qT, const float* __restrict__ kT,
             const float* __restrict__ v, const __half* __restrict__ o1T,
             const float* __restrict__ g2, const float* __restrict__ be2,
             __half* __restrict__ o2T)
{
    extern __shared__ char sm[];
    const int t = threadIdx.x, wid = t >> 5, lane = t & 31;
    const int xt = blockIdx.x;
    const int sp = blockIdx.y >> 2, hh = blockIdx.y & 3;
    const int b = blockIdx.z;

    const size_t qrow = (size_t)b * NN + sp * 256 + xt * 128;
    const float* qp  = qT  + qrow * PP + hh * DH;
    const float* kp  = kT  + ((size_t)b * NN + sp * 256) * PP + hh * DH;
    const float* vp  = v   + ((size_t)b * PP + hh * DH) * NN + sp * 256;
    const __half* o1p = o1T + qrow * PP + hh * DH;
    __half* o2p       = o2T + qrow * PP + hh * DH;

#if HAS_TCGEN05
    const uint32_t sbase = smem_u32(sm);
    if (t == 0) { MBAR_INIT(sbase + 16, 1); MBAR_INIT(sbase + 24, 1);
                  MBAR_INIT(sbase + 64, 1); }
    if (t >= 8 && t < 12) MBAR_INIT(sbase + 32 + 8 * (t - 8), 128);
    if (wid == 0) TM_ALLOC(sbase + 0, 512);
    ((float*)(sm + 1024))[t] = g2[hh * DH + t] * INVF;
    ((float*)(sm + 1536))[t] = be2[hh * DH + t];
    __syncthreads();
    uint32_t tmem;
    asm volatile("ld.shared.b32 %0, [%1];" : "=r"(tmem) : "r"(sbase + 0));
    const uint32_t kvoff[2] = {AS_KV0, AS_KV1};

    // ---- preload V chunks 0,1 into KV2,KV3 ----
#pragma unroll
    for (int j = 0; j < 2; j++) {
        const uint32_t dst = sbase + ((j == 0) ? AS_KV2 : AS_KV3);
#pragma unroll
        for (int r = 0; r < 16; r++) {
            int i = t + r * 128, row = i >> 4, seg = i & 15;
            CP_ASYNC16(dst + (seg >> 3) * 16384 + SW128(row * 128 + (seg & 7) * 16),
                       vp + (size_t)row * NN + j * 64 + seg * 4);
        }
        CP_MBAR_ARRIVE(sbase + 32 + 8 * j);
    }

    // ---- load Q tile ----
#pragma unroll
    for (int r = 0; r < 32; r++) {
        int i = t + r * 128;
        int row = i >> 5, rem = i & 31, j = rem >> 3, seg = rem & 7;
        float4 vq = *(const float4*)(qp + (size_t)row * PP + j * 32 + seg * 4);
        *(float4*)(sm + AS_Q + j * 16384 + SW128(row * 128 + seg * 16)) = vq;
    }

    // ---- S = Q.K^T, double-buffered K ----
    float4 kv[16];
#pragma unroll
    for (int r = 0; r < 16; r++) {
        int i = t + r * 128, row = i >> 3, seg = i & 7;
        kv[r] = *(const float4*)(kp + (size_t)row * PP + seg * 4);
    }
    for (int c = 0; c < 4; c++) {
        const int buf = c & 1;
        const uint32_t mb = sbase + 16 + 8 * buf;
        if (c >= 2) MBAR_WAIT(mb, 0);
#pragma unroll
        for (int r = 0; r < 16; r++) {
            int i = t + r * 128, row = i >> 3, seg = i & 7;
            *(float4*)(sm + kvoff[buf] + SW128(row * 128 + seg * 16)) = kv[r];
        }
        if (c < 3) {
#pragma unroll
            for (int r = 0; r < 16; r++) {
                int i = t + r * 128, row = i >> 3, seg = i & 7;
                kv[r] = *(const float4*)(kp + (size_t)row * PP + (c + 1) * 32 + seg * 4);
            }
        }
        __syncthreads();
        if (wid == 0 && elect1()) {
            FENCE_ASYNC();
            uint64_t qd = mkdesc(sbase + AS_Q + c * 16384);
            uint64_t kd = mkdesc(sbase + kvoff[buf]);
#pragma unroll
            for (int s = 0; s < 4; s++)
                mma_ss(tmem, qd + s * 2, kd + s * 2, IDESC_256,
                       (c > 0 || s > 0) ? 1u : 0u);
            TM_COMMIT(mb);
        }
    }
    MBAR_WAIT(sbase + 24, 1);
    TM_FENCE_AFTER();

    // ---- issue V chunks 2,3 into KV0,KV1 (overlaps softmax) ----
#pragma unroll
    for (int j = 2; j < 4; j++) {
        const uint32_t dst = sbase + kvoff[j - 2];
#pragma unroll
        for (int r = 0; r < 16; r++) {
            int i = t + r * 128, row = i >> 4, seg = i & 15;
            CP_ASYNC16(dst + (seg >> 3) * 16384 + SW128(row * 128 + (seg & 7) * 16),
                       vp + (size_t)row * NN + j * 64 + seg * 4);
        }
        CP_MBAR_ARRIVE(sbase + 32 + 8 * j);
    }

    // ---- softmax; P unnormalized in TMEM ----
    uint32_t rs[32];
    float mx = -1e30f;
#pragma unroll
    for (int cc = 0; cc < 8; cc++) {
        TM_LD_X32(rs, tmem + cc * 32);
        TM_WAIT_LD();
#pragma unroll
        for (int i = 0; i < 32; i++) mx = fmaxf(mx, __uint_as_float(rs[i]));
    }
    float ssum = 0.f;
#pragma unroll
    for (int cc = 0; cc < 8; cc++) {
        TM_LD_X32(rs, tmem + cc * 32);
        TM_WAIT_LD();
#pragma unroll
        for (int i = 0; i < 32; i++) {
            float e = __expf(__uint_as_float(rs[i]) - mx);
            ssum += e;
            rs[i] = __float_as_uint(e);
        }
        TM_ST_X32(tmem + cc * 32, rs);
    }
    TM_WAIT_ST();
    const float sinv = 1.f / ssum;
    TM_FENCE_BEFORE();
    __syncthreads();

    // ---- PV (V preloaded) ----
    if (wid == 0 && elect1()) {
        TM_FENCE_AFTER();
        const uint32_t vbuf[4] = {AS_KV2, AS_KV3, AS_KV0, AS_KV1};
#pragma unroll
        for (int j = 0; j < 4; j++) {
            MBAR_WAIT(sbase + 32 + 8 * j, 0);
            FENCE_ASYNC();
            uint64_t vd = mkdesc(sbase + vbuf[j]);
#pragma unroll
            for (int s = 0; s < 8; s++)
                mma_ts(tmem + 256, tmem + j * 64 + s * 8,
                       vd + (s >> 2) * 1024 + (s & 3) * 2, IDESC_128,
                       (j > 0 || s > 0) ? 1u : 0u);
        }
        TM_COMMIT(sbase + 64);
    }
    MBAR_WAIT(sbase + 64, 0);
    TM_FENCE_AFTER();

    // ---- epilogue: (O*sinv + o1h)*g2' + be2, relu -> o2T fp16 ----
    const float* g2s  = (const float*)(sm + 1024);
    const float* be2s = (const float*)(sm + 1536);
    const __half* myo1 = o1p + (size_t)(wid * 32 + lane) * PP;
    __half* myo2       = o2p + (size_t)(wid * 32 + lane) * PP;
#pragma unroll
    for (int k = 0; k < 4; k++) {
        TM_LD_X32(rs, tmem + 256 + k * 32);
        TM_WAIT_LD();
#pragma unroll
        for (int i = 0; i < 32; i += 4) {
            int d = k * 32 + i;
            uint2 h4 = *(const uint2*)(myo1 + d);
            float2 r01 = __half22float2(*(__half2*)&h4.x);
            float2 r23 = __half22float2(*(__half2*)&h4.y);
            float o0 = fmaxf(fmaf(fmaf(__uint_as_float(rs[i + 0]), sinv, r01.x), g2s[d + 0], be2s[d + 0]), 0.f);
            float o1 = fmaxf(fmaf(fmaf(__uint_as_float(rs[i + 1]), sinv, r01.y), g2s[d + 1], be2s[d + 1]), 0.f);
            float o2 = fmaxf(fmaf(fmaf(__uint_as_float(rs[i + 2]), sinv, r23.x), g2s[d + 2], be2s[d + 2]), 0.f);
            float o3 = fmaxf(fmaf(fmaf(__uint_as_float(rs[i + 3]), sinv, r23.y), g2s[d + 3], be2s[d + 3]), 0.f);
            uint2 oh;
            *(__half2*)&oh.x = __floats2half2_rn(o0, o1);
            *(__half2*)&oh.y = __floats2half2_rn(o2, o3);
            *(uint2*)(myo2 + d) = oh;
        }
    }
    __syncthreads();
    if (wid == 0) TM_DEALLOC(tmem, 512);

#else  // fp32 fallback
    const int x = t;
    float sb[256];
    float mx = -1e30f;
    for (int y = 0; y < 256; y++) {
        float s = 0.f;
        for (int d = 0; d < DH; d++)
            s += qp[(size_t)x * PP + d] * kp[(size_t)y * PP + d];
        sb[y] = s;
        mx = fmaxf(mx, s);
    }
    float ssum = 0.f;
    for (int y = 0; y < 256; y++) { sb[y] = __expf(sb[y] - mx); ssum += sb[y]; }
    float sinv = 1.f / ssum;
    for (int d = 0; d < DH; d++) {
        float o = 0.f;
        for (int y = 0; y < 256; y++) o += sb[y] * vp[(size_t)d * NN + y];
        float val = (o * sinv + __half2float(o1p[(size_t)x * PP + d]))
                    * (g2[hh * DH + d] * INVF) + be2[hh * DH + d];
        o2p[(size_t)x * PP + d] = __float2half_rn(fmaxf(val, 0.f));
    }
#endif
}

// ---------------------------------------------------------------------------
extern "C" void kernel_launch(void* const* d_in, const int* in_sizes, int n_in,
                              void* d_out, int out_size)
{
    const float* x   = (const float*)d_in[0];
    const float* w1  = (const float*)d_in[1];
    const float* b1  = (const float*)d_in[2];
    const float* g1  = (const float*)d_in[3];
    const float* be1 = (const float*)d_in[4];
    const float* wq  = (const float*)d_in[5];
    const float* wk  = (const float*)d_in[6];
    const float* wv  = (const float*)d_in[7];
    const float* g2  = (const float*)d_in[8];
    const float* be2 = (const float*)d_in[9];
    const float* w3  = (const float*)d_in[10];
    const float* b3  = (const float*)d_in[11];
    const float* g3  = (const float*)d_in[12];
    const float* be3 = (const float*)d_in[13];
    float* out = (float*)d_out;

    __half *xT, *o1T, *o2T, *wr;
    float *qT, *kT, *vb;
    cudaGetSymbolAddress((void**)&xT,  g_xT);
    cudaGetSymbolAddress((void**)&o1T, g_o1T);
    cudaGetSymbolAddress((void**)&qT,  g_qT);
    cudaGetSymbolAddress((void**)&kT,  g_kT);
    cudaGetSymbolAddress((void**)&vb,  g_v);
    cudaGetSymbolAddress((void**)&o2T, g_o2T);
    cudaGetSymbolAddress((void**)&wr,  g_wr);

    cudaFuncSetAttribute((const void*)tgp<0>, cudaFuncAttributeMaxDynamicSharedMemorySize, GSMEM);
    cudaFuncSetAttribute((const void*)tgp<1>, cudaFuncAttributeMaxDynamicSharedMemorySize, GSMEM);
    cudaFuncSetAttribute((const void*)tgp<2>, cudaFuncAttributeMaxDynamicSharedMemorySize, GSMEM);
    cudaFuncSetAttribute((const void*)attn_tc, cudaFuncAttributeMaxDynamicSharedMemorySize, ASMEM);

    // 0a) weights -> fp16 (contiguous)
    round_w5<<<(N4_TOT + 255) / 256, 256>>>(w1, wq, wk, wv, w3, wr);
    // 0b) xT[b][hw][c] fp16
    transpose_k<<<dim3(64, 32, BB), 256>>>(x, xT, CIN, NN);
    // 1) conv1 -> o1T fp16 (persistent WS, f16 MMA)
    tgp<0><<<GRID_P, 256, GSMEM>>>(wr + WR_W1, xT, o1T, nullptr, nullptr,
                                   nullptr, g1, be1, b1);
    // 2) fused qkv -> qT/kT/v fp32 (attention unchanged)
    tgp<1><<<GRID_P, 256, GSMEM>>>(wr + WR_WQ, o1T, qT, kT, vb,
                                   nullptr, nullptr, nullptr, nullptr);
    // 3) attention (tf32 MMAs) -> o2T fp16
    attn_tc<<<dim3(2, 32, BB), 128, ASMEM>>>(qT, kT, vb, o1T, g2, be2, o2T);
    // 4) conv3 (f16 MMA) -> out fp32 (bn3 + resid + relu)
    tgp<2><<<GRID_P, 256, GSMEM>>>(wr + WR_W3, o2T, out, nullptr, nullptr,
                                   x, g3, be3, b3);
}

// round 16
// speedup vs baseline: 2.3476x; 1.1232x over previous
#include <cuda_runtime.h>
#include <cuda_fp16.h>
#include <cstdint>

// Problem constants
#define BB 16
#define CIN 1024
#define PP 512
#define NN 2048          // H*W
#define DH 128           // head dim
#define INVF 0.99999500003749969f      // 1/sqrt(1+1e-5)
#define QSCALE 0.08838834764831843f    // 128^-0.5
#define GRID_P 152                      // GB300 SM count (persistent grid)

#if defined(__CUDA_ARCH__) && (__CUDA_ARCH__ >= 1000) && \
    (defined(__CUDA_ARCH_FEAT_SM103_ALL) || defined(__CUDA_ARCH_FEAT_SM100_ALL) || \
     defined(__CUDA_ARCH_SPECIFIC__) || defined(__CUDA_ARCH_FAMILY_SPECIFIC__))
#define HAS_TCGEN05 1
#else
#define HAS_TCGEN05 0
#endif

// Scratch (device globals) — fully fp16 intermediates
__device__ __half g_xT [(size_t)BB * CIN * NN];   // [b][hw][c]
__device__ __half g_o1T[(size_t)BB * PP * NN];    // [b][hw][p]
__device__ __half g_qT [(size_t)BB * PP * NN];    // [b][hw][p] (pre-scaled)
__device__ __half g_kT [(size_t)BB * PP * NN];    // [b][hw][p]
__device__ __half g_v  [(size_t)BB * PP * NN];    // [b][p][hw]
__device__ __half g_o2T[(size_t)BB * PP * NN];    // [b][hw][p]
// fp16 weights, contiguous: w1 | wq | wk | wv | w3
#define WR_W1 0
#define WR_WQ (512 * 1024)
#define WR_WK (WR_WQ + 512 * 512)
#define WR_WV (WR_WK + 512 * 512)
#define WR_W3 (WR_WV + 512 * 512)
__device__ __half g_wr[WR_W3 + 1024 * 512];

// ---------------------------------------------------------------------------
__device__ __forceinline__ uint32_t smem_u32(const void* p) {
    uint32_t a;
    asm("{ .reg .u64 t; cvta.to.shared.u64 t, %1; cvt.u32.u64 %0, t; }"
        : "=r"(a) : "l"(p));
    return a;
}
__device__ __forceinline__ uint32_t h2_bits(__half2 h) {
    return *(uint32_t*)&h;
}

#if HAS_TCGEN05
__device__ __forceinline__ uint32_t elect1() {
    uint32_t p;
    asm volatile("{ .reg .pred p; elect.sync _|p, 0xFFFFFFFF; selp.b32 %0,1,0,p; }"
                 : "=r"(p));
    return p;
}
#define SW128(o) ((o) ^ ((((uint32_t)(o)) >> 3) & 0x70))

#define MBAR_INIT(a, c) \
    asm volatile("mbarrier.init.shared.b64 [%0], %1;" :: "r"(a), "r"(c) : "memory")

#define MBAR_ARRIVE(a) \
    asm volatile("mbarrier.arrive.shared::cta.b64 _, [%0];" :: "r"(a) : "memory")

#define MBAR_WAIT(a, ph) do { \
    uint32_t _d; \
    asm volatile("{ .reg .pred p; mbarrier.try_wait.parity.acquire.cta.shared::cta.b64 p,[%1],%2; selp.b32 %0,1,0,p; }" \
                 : "=r"(_d) : "r"(a), "r"((uint32_t)(ph)) : "memory"); \
    if (!_d) { \
        asm volatile("{ .reg .pred P;\nLW_%=:\nmbarrier.try_wait.parity.acquire.cta.shared::cta.b64 P,[%0],%1,0x989680;\n@P bra.uni LD_%=;\nbra.uni LW_%=;\nLD_%=:\n}" \
                     :: "r"(a), "r"((uint32_t)(ph)) : "memory"); \
    } } while (0)

#define TM_ALLOC(sa, n) \
    asm volatile("tcgen05.alloc.cta_group::1.sync.aligned.shared::cta.b32 [%0], %1;" \
                 :: "r"(sa), "r"(n) : "memory")
#define TM_DEALLOC(t, n) \
    asm volatile("tcgen05.dealloc.cta_group::1.sync.aligned.b32 %0, %1;" :: "r"(t), "r"(n))
#define TM_COMMIT(mb) \
    asm volatile("tcgen05.commit.cta_group::1.mbarrier::arrive::one.shared::cluster.b64 [%0];" \
                 :: "r"(mb) : "memory")
#define TM_FENCE_AFTER()  asm volatile("tcgen05.fence::after_thread_sync;" ::: "memory")
#define TM_FENCE_BEFORE() asm volatile("tcgen05.fence::before_thread_sync;" ::: "memory")
#define TM_WAIT_LD()      asm volatile("tcgen05.wait::ld.sync.aligned;" ::: "memory")
#define TM_WAIT_ST()      asm volatile("tcgen05.wait::st.sync.aligned;" ::: "memory")
#define FENCE_ASYNC()     asm volatile("fence.proxy.async.shared::cta;" ::: "memory")

#define CP_ASYNC16(dst, src) \
    asm volatile("cp.async.cg.shared.global [%0], [%1], 16;" \
                 :: "r"(dst), "l"(src) : "memory")
#define CP_MBAR_ARRIVE(mb) \
    asm volatile("cp.async.mbarrier.arrive.noinc.shared::cta.b64 [%0];" \
                 :: "r"(mb) : "memory")

#define TM_LD_X32(r, addr) \
    asm volatile("tcgen05.ld.sync.aligned.32x32b.x32.b32 " \
        "{%0,%1,%2,%3,%4,%5,%6,%7,%8,%9,%10,%11,%12,%13,%14,%15," \
        "%16,%17,%18,%19,%20,%21,%22,%23,%24,%25,%26,%27,%28,%29,%30,%31}, [%32];" \
        : "=r"((r)[0]),"=r"((r)[1]),"=r"((r)[2]),"=r"((r)[3]), \
          "=r"((r)[4]),"=r"((r)[5]),"=r"((r)[6]),"=r"((r)[7]), \
          "=r"((r)[8]),"=r"((r)[9]),"=r"((r)[10]),"=r"((r)[11]), \
          "=r"((r)[12]),"=r"((r)[13]),"=r"((r)[14]),"=r"((r)[15]), \
          "=r"((r)[16]),"=r"((r)[17]),"=r"((r)[18]),"=r"((r)[19]), \
          "=r"((r)[20]),"=r"((r)[21]),"=r"((r)[22]),"=r"((r)[23]), \
          "=r"((r)[24]),"=r"((r)[25]),"=r"((r)[26]),"=r"((r)[27]), \
          "=r"((r)[28]),"=r"((r)[29]),"=r"((r)[30]),"=r"((r)[31]) \
        : "r"(addr))

#define TM_ST_X16(addr, r) \
    asm volatile("tcgen05.st.sync.aligned.32x32b.x16.b32 [%0], " \
        "{%1,%2,%3,%4,%5,%6,%7,%8,%9,%10,%11,%12,%13,%14,%15,%16};" \
        :: "r"(addr), \
           "r"((r)[0]),"r"((r)[1]),"r"((r)[2]),"r"((r)[3]), \
           "r"((r)[4]),"r"((r)[5]),"r"((r)[6]),"r"((r)[7]), \
           "r"((r)[8]),"r"((r)[9]),"r"((r)[10]),"r"((r)[11]), \
           "r"((r)[12]),"r"((r)[13]),"r"((r)[14]),"r"((r)[15]) \
        : "memory")

__device__ __forceinline__ uint64_t mkdesc(uint32_t addr) {
    return ((uint64_t)2 << 61) | ((uint64_t)1 << 46) | ((uint64_t)64 << 32) |
           ((uint64_t)1 << 16) | ((addr >> 4) & 0x3FFF);
}
__device__ __forceinline__ void mma_ss_f16(uint32_t d, uint64_t ad, uint64_t bd,
                                           uint32_t id, uint32_t en) {
    asm volatile(
        "{ .reg .pred p; setp.ne.u32 p, %5, 0;\n\t"
        "tcgen05.mma.cta_group::1.kind::f16 [%0], %1, %2, %3, {%4,%4,%4,%4}, p;\n\t}"
        :: "r"(d), "l"(ad), "l"(bd), "r"(id), "r"(0u), "r"(en) : "memory");
}
__device__ __forceinline__ void mma_ts_f16(uint32_t d, uint32_t a, uint64_t bd,
                                           uint32_t id, uint32_t en) {
    asm volatile(
        "{ .reg .pred p; setp.ne.u32 p, %5, 0;\n\t"
        "tcgen05.mma.cta_group::1.kind::f16 [%0], [%1], %2, %3, {%4,%4,%4,%4}, p;\n\t}"
        :: "r"(d), "r"(a), "l"(bd), "r"(id), "r"(0u), "r"(en) : "memory");
}
// f16 (atype=btype=0), F32 accum
#define IDESC_H256 ((1u << 4) | (32u << 17) | (8u << 24))
#define IDESC_H128 ((1u << 4) | (16u << 17) | (8u << 24))
#endif  // HAS_TCGEN05

// ---------------------------------------------------------------------------
// Weights -> fp16 (one launch, contiguous g_wr)
// ---------------------------------------------------------------------------
#define N4_W1 131072
#define N4_P  65536
#define N4_W3 131072
#define N4_TOT (N4_W1 + 3 * N4_P + N4_W3)

__global__ __launch_bounds__(256)
void round_w5(const float* __restrict__ w1, const float* __restrict__ wq,
              const float* __restrict__ wk, const float* __restrict__ wv,
              const float* __restrict__ w3, __half* __restrict__ out)
{
    int i = blockIdx.x * 256 + threadIdx.x;
    if (i >= N4_TOT) return;
    const float4* src;
    int j = i;
    if (j < N4_W1) src = (const float4*)w1;
    else if ((j -= N4_W1) < N4_P) src = (const float4*)wq;
    else if ((j -= N4_P) < N4_P) src = (const float4*)wk;
    else if ((j -= N4_P) < N4_P) src = (const float4*)wv;
    else { j -= N4_P; src = (const float4*)w3; }
    float4 v = src[j];
    __half2* o = (__half2*)(out + (size_t)i * 4);
    o[0] = __floats2half2_rn(v.x, v.y);
    o[1] = __floats2half2_rn(v.z, v.w);
}

// ---------------------------------------------------------------------------
// Tiled transpose per batch, fp32 in -> fp16 out
// ---------------------------------------------------------------------------
__global__ __launch_bounds__(256)
void transpose_k(const float* __restrict__ in, __half* __restrict__ out, int R, int C)
{
    __shared__ float tile[32][33];
    const int b = blockIdx.z;
    const float* ip = in + (size_t)b * R * C;
    __half* op = out + (size_t)b * R * C;
    const int c0 = blockIdx.x * 32, r0 = blockIdx.y * 32;
    const int tx = threadIdx.x & 31, ty = threadIdx.x >> 5;
#pragma unroll
    for (int i = 0; i < 32; i += 8)
        tile[ty + i][tx] = ip[(size_t)(r0 + ty + i) * C + c0 + tx];
    __syncthreads();
#pragma unroll
    for (int i = 0; i < 32; i += 8)
        op[(size_t)(c0 + ty + i) * R + r0 + tx] = __float2half_rn(tile[tx][ty + i]);
}

// ---------------------------------------------------------------------------
// Warp-specialized persistent tcgen05 fp16 GEMM (R14 structure).
// MODE 0: conv1 K=1024 -> o1T fp16 (bn1+relu)
// MODE 1: qkv  K=512: id<1024 -> qT/kT fp16 (q scaled); id>=1024 (flipped)
//              -> v fp16
// MODE 2: conv3 K=512 (flipped) -> out fp32 (bn3+resid+relu)
// ---------------------------------------------------------------------------
#define NSTAGE 4
#define STAGE_B 49152u
#define GS_BN   (1024u + NSTAGE * STAGE_B)
#define GSMEM   (GS_BN + 2 * 1024 * 4)

template <int MODE>
__device__ __forceinline__ void tile_ab(int id, const __half* W, const __half* ACT,
                                        const __half*& A, const __half*& B)
{
    if (MODE == 0) {
        int m0 = (id & 3) << 7, n0 = ((id >> 2) & 7) << 8, bz = id >> 5;
        A = W + (size_t)m0 * 1024;
        B = ACT + ((size_t)bz * NN + n0) * 1024;
    } else if (MODE == 1) {
        if (id < 1024) {
            int m0 = (id & 7) << 7, n0 = ((id >> 3) & 7) << 8, bz = id >> 6;
            A = W + (size_t)m0 * 512;
            B = ACT + ((size_t)bz * NN + n0) * 512;
        } else {
            int j = id - 1024;
            int m0 = (j & 15) << 7, n0 = ((j >> 4) & 1) << 8, bz = j >> 5;
            A = ACT + ((size_t)bz * NN + m0) * 512;
            B = W + 524288u + (size_t)n0 * 512;
        }
    } else {
        int m0 = (id & 15) << 7, n0 = ((id >> 4) & 3) << 8, bz = id >> 6;
        A = ACT + ((size_t)bz * NN + m0) * 512;
        B = W + (size_t)n0 * 512;
    }
}

template <int MODE>
__device__ __forceinline__ void epi_scalar(int id, int ml, int n, float acc,
    void* O0v, void* O1v, void* O2v, const float* resid,
    const float* g, const float* be, const float* cb)
{
    if (MODE == 0) {
        int m0 = (id & 3) << 7, n0 = ((id >> 2) & 7) << 8, bz = id >> 5;
        int m = m0 + ml;
        float s = g[m] * INVF, tt = cb[m] * s + be[m];
        ((__half*)O0v)[((size_t)bz * NN + n0 + n) * 512 + m] =
            __float2half_rn(fmaxf(fmaf(acc, s, tt), 0.f));
    } else if (MODE == 1) {
        if (id < 1024) {
            int m0 = (id & 7) << 7, n0 = ((id >> 3) & 7) << 8, bz = id >> 6;
            __half* T = (m0 < 512) ? (__half*)O0v : (__half*)O1v;
            float qs = (m0 < 512) ? QSCALE : 1.f;
            T[((size_t)bz * NN + n0 + n) * 512 + ((m0 + ml) & 511)] =
                __float2half_rn(acc * qs);
        } else {
            int j = id - 1024;
            int m0 = (j & 15) << 7, n0 = ((j >> 4) & 1) << 8, bz = j >> 5;
            ((__half*)O2v)[((size_t)bz * 512 + n0 + n) * NN + m0 + ml] =
                __float2half_rn(acc);
        }
    } else {
        int m0 = (id & 15) << 7, n0 = ((id >> 4) & 3) << 8, bz = id >> 6;
        int c = n0 + n;
        float s = g[c] * INVF, tt = cb[c] * s + be[c];
        size_t off = ((size_t)bz * 1024 + c) * NN + m0 + ml;
        ((float*)O0v)[off] = fmaxf(fmaf(acc, s, tt) + resid[off], 0.f);
    }
}

#if HAS_TCGEN05
template <int MODE>
__device__ __forceinline__ void issue_chunk(uint32_t sbase, int gc, int cta,
                                            const __half* W, const __half* ACT, int t)
{
    constexpr int NKS = (MODE == 0) ? 4 : 3;
    constexpr int K = (MODE == 0) ? 1024 : 512;
    const int lt = gc >> NKS, c = gc & ((1 << NKS) - 1);
    const __half *A, *B;
    tile_ab<MODE>(cta + lt * GRID_P, W, ACT, A, B);
    const uint32_t st = sbase + 1024u + (uint32_t)(gc & 3) * STAGE_B;
#pragma unroll
    for (int r = 0; r < 8; r++) {
        int idx = t + r * 128, row = idx >> 3, seg = idx & 7;
        CP_ASYNC16(st + SW128(row * 128 + seg * 16),
                   A + (size_t)row * K + c * 64 + seg * 8);
    }
#pragma unroll
    for (int r = 0; r < 16; r++) {
        int idx = t + r * 128, row = idx >> 3, seg = idx & 7;
        CP_ASYNC16(st + 16384u + SW128(row * 128 + seg * 16),
                   B + (size_t)row * K + c * 64 + seg * 8);
    }
    CP_MBAR_ARRIVE(sbase + 16 + 8 * (gc & 3));
}

template <int MODE>
__device__ __forceinline__ void epi_tile(int id, int abuf, uint32_t tmem, char* smem,
    void* O0v, void* O1v, void* O2v, const float* resid,
    const float* g, const float* be, const float* cb, int wid, int lane)
{
    __half* Oh = nullptr; float* Of = nullptr;
    const float* Rb = nullptr;
    size_t sN; int n0g = 0, m0;
    float qs = 1.f;
    if (MODE == 0) {
        m0 = (id & 3) << 7; int n0 = ((id >> 2) & 7) << 8; int bz = id >> 5;
        Oh = (__half*)O0v + ((size_t)bz * NN + n0) * 512 + m0;  sN = 512;
    } else if (MODE == 1) {
        if (id < 1024) {
            m0 = (id & 7) << 7; int n0 = ((id >> 3) & 7) << 8; int bz = id >> 6;
            __half* T = (m0 < 512) ? (__half*)O0v : (__half*)O1v;
            if (m0 < 512) qs = QSCALE;
            Oh = T + ((size_t)bz * NN + n0) * 512 + (m0 & 511);  sN = 512;
        } else {
            int j = id - 1024;
            m0 = (j & 15) << 7; int n0 = ((j >> 4) & 1) << 8; int bz = j >> 5;
            Oh = (__half*)O2v + ((size_t)bz * 512 + n0) * NN + m0;  sN = NN;
        }
    } else {
        m0 = (id & 15) << 7; int n0 = ((id >> 4) & 3) << 8; int bz = id >> 6;
        Of = (float*)O0v + ((size_t)bz * 1024 + n0) * NN + m0;
        Rb = resid + ((size_t)bz * 1024 + n0) * NN + m0;
        sN = NN; n0g = n0;
    }
    const int ml = (wid & 3) * 32 + lane;
    float sL = qs, tL = 0.f;
    if (MODE == 0) { int m = m0 + ml; sL = g[m] * INVF; tL = cb[m] * sL + be[m]; }
    const float* bs = (const float*)(smem + GS_BN);
    const float* bt = (const float*)(smem + GS_BN + 4096);

    uint32_t r0[32];
#pragma unroll
    for (int k = 0; k < 8; k++) {
        TM_LD_X32(r0, tmem + abuf * 256 + k * 32);
        TM_WAIT_LD();
#pragma unroll
        for (int i = 0; i < 32; i++) {
            const int n = k * 32 + i;
            float v = __uint_as_float(r0[i]);
            if (MODE == 2) {
                v = fmaxf(fmaf(v, bs[n0g + n], bt[n0g + n]) + Rb[(size_t)n * sN + ml], 0.f);
                Of[(size_t)n * sN + ml] = v;
            } else if (MODE == 0) {
                Oh[(size_t)n * sN + ml] =
                    __float2half_rn(fmaxf(fmaf(v, sL, tL), 0.f));
            } else {
                Oh[(size_t)n * sN + ml] = __float2half_rn(v * sL);
            }
        }
    }
}
#endif  // HAS_TCGEN05

template <int MODE>
__global__ __launch_bounds__(256)
void tgp(const __half* __restrict__ W, const __half* __restrict__ ACT,
         void* __restrict__ O0v, void* __restrict__ O1v, void* __restrict__ O2v,
         const float* __restrict__ resid,
         const float* __restrict__ g, const float* __restrict__ be,
         const float* __restrict__ cb)
{
    constexpr int TOT   = (MODE == 0) ? 512 : (MODE == 1) ? 1536 : 1024;
    constexpr int NKS   = (MODE == 0) ? 4 : 3;
    constexpr int NK    = 1 << NKS;
    const int cta = blockIdx.x;
    const int t = threadIdx.x;
    const int ntl = (TOT - cta + GRID_P - 1) / GRID_P;
    if (ntl <= 0) return;
    const int totc = ntl * NK;

#if HAS_TCGEN05
    extern __shared__ char smem[];
    const uint32_t sbase = smem_u32(smem);
    const int wid = t >> 5, lane = t & 31;
    if (t < 4)                MBAR_INIT(sbase + 16 + 8 * t, 128);
    else if (t < 8)           MBAR_INIT(sbase + 48 + 8 * (t - 4), 1);
    else if (t < 10)          MBAR_INIT(sbase + 80 + 8 * (t - 8), 1);
    else if (t < 12)          MBAR_INIT(sbase + 96 + 8 * (t - 10), 128);
    if (wid == 0) TM_ALLOC(sbase + 0, 512);
    if (MODE == 2) {
        for (int i = t; i < 1024; i += 256) {
            float s = g[i] * INVF;
            ((float*)(smem + GS_BN))[i] = s;
            ((float*)(smem + GS_BN + 4096))[i] = cb[i] * s + be[i];
        }
    }
    __syncthreads();
    uint32_t tmem;
    asm volatile("ld.shared.b32 %0, [%1];" : "=r"(tmem) : "r"(sbase + 0));

    if (t < 128) {
        issue_chunk<MODE>(sbase, 0, cta, W, ACT, t);
        if (totc > 1) issue_chunk<MODE>(sbase, 1, cta, W, ACT, t);
        if (totc > 2) issue_chunk<MODE>(sbase, 2, cta, W, ACT, t);

        for (int gc = 0; gc < totc; gc++) {
            const int s = gc & 3, c = gc & (NK - 1), lt = gc >> NKS;
            if (wid == 0 && elect1()) {
                if (c == 0 && lt >= 2) {
                    MBAR_WAIT(sbase + 96 + 8 * (lt & 1), ((lt >> 1) - 1) & 1);
                    TM_FENCE_AFTER();
                }
                MBAR_WAIT(sbase + 16 + 8 * s, (gc >> 2) & 1);
                FENCE_ASYNC();
                const uint32_t st = sbase + 1024u + (uint32_t)s * STAGE_B;
                const uint64_t ad = mkdesc(st);
                const uint64_t bd = mkdesc(st + 16384u);
                const uint32_t dacc = tmem + (uint32_t)((lt & 1) << 8);
#pragma unroll
                for (int si = 0; si < 4; si++)
                    mma_ss_f16(dacc, ad + si * 2, bd + si * 2, IDESC_H256,
                               (c > 0 || si > 0) ? 1u : 0u);
                TM_COMMIT(sbase + 48 + 8 * s);
            }
            if (gc >= 1) {
                MBAR_WAIT(sbase + 48 + 8 * ((gc - 1) & 3), ((gc - 1) >> 2) & 1);
                if (c == 0 && wid == 0 && elect1())
                    MBAR_ARRIVE(sbase + 80 + 8 * ((lt - 1) & 1));
            }
            if (gc + 3 < totc) issue_chunk<MODE>(sbase, gc + 3, cta, W, ACT, t);
        }
        MBAR_WAIT(sbase + 48 + 8 * ((totc - 1) & 3), ((totc - 1) >> 2) & 1);
        if (wid == 0 && elect1())
            MBAR_ARRIVE(sbase + 80 + 8 * ((ntl - 1) & 1));
    } else {
        for (int lt = 0; lt < ntl; lt++) {
            MBAR_WAIT(sbase + 80 + 8 * (lt & 1), (lt >> 1) & 1);
            TM_FENCE_AFTER();
            epi_tile<MODE>(cta + lt * GRID_P, lt & 1, tmem, smem,
                           O0v, O1v, O2v, resid, g, be, cb, wid, lane);
            TM_FENCE_BEFORE();
            MBAR_ARRIVE(sbase + 96 + 8 * (lt & 1));
        }
    }
    __syncthreads();
    if (wid == 0) TM_DEALLOC(tmem, 512);

#else  // fp32 fallback
    constexpr int K = (MODE == 0) ? 1024 : 512;
    for (int lt = 0; lt < ntl; lt++) {
        const int id = cta + lt * GRID_P;
        const __half *A, *B;
        tile_ab<MODE>(id, W, ACT, A, B);
        for (int e = t; e < 128 * 256; e += 256) {
            const int ml = e & 127, n = e >> 7;
            float acc = 0.f;
            for (int k = 0; k < K; k++)
                acc += __half2float(A[(size_t)ml * K + k]) *
                       __half2float(B[(size_t)n * K + k]);
            epi_scalar<MODE>(id, ml, n, acc, O0v, O1v, O2v, resid, g, be, cb);
        }
    }
#endif
}

// ---------------------------------------------------------------------------
// Fully-fp16 tcgen05 attention. All loads cp.async up front:
//   Q (32KB, 2 K64 atoms) + K (64KB, 2 atoms) -> qkb ; V (64KB, 4 chunks) -> vb.
// S = Q.K^T (f16, 8 MMAs, commit smb) -> softmax (fp32 from TMEM, P packed
// fp16 into TMEM cols 256..384) -> PV (TS f16, 16 MMAs, commit pvb) ->
// epilogue from cols 384..512. Four single-use barriers; no parity reuse.
// TMEM: S[0,256) fp32 | P[256,384) fp16-packed | O[384,512) fp32.
// ---------------------------------------------------------------------------
#define AS_Q  2048u
#define AS_K  (2048u + 32768u)
#define AS_V  (AS_K + 65536u)
#define ASMEM (2048 + 32768 + 65536 + 65536)   // 166912

__global__ __launch_bounds__(128)
void attn_tc(const __half* __restrict__ qT, const __half* __restrict__ kT,
             const __half* __restrict__ v, const __half* __restrict__ o1T,
             const float* __restrict__ g2, const float* __restrict__ be2,
             __half* __restrict__ o2T)
{
    extern __shared__ char sm[];
    const int t = threadIdx.x, wid = t >> 5, lane = t & 31;
    const int xt = blockIdx.x;
    const int sp = blockIdx.y >> 2, hh = blockIdx.y & 3;
    const int b = blockIdx.z;

    const size_t qrow = (size_t)b * NN + sp * 256 + xt * 128;
    const __half* qp  = qT  + qrow * PP + hh * DH;
    const __half* kp  = kT  + ((size_t)b * NN + sp * 256) * PP + hh * DH;
    const __half* vp  = v   + ((size_t)b * PP + hh * DH) * NN + sp * 256;
    const __half* o1p = o1T + qrow * PP + hh * DH;
    __half* o2p       = o2T + qrow * PP + hh * DH;

#if HAS_TCGEN05
    const uint32_t sbase = smem_u32(sm);
    // single-use mbars: qkb@16(128) vb@24(128) smb@32(1) pvb@40(1)
    if (t == 0) { MBAR_INIT(sbase + 16, 128); MBAR_INIT(sbase + 24, 128);
                  MBAR_INIT(sbase + 32, 1);   MBAR_INIT(sbase + 40, 1); }
    if (wid == 0) TM_ALLOC(sbase + 0, 512);
    ((float*)(sm + 1024))[t] = g2[hh * DH + t] * INVF;
    ((float*)(sm + 1536))[t] = be2[hh * DH + t];
    __syncthreads();
    uint32_t tmem;
    asm volatile("ld.shared.b32 %0, [%1];" : "=r"(tmem) : "r"(sbase + 0));

    // ---- Q (128x128h, atoms j=k>>6) + K (256x128h) -> qkb ----
#pragma unroll
    for (int r = 0; r < 16; r++) {
        int i = t + r * 128, row = i >> 4, s16 = i & 15;
        int j = s16 >> 3, sg = s16 & 7;
        CP_ASYNC16(sbase + AS_Q + j * 16384u + SW128(row * 128 + sg * 16),
                   qp + (size_t)row * PP + s16 * 8);
    }
#pragma unroll
    for (int r = 0; r < 32; r++) {
        int i = t + r * 128, row = i >> 4, s16 = i & 15;
        int j = s16 >> 3, sg = s16 & 7;
        CP_ASYNC16(sbase + AS_K + j * 32768u + SW128(row * 128 + sg * 16),
                   kp + (size_t)row * PP + s16 * 8);
    }
    CP_MBAR_ARRIVE(sbase + 16);
    // ---- V (128 d-rows x 256 keys; chunk j = key>>6) -> vb ----
#pragma unroll
    for (int r = 0; r < 32; r++) {
        int i = t + r * 128, row = i >> 5, s32 = i & 31;
        int j = s32 >> 3, sg = s32 & 7;
        CP_ASYNC16(sbase + AS_V + j * 16384u + SW128(row * 128 + sg * 16),
                   vp + (size_t)row * NN + s32 * 8);
    }
    CP_MBAR_ARRIVE(sbase + 24);

    // ---- S = Q.K^T (8 f16 MMAs, single commit) ----
    if (wid == 0 && elect1()) {
        MBAR_WAIT(sbase + 16, 0);
        FENCE_ASYNC();
#pragma unroll
        for (int j = 0; j < 2; j++) {
            uint64_t qd = mkdesc(sbase + AS_Q + j * 16384u);
            uint64_t kd = mkdesc(sbase + AS_K + j * 32768u);
#pragma unroll
            for (int s = 0; s < 4; s++)
                mma_ss_f16(tmem, qd + s * 2, kd + s * 2, IDESC_H256,
                           (j > 0 || s > 0) ? 1u : 0u);
        }
        TM_COMMIT(sbase + 32);
    }
    MBAR_WAIT(sbase + 32, 0);
    TM_FENCE_AFTER();

    // ---- softmax; lane = query row; pack P fp16 into cols 256..384 ----
    uint32_t rs[32];
    float mx = -1e30f;
#pragma unroll
    for (int cc = 0; cc < 8; cc++) {
        TM_LD_X32(rs, tmem + cc * 32);
        TM_WAIT_LD();
#pragma unroll
        for (int i = 0; i < 32; i++) mx = fmaxf(mx, __uint_as_float(rs[i]));
    }
    float ssum = 0.f;
#pragma unroll
    for (int cc = 0; cc < 8; cc++) {
        TM_LD_X32(rs, tmem + cc * 32);
        TM_WAIT_LD();
        uint32_t pk[16];
#pragma unroll
        for (int i = 0; i < 32; i += 2) {
            float e0 = __expf(__uint_as_float(rs[i]) - mx);
            float e1 = __expf(__uint_as_float(rs[i + 1]) - mx);
            ssum += e0 + e1;
            __half2 hp = __floats2half2_rn(e0, e1);
            pk[i >> 1] = h2_bits(hp);
        }
        TM_ST_X16(tmem + 256 + cc * 16, pk);
    }
    TM_WAIT_ST();
    const float sinv = 1.f / ssum;
    TM_FENCE_BEFORE();
    __syncthreads();              // all P stores visible before PV

    // ---- PV = P.V (TS f16; 4 chunks x 4 K16 steps; single commit) ----
    if (wid == 0 && elect1()) {
        TM_FENCE_AFTER();
        MBAR_WAIT(sbase + 24, 0);
        FENCE_ASYNC();
#pragma unroll
        for (int j = 0; j < 4; j++) {
            uint64_t vd = mkdesc(sbase + AS_V + j * 16384u);
#pragma unroll
            for (int s = 0; s < 4; s++)
                mma_ts_f16(tmem + 384, tmem + 256 + j * 32 + s * 8,
                           vd + s * 2, IDESC_H128,
                           (j > 0 || s > 0) ? 1u : 0u);
        }
        TM_COMMIT(sbase + 40);
    }
    MBAR_WAIT(sbase + 40, 0);
    TM_FENCE_AFTER();

    // ---- epilogue: (O*sinv + o1h)*g2' + be2, relu -> o2T fp16 ----
    const float* g2s  = (const float*)(sm + 1024);
    const float* be2s = (const float*)(sm + 1536);
    const __half* myo1 = o1p + (size_t)(wid * 32 + lane) * PP;
    __half* myo2       = o2p + (size_t)(wid * 32 + lane) * PP;
#pragma unroll
    for (int k = 0; k < 4; k++) {
        TM_LD_X32(rs, tmem + 384 + k * 32);
        TM_WAIT_LD();
#pragma unroll
        for (int i = 0; i < 32; i += 4) {
            int d = k * 32 + i;
            uint2 h4 = *(const uint2*)(myo1 + d);
            float2 r01 = __half22float2(*(__half2*)&h4.x);
            float2 r23 = __half22float2(*(__half2*)&h4.y);
            float o0 = fmaxf(fmaf(fmaf(__uint_as_float(rs[i + 0]), sinv, r01.x), g2s[d + 0], be2s[d + 0]), 0.f);
            float o1 = fmaxf(fmaf(fmaf(__uint_as_float(rs[i + 1]), sinv, r01.y), g2s[d + 1], be2s[d + 1]), 0.f);
            float o2 = fmaxf(fmaf(fmaf(__uint_as_float(rs[i + 2]), sinv, r23.x), g2s[d + 2], be2s[d + 2]), 0.f);
            float o3 = fmaxf(fmaf(fmaf(__uint_as_float(rs[i + 3]), sinv, r23.y), g2s[d + 3], be2s[d + 3]), 0.f);
            uint2 oh;
            *(__half2*)&oh.x = __floats2half2_rn(o0, o1);
            *(__half2*)&oh.y = __floats2half2_rn(o2, o3);
            *(uint2*)(myo2 + d) = oh;
        }
    }
    __syncthreads();
    if (wid == 0) TM_DEALLOC(tmem, 512);

#else  // fp32 fallback
    const int x = t;
    float sb[256];
    float mx = -1e30f;
    for (int y = 0; y < 256; y++) {
        float s = 0.f;
        for (int d = 0; d < DH; d++)
            s += __half2float(qp[(size_t)x * PP + d]) *
                 __half2float(kp[(size_t)y * PP + d]);
        sb[y] = s;
        mx = fmaxf(mx, s);
    }
    float ssum = 0.f;
    for (int y = 0; y < 256; y++) { sb[y] = __expf(sb[y] - mx); ssum += sb[y]; }
    float sinv = 1.f / ssum;
    for (int d = 0; d < DH; d++) {
        float o = 0.f;
        for (int y = 0; y < 256; y++)
            o += sb[y] * __half2float(vp[(size_t)d * NN + y]);
        float val = (o * sinv + __half2float(o1p[(size_t)x * PP + d]))
                    * (g2[hh * DH + d] * INVF) + be2[hh * DH + d];
        o2p[(size_t)x * PP + d] = __float2half_rn(fmaxf(val, 0.f));
    }
#endif
}

// ---------------------------------------------------------------------------
extern "C" void kernel_launch(void* const* d_in, const int* in_sizes, int n_in,
                              void* d_out, int out_size)
{
    const float* x   = (const float*)d_in[0];
    const float* w1  = (const float*)d_in[1];
    const float* b1  = (const float*)d_in[2];
    const float* g1  = (const float*)d_in[3];
    const float* be1 = (const float*)d_in[4];
    const float* wq  = (const float*)d_in[5];
    const float* wk  = (const float*)d_in[6];
    const float* wv  = (const float*)d_in[7];
    const float* g2  = (const float*)d_in[8];
    const float* be2 = (const float*)d_in[9];
    const float* w3  = (const float*)d_in[10];
    const float* b3  = (const float*)d_in[11];
    const float* g3  = (const float*)d_in[12];
    const float* be3 = (const float*)d_in[13];
    float* out = (float*)d_out;

    __half *xT, *o1T, *qT, *kT, *vb, *o2T, *wr;
    cudaGetSymbolAddress((void**)&xT,  g_xT);
    cudaGetSymbolAddress((void**)&o1T, g_o1T);
    cudaGetSymbolAddress((void**)&qT,  g_qT);
    cudaGetSymbolAddress((void**)&kT,  g_kT);
    cudaGetSymbolAddress((void**)&vb,  g_v);
    cudaGetSymbolAddress((void**)&o2T, g_o2T);
    cudaGetSymbolAddress((void**)&wr,  g_wr);

    cudaFuncSetAttribute((const void*)tgp<0>, cudaFuncAttributeMaxDynamicSharedMemorySize, GSMEM);
    cudaFuncSetAttribute((const void*)tgp<1>, cudaFuncAttributeMaxDynamicSharedMemorySize, GSMEM);
    cudaFuncSetAttribute((const void*)tgp<2>, cudaFuncAttributeMaxDynamicSharedMemorySize, GSMEM);
    cudaFuncSetAttribute((const void*)attn_tc, cudaFuncAttributeMaxDynamicSharedMemorySize, ASMEM);

    // 0a) weights -> fp16
    round_w5<<<(N4_TOT + 255) / 256, 256>>>(w1, wq, wk, wv, w3, wr);
    // 0b) xT[b][hw][c] fp16
    transpose_k<<<dim3(64, 32, BB), 256>>>(x, xT, CIN, NN);
    // 1) conv1 -> o1T fp16
    tgp<0><<<GRID_P, 256, GSMEM>>>(wr + WR_W1, xT, o1T, nullptr, nullptr,
                                   nullptr, g1, be1, b1);
    // 2) fused qkv -> qT/kT/v fp16 (q pre-scaled)
    tgp<1><<<GRID_P, 256, GSMEM>>>(wr + WR_WQ, o1T, qT, kT, vb,
                                   nullptr, nullptr, nullptr, nullptr);
    // 3) fully-fp16 attention -> o2T fp16
    attn_tc<<<dim3(2, 32, BB), 128, ASMEM>>>(qT, kT, vb, o1T, g2, be2, o2T);
    // 4) conv3 -> out fp32 (bn3 + resid + relu)
    tgp<2><<<GRID_P, 256, GSMEM>>>(wr + WR_W3, o2T, out, nullptr, nullptr,
                                   x, g3, be3, b3);
}

// round 17
// speedup vs baseline: 2.4079x; 1.0257x over previous
#include <cuda_runtime.h>
#include <cuda_fp16.h>
#include <cstdint>

// Problem constants
#define BB 16
#define CIN 1024
#define PP 512
#define NN 2048          // H*W
#define DH 128           // head dim
#define INVF 0.99999500003749969f      // 1/sqrt(1+1e-5)
#define QSCALE 0.08838834764831843f    // 128^-0.5
#define GRID_P 152                      // GB300 SM count (persistent grid)

#if defined(__CUDA_ARCH__) && (__CUDA_ARCH__ >= 1000) && \
    (defined(__CUDA_ARCH_FEAT_SM103_ALL) || defined(__CUDA_ARCH_FEAT_SM100_ALL) || \
     defined(__CUDA_ARCH_SPECIFIC__) || defined(__CUDA_ARCH_FAMILY_SPECIFIC__))
#define HAS_TCGEN05 1
#else
#define HAS_TCGEN05 0
#endif

// Scratch (device globals) — fully fp16 intermediates
__device__ __half g_xT [(size_t)BB * CIN * NN];   // [b][hw][c]
__device__ __half g_o1T[(size_t)BB * PP * NN];    // [b][hw][p]
__device__ __half g_qT [(size_t)BB * PP * NN];    // [b][hw][p] (pre-scaled)
__device__ __half g_kT [(size_t)BB * PP * NN];    // [b][hw][p]
__device__ __half g_v  [(size_t)BB * PP * NN];    // [b][p][hw]
__device__ __half g_o2T[(size_t)BB * PP * NN];    // [b][hw][p]
// fp16 weights, contiguous: w1 | wq | wk | wv | w3
#define WR_W1 0
#define WR_WQ (512 * 1024)
#define WR_WK (WR_WQ + 512 * 512)
#define WR_WV (WR_WK + 512 * 512)
#define WR_W3 (WR_WV + 512 * 512)
__device__ __half g_wr[WR_W3 + 1024 * 512];

// ---------------------------------------------------------------------------
__device__ __forceinline__ uint32_t smem_u32(const void* p) {
    uint32_t a;
    asm("{ .reg .u64 t; cvta.to.shared.u64 t, %1; cvt.u32.u64 %0, t; }"
        : "=r"(a) : "l"(p));
    return a;
}
__device__ __forceinline__ uint32_t h2_bits(__half2 h) {
    return *(uint32_t*)&h;
}

#if HAS_TCGEN05
__device__ __forceinline__ uint32_t elect1() {
    uint32_t p;
    asm volatile("{ .reg .pred p; elect.sync _|p, 0xFFFFFFFF; selp.b32 %0,1,0,p; }"
                 : "=r"(p));
    return p;
}
#define SW128(o) ((o) ^ ((((uint32_t)(o)) >> 3) & 0x70))

#define MBAR_INIT(a, c) \
    asm volatile("mbarrier.init.shared.b64 [%0], %1;" :: "r"(a), "r"(c) : "memory")

#define MBAR_ARRIVE(a) \
    asm volatile("mbarrier.arrive.shared::cta.b64 _, [%0];" :: "r"(a) : "memory")

#define MBAR_WAIT(a, ph) do { \
    uint32_t _d; \
    asm volatile("{ .reg .pred p; mbarrier.try_wait.parity.acquire.cta.shared::cta.b64 p,[%1],%2; selp.b32 %0,1,0,p; }" \
                 : "=r"(_d) : "r"(a), "r"((uint32_t)(ph)) : "memory"); \
    if (!_d) { \
        asm volatile("{ .reg .pred P;\nLW_%=:\nmbarrier.try_wait.parity.acquire.cta.shared::cta.b64 P,[%0],%1,0x989680;\n@P bra.uni LD_%=;\nbra.uni LW_%=;\nLD_%=:\n}" \
                     :: "r"(a), "r"((uint32_t)(ph)) : "memory"); \
    } } while (0)

#define TM_ALLOC(sa, n) \
    asm volatile("tcgen05.alloc.cta_group::1.sync.aligned.shared::cta.b32 [%0], %1;" \
                 :: "r"(sa), "r"(n) : "memory")
#define TM_DEALLOC(t, n) \
    asm volatile("tcgen05.dealloc.cta_group::1.sync.aligned.b32 %0, %1;" :: "r"(t), "r"(n))
#define TM_COMMIT(mb) \
    asm volatile("tcgen05.commit.cta_group::1.mbarrier::arrive::one.shared::cluster.b64 [%0];" \
                 :: "r"(mb) : "memory")
#define TM_FENCE_AFTER()  asm volatile("tcgen05.fence::after_thread_sync;" ::: "memory")
#define TM_FENCE_BEFORE() asm volatile("tcgen05.fence::before_thread_sync;" ::: "memory")
#define TM_WAIT_LD()      asm volatile("tcgen05.wait::ld.sync.aligned;" ::: "memory")
#define TM_WAIT_ST()      asm volatile("tcgen05.wait::st.sync.aligned;" ::: "memory")
#define FENCE_ASYNC()     asm volatile("fence.proxy.async.shared::cta;" ::: "memory")

#define CP_ASYNC16(dst, src) \
    asm volatile("cp.async.cg.shared.global [%0], [%1], 16;" \
                 :: "r"(dst), "l"(src) : "memory")
#define CP_MBAR_ARRIVE(mb) \
    asm volatile("cp.async.mbarrier.arrive.noinc.shared::cta.b64 [%0];" \
                 :: "r"(mb) : "memory")

#define TM_LD_X32(r, addr) \
    asm volatile("tcgen05.ld.sync.aligned.32x32b.x32.b32 " \
        "{%0,%1,%2,%3,%4,%5,%6,%7,%8,%9,%10,%11,%12,%13,%14,%15," \
        "%16,%17,%18,%19,%20,%21,%22,%23,%24,%25,%26,%27,%28,%29,%30,%31}, [%32];" \
        : "=r"((r)[0]),"=r"((r)[1]),"=r"((r)[2]),"=r"((r)[3]), \
          "=r"((r)[4]),"=r"((r)[5]),"=r"((r)[6]),"=r"((r)[7]), \
          "=r"((r)[8]),"=r"((r)[9]),"=r"((r)[10]),"=r"((r)[11]), \
          "=r"((r)[12]),"=r"((r)[13]),"=r"((r)[14]),"=r"((r)[15]), \
          "=r"((r)[16]),"=r"((r)[17]),"=r"((r)[18]),"=r"((r)[19]), \
          "=r"((r)[20]),"=r"((r)[21]),"=r"((r)[22]),"=r"((r)[23]), \
          "=r"((r)[24]),"=r"((r)[25]),"=r"((r)[26]),"=r"((r)[27]), \
          "=r"((r)[28]),"=r"((r)[29]),"=r"((r)[30]),"=r"((r)[31]) \
        : "r"(addr))

#define TM_ST_X16(addr, r) \
    asm volatile("tcgen05.st.sync.aligned.32x32b.x16.b32 [%0], " \
        "{%1,%2,%3,%4,%5,%6,%7,%8,%9,%10,%11,%12,%13,%14,%15,%16};" \
        :: "r"(addr), \
           "r"((r)[0]),"r"((r)[1]),"r"((r)[2]),"r"((r)[3]), \
           "r"((r)[4]),"r"((r)[5]),"r"((r)[6]),"r"((r)[7]), \
           "r"((r)[8]),"r"((r)[9]),"r"((r)[10]),"r"((r)[11]), \
           "r"((r)[12]),"r"((r)[13]),"r"((r)[14]),"r"((r)[15]) \
        : "memory")

__device__ __forceinline__ uint64_t mkdesc(uint32_t addr) {
    return ((uint64_t)2 << 61) | ((uint64_t)1 << 46) | ((uint64_t)64 << 32) |
           ((uint64_t)1 << 16) | ((addr >> 4) & 0x3FFF);
}
__device__ __forceinline__ void mma_ss_f16(uint32_t d, uint64_t ad, uint64_t bd,
                                           uint32_t id, uint32_t en) {
    asm volatile(
        "{ .reg .pred p; setp.ne.u32 p, %5, 0;\n\t"
        "tcgen05.mma.cta_group::1.kind::f16 [%0], %1, %2, %3, {%4,%4,%4,%4}, p;\n\t}"
        :: "r"(d), "l"(ad), "l"(bd), "r"(id), "r"(0u), "r"(en) : "memory");
}
__device__ __forceinline__ void mma_ts_f16(uint32_t d, uint32_t a, uint64_t bd,
                                           uint32_t id, uint32_t en) {
    asm volatile(
        "{ .reg .pred p; setp.ne.u32 p, %5, 0;\n\t"
        "tcgen05.mma.cta_group::1.kind::f16 [%0], [%1], %2, %3, {%4,%4,%4,%4}, p;\n\t}"
        :: "r"(d), "r"(a), "l"(bd), "r"(id), "r"(0u), "r"(en) : "memory");
}
// f16 (atype=btype=0), F32 accum
#define IDESC_H256 ((1u << 4) | (32u << 17) | (8u << 24))
#define IDESC_H128 ((1u << 4) | (16u << 17) | (8u << 24))
#endif  // HAS_TCGEN05

// ---------------------------------------------------------------------------
// Weights -> fp16 (one launch, contiguous g_wr)
// ---------------------------------------------------------------------------
#define N4_W1 131072
#define N4_P  65536
#define N4_W3 131072
#define N4_TOT (N4_W1 + 3 * N4_P + N4_W3)

__global__ __launch_bounds__(256)
void round_w5(const float* __restrict__ w1, const float* __restrict__ wq,
              const float* __restrict__ wk, const float* __restrict__ wv,
              const float* __restrict__ w3, __half* __restrict__ out)
{
    int i = blockIdx.x * 256 + threadIdx.x;
    if (i >= N4_TOT) return;
    const float4* src;
    int j = i;
    if (j < N4_W1) src = (const float4*)w1;
    else if ((j -= N4_W1) < N4_P) src = (const float4*)wq;
    else if ((j -= N4_P) < N4_P) src = (const float4*)wk;
    else if ((j -= N4_P) < N4_P) src = (const float4*)wv;
    else { j -= N4_P; src = (const float4*)w3; }
    float4 v = src[j];
    __half2* o = (__half2*)(out + (size_t)i * 4);
    o[0] = __floats2half2_rn(v.x, v.y);
    o[1] = __floats2half2_rn(v.z, v.w);
}

// ---------------------------------------------------------------------------
// Tiled transpose per batch, fp32 in -> fp16 out
// ---------------------------------------------------------------------------
__global__ __launch_bounds__(256)
void transpose_k(const float* __restrict__ in, __half* __restrict__ out, int R, int C)
{
    __shared__ float tile[32][33];
    const int b = blockIdx.z;
    const float* ip = in + (size_t)b * R * C;
    __half* op = out + (size_t)b * R * C;
    const int c0 = blockIdx.x * 32, r0 = blockIdx.y * 32;
    const int tx = threadIdx.x & 31, ty = threadIdx.x >> 5;
#pragma unroll
    for (int i = 0; i < 32; i += 8)
        tile[ty + i][tx] = ip[(size_t)(r0 + ty + i) * C + c0 + tx];
    __syncthreads();
#pragma unroll
    for (int i = 0; i < 32; i += 8)
        op[(size_t)(c0 + ty + i) * R + r0 + tx] = __float2half_rn(tile[tx][ty + i]);
}

// ---------------------------------------------------------------------------
// Warp-specialized persistent tcgen05 fp16 GEMM (R16 verified, unchanged).
// ---------------------------------------------------------------------------
#define NSTAGE 4
#define STAGE_B 49152u
#define GS_BN   (1024u + NSTAGE * STAGE_B)
#define GSMEM   (GS_BN + 2 * 1024 * 4)

template <int MODE>
__device__ __forceinline__ void tile_ab(int id, const __half* W, const __half* ACT,
                                        const __half*& A, const __half*& B)
{
    if (MODE == 0) {
        int m0 = (id & 3) << 7, n0 = ((id >> 2) & 7) << 8, bz = id >> 5;
        A = W + (size_t)m0 * 1024;
        B = ACT + ((size_t)bz * NN + n0) * 1024;
    } else if (MODE == 1) {
        if (id < 1024) {
            int m0 = (id & 7) << 7, n0 = ((id >> 3) & 7) << 8, bz = id >> 6;
            A = W + (size_t)m0 * 512;
            B = ACT + ((size_t)bz * NN + n0) * 512;
        } else {
            int j = id - 1024;
            int m0 = (j & 15) << 7, n0 = ((j >> 4) & 1) << 8, bz = j >> 5;
            A = ACT + ((size_t)bz * NN + m0) * 512;
            B = W + 524288u + (size_t)n0 * 512;
        }
    } else {
        int m0 = (id & 15) << 7, n0 = ((id >> 4) & 3) << 8, bz = id >> 6;
        A = ACT + ((size_t)bz * NN + m0) * 512;
        B = W + (size_t)n0 * 512;
    }
}

template <int MODE>
__device__ __forceinline__ void epi_scalar(int id, int ml, int n, float acc,
    void* O0v, void* O1v, void* O2v, const float* resid,
    const float* g, const float* be, const float* cb)
{
    if (MODE == 0) {
        int m0 = (id & 3) << 7, n0 = ((id >> 2) & 7) << 8, bz = id >> 5;
        int m = m0 + ml;
        float s = g[m] * INVF, tt = cb[m] * s + be[m];
        ((__half*)O0v)[((size_t)bz * NN + n0 + n) * 512 + m] =
            __float2half_rn(fmaxf(fmaf(acc, s, tt), 0.f));
    } else if (MODE == 1) {
        if (id < 1024) {
            int m0 = (id & 7) << 7, n0 = ((id >> 3) & 7) << 8, bz = id >> 6;
            __half* T = (m0 < 512) ? (__half*)O0v : (__half*)O1v;
            float qs = (m0 < 512) ? QSCALE : 1.f;
            T[((size_t)bz * NN + n0 + n) * 512 + ((m0 + ml) & 511)] =
                __float2half_rn(acc * qs);
        } else {
            int j = id - 1024;
            int m0 = (j & 15) << 7, n0 = ((j >> 4) & 1) << 8, bz = j >> 5;
            ((__half*)O2v)[((size_t)bz * 512 + n0 + n) * NN + m0 + ml] =
                __float2half_rn(acc);
        }
    } else {
        int m0 = (id & 15) << 7, n0 = ((id >> 4) & 3) << 8, bz = id >> 6;
        int c = n0 + n;
        float s = g[c] * INVF, tt = cb[c] * s + be[c];
        size_t off = ((size_t)bz * 1024 + c) * NN + m0 + ml;
        ((float*)O0v)[off] = fmaxf(fmaf(acc, s, tt) + resid[off], 0.f);
    }
}

#if HAS_TCGEN05
template <int MODE>
__device__ __forceinline__ void issue_chunk(uint32_t sbase, int gc, int cta,
                                            const __half* W, const __half* ACT, int t)
{
    constexpr int NKS = (MODE == 0) ? 4 : 3;
    constexpr int K = (MODE == 0) ? 1024 : 512;
    const int lt = gc >> NKS, c = gc & ((1 << NKS) - 1);
    const __half *A, *B;
    tile_ab<MODE>(cta + lt * GRID_P, W, ACT, A, B);
    const uint32_t st = sbase + 1024u + (uint32_t)(gc & 3) * STAGE_B;
#pragma unroll
    for (int r = 0; r < 8; r++) {
        int idx = t + r * 128, row = idx >> 3, seg = idx & 7;
        CP_ASYNC16(st + SW128(row * 128 + seg * 16),
                   A + (size_t)row * K + c * 64 + seg * 8);
    }
#pragma unroll
    for (int r = 0; r < 16; r++) {
        int idx = t + r * 128, row = idx >> 3, seg = idx & 7;
        CP_ASYNC16(st + 16384u + SW128(row * 128 + seg * 16),
                   B + (size_t)row * K + c * 64 + seg * 8);
    }
    CP_MBAR_ARRIVE(sbase + 16 + 8 * (gc & 3));
}

template <int MODE>
__device__ __forceinline__ void epi_tile(int id, int abuf, uint32_t tmem, char* smem,
    void* O0v, void* O1v, void* O2v, const float* resid,
    const float* g, const float* be, const float* cb, int wid, int lane)
{
    __half* Oh = nullptr; float* Of = nullptr;
    const float* Rb = nullptr;
    size_t sN; int n0g = 0, m0;
    float qs = 1.f;
    if (MODE == 0) {
        m0 = (id & 3) << 7; int n0 = ((id >> 2) & 7) << 8; int bz = id >> 5;
        Oh = (__half*)O0v + ((size_t)bz * NN + n0) * 512 + m0;  sN = 512;
    } else if (MODE == 1) {
        if (id < 1024) {
            m0 = (id & 7) << 7; int n0 = ((id >> 3) & 7) << 8; int bz = id >> 6;
            __half* T = (m0 < 512) ? (__half*)O0v : (__half*)O1v;
            if (m0 < 512) qs = QSCALE;
            Oh = T + ((size_t)bz * NN + n0) * 512 + (m0 & 511);  sN = 512;
        } else {
            int j = id - 1024;
            m0 = (j & 15) << 7; int n0 = ((j >> 4) & 1) << 8; int bz = j >> 5;
            Oh = (__half*)O2v + ((size_t)bz * 512 + n0) * NN + m0;  sN = NN;
        }
    } else {
        m0 = (id & 15) << 7; int n0 = ((id >> 4) & 3) << 8; int bz = id >> 6;
        Of = (float*)O0v + ((size_t)bz * 1024 + n0) * NN + m0;
        Rb = resid + ((size_t)bz * 1024 + n0) * NN + m0;
        sN = NN; n0g = n0;
    }
    const int ml = (wid & 3) * 32 + lane;
    float sL = qs, tL = 0.f;
    if (MODE == 0) { int m = m0 + ml; sL = g[m] * INVF; tL = cb[m] * sL + be[m]; }
    const float* bs = (const float*)(smem + GS_BN);
    const float* bt = (const float*)(smem + GS_BN + 4096);

    uint32_t r0[32];
#pragma unroll
    for (int k = 0; k < 8; k++) {
        TM_LD_X32(r0, tmem + abuf * 256 + k * 32);
        TM_WAIT_LD();
#pragma unroll
        for (int i = 0; i < 32; i++) {
            const int n = k * 32 + i;
            float v = __uint_as_float(r0[i]);
            if (MODE == 2) {
                v = fmaxf(fmaf(v, bs[n0g + n], bt[n0g + n]) + Rb[(size_t)n * sN + ml], 0.f);
                Of[(size_t)n * sN + ml] = v;
            } else if (MODE == 0) {
                Oh[(size_t)n * sN + ml] =
                    __float2half_rn(fmaxf(fmaf(v, sL, tL), 0.f));
            } else {
                Oh[(size_t)n * sN + ml] = __float2half_rn(v * sL);
            }
        }
    }
}
#endif  // HAS_TCGEN05

template <int MODE>
__global__ __launch_bounds__(256)
void tgp(const __half* __restrict__ W, const __half* __restrict__ ACT,
         void* __restrict__ O0v, void* __restrict__ O1v, void* __restrict__ O2v,
         const float* __restrict__ resid,
         const float* __restrict__ g, const float* __restrict__ be,
         const float* __restrict__ cb)
{
    constexpr int TOT   = (MODE == 0) ? 512 : (MODE == 1) ? 1536 : 1024;
    constexpr int NKS   = (MODE == 0) ? 4 : 3;
    constexpr int NK    = 1 << NKS;
    const int cta = blockIdx.x;
    const int t = threadIdx.x;
    const int ntl = (TOT - cta + GRID_P - 1) / GRID_P;
    if (ntl <= 0) return;
    const int totc = ntl * NK;

#if HAS_TCGEN05
    extern __shared__ char smem[];
    const uint32_t sbase = smem_u32(smem);
    const int wid = t >> 5, lane = t & 31;
    if (t < 4)                MBAR_INIT(sbase + 16 + 8 * t, 128);
    else if (t < 8)           MBAR_INIT(sbase + 48 + 8 * (t - 4), 1);
    else if (t < 10)          MBAR_INIT(sbase + 80 + 8 * (t - 8), 1);
    else if (t < 12)          MBAR_INIT(sbase + 96 + 8 * (t - 10), 128);
    if (wid == 0) TM_ALLOC(sbase + 0, 512);
    if (MODE == 2) {
        for (int i = t; i < 1024; i += 256) {
            float s = g[i] * INVF;
            ((float*)(smem + GS_BN))[i] = s;
            ((float*)(smem + GS_BN + 4096))[i] = cb[i] * s + be[i];
        }
    }
    __syncthreads();
    uint32_t tmem;
    asm volatile("ld.shared.b32 %0, [%1];" : "=r"(tmem) : "r"(sbase + 0));

    if (t < 128) {
        issue_chunk<MODE>(sbase, 0, cta, W, ACT, t);
        if (totc > 1) issue_chunk<MODE>(sbase, 1, cta, W, ACT, t);
        if (totc > 2) issue_chunk<MODE>(sbase, 2, cta, W, ACT, t);

        for (int gc = 0; gc < totc; gc++) {
            const int s = gc & 3, c = gc & (NK - 1), lt = gc >> NKS;
            if (wid == 0 && elect1()) {
                if (c == 0 && lt >= 2) {
                    MBAR_WAIT(sbase + 96 + 8 * (lt & 1), ((lt >> 1) - 1) & 1);
                    TM_FENCE_AFTER();
                }
                MBAR_WAIT(sbase + 16 + 8 * s, (gc >> 2) & 1);
                FENCE_ASYNC();
                const uint32_t st = sbase + 1024u + (uint32_t)s * STAGE_B;
                const uint64_t ad = mkdesc(st);
                const uint64_t bd = mkdesc(st + 16384u);
                const uint32_t dacc = tmem + (uint32_t)((lt & 1) << 8);
#pragma unroll
                for (int si = 0; si < 4; si++)
                    mma_ss_f16(dacc, ad + si * 2, bd + si * 2, IDESC_H256,
                               (c > 0 || si > 0) ? 1u : 0u);
                TM_COMMIT(sbase + 48 + 8 * s);
            }
            if (gc >= 1) {
                MBAR_WAIT(sbase + 48 + 8 * ((gc - 1) & 3), ((gc - 1) >> 2) & 1);
                if (c == 0 && wid == 0 && elect1())
                    MBAR_ARRIVE(sbase + 80 + 8 * ((lt - 1) & 1));
            }
            if (gc + 3 < totc) issue_chunk<MODE>(sbase, gc + 3, cta, W, ACT, t);
        }
        MBAR_WAIT(sbase + 48 + 8 * ((totc - 1) & 3), ((totc - 1) >> 2) & 1);
        if (wid == 0 && elect1())
            MBAR_ARRIVE(sbase + 80 + 8 * ((ntl - 1) & 1));
    } else {
        for (int lt = 0; lt < ntl; lt++) {
            MBAR_WAIT(sbase + 80 + 8 * (lt & 1), (lt >> 1) & 1);
            TM_FENCE_AFTER();
            epi_tile<MODE>(cta + lt * GRID_P, lt & 1, tmem, smem,
                           O0v, O1v, O2v, resid, g, be, cb, wid, lane);
            TM_FENCE_BEFORE();
            MBAR_ARRIVE(sbase + 96 + 8 * (lt & 1));
        }
    }
    __syncthreads();
    if (wid == 0) TM_DEALLOC(tmem, 512);

#else  // fp32 fallback
    constexpr int K = (MODE == 0) ? 1024 : 512;
    for (int lt = 0; lt < ntl; lt++) {
        const int id = cta + lt * GRID_P;
        const __half *A, *B;
        tile_ab<MODE>(id, W, ACT, A, B);
        for (int e = t; e < 128 * 256; e += 256) {
            const int ml = e & 127, n = e >> 7;
            float acc = 0.f;
            for (int k = 0; k < K; k++)
                acc += __half2float(A[(size_t)ml * K + k]) *
                       __half2float(B[(size_t)n * K + k]);
            epi_scalar<MODE>(id, ml, n, acc, O0v, O1v, O2v, resid, g, be, cb);
        }
    }
#endif
}

// ---------------------------------------------------------------------------
// Persistent pipelined fp16 attention: 152 CTAs, ~7 tiles each, single
// Q/K/V buffer set; QK(i+1) issued after softmax(i) (K freed by S-done),
// V(i+1) issued after PV-done(i). Each of the 4 barriers (qkf/vf cnt128,
// smb/pvb cnt1) completes exactly once per iteration; waits use phase it&1
// -> <=1 phase skew by construction.
// TMEM: S[0,256) fp32 | P[256,384) fp16-packed | O[384,512) fp32.
// bn2 tables double-buffered (tbl[it&1]) to tolerate thread skew into epi.
// ---------------------------------------------------------------------------
#define AS_TBL 2048u
#define AS_Q   4096u
#define AS_K   (AS_Q + 32768u)
#define AS_V   (AS_K + 65536u)
#define ASMEM  (AS_V + 65536u)   // 167936

#define NT_ATT 1024

#if HAS_TCGEN05
__device__ __forceinline__ void att_ptrs(int id, const __half* qT,
    const __half* kT, const __half* v, const __half* o1T, __half* o2T,
    const __half*& qp, const __half*& kp, const __half*& vp,
    const __half*& o1p, __half*& o2p, int& hh)
{
    const int xt = id & 1, hy = (id >> 1) & 31, b = id >> 6;
    const int sp = hy >> 2;
    hh = hy & 3;
    const size_t qrow = (size_t)b * NN + sp * 256 + xt * 128;
    qp  = qT  + qrow * PP + hh * DH;
    kp  = kT  + ((size_t)b * NN + sp * 256) * PP + hh * DH;
    vp  = v   + ((size_t)b * PP + hh * DH) * NN + sp * 256;
    o1p = o1T + qrow * PP + hh * DH;
    o2p = (__half*)o2T + qrow * PP + hh * DH;
}

__device__ __forceinline__ void att_issue_qk(uint32_t sbase, const __half* qp,
                                             const __half* kp, int t)
{
#pragma unroll
    for (int r = 0; r < 16; r++) {
        int i = t + r * 128, row = i >> 4, s16 = i & 15;
        int j = s16 >> 3, sg = s16 & 7;
        CP_ASYNC16(sbase + AS_Q + j * 16384u + SW128(row * 128 + sg * 16),
                   qp + (size_t)row * PP + s16 * 8);
    }
#pragma unroll
    for (int r = 0; r < 32; r++) {
        int i = t + r * 128, row = i >> 4, s16 = i & 15;
        int j = s16 >> 3, sg = s16 & 7;
        CP_ASYNC16(sbase + AS_K + j * 32768u + SW128(row * 128 + sg * 16),
                   kp + (size_t)row * PP + s16 * 8);
    }
    CP_MBAR_ARRIVE(sbase + 16);
}

__device__ __forceinline__ void att_issue_v(uint32_t sbase, const __half* vp, int t)
{
#pragma unroll
    for (int r = 0; r < 32; r++) {
        int i = t + r * 128, row = i >> 5, s32 = i & 31;
        int j = s32 >> 3, sg = s32 & 7;
        CP_ASYNC16(sbase + AS_V + j * 16384u + SW128(row * 128 + sg * 16),
                   vp + (size_t)row * NN + s32 * 8);
    }
    CP_MBAR_ARRIVE(sbase + 24);
}
#endif  // HAS_TCGEN05

__global__ __launch_bounds__(128)
void attn_tc(const __half* __restrict__ qT, const __half* __restrict__ kT,
             const __half* __restrict__ v, const __half* __restrict__ o1T,
             const float* __restrict__ g2, const float* __restrict__ be2,
             __half* __restrict__ o2T)
{
    const int cta = blockIdx.x;
    const int t = threadIdx.x, wid = t >> 5, lane = t & 31;
    const int ntl = (NT_ATT - cta + GRID_P - 1) / GRID_P;
    if (ntl <= 0) return;

#if HAS_TCGEN05
    extern __shared__ char sm[];
    const uint32_t sbase = smem_u32(sm);
    // mbars: qkf@16(128) vf@24(128) smb@32(1) pvb@40(1); one event per iter
    if (t == 0) { MBAR_INIT(sbase + 16, 128); MBAR_INIT(sbase + 24, 128);
                  MBAR_INIT(sbase + 32, 1);   MBAR_INIT(sbase + 40, 1); }
    if (wid == 0) TM_ALLOC(sbase + 0, 512);
    __syncthreads();
    uint32_t tmem;
    asm volatile("ld.shared.b32 %0, [%1];" : "=r"(tmem) : "r"(sbase + 0));

    // prologue: tile 0 loads
    {
        const __half *qp, *kp, *vp, *o1p; __half* o2p; int hh;
        att_ptrs(cta, qT, kT, v, o1T, o2T, qp, kp, vp, o1p, o2p, hh);
        att_issue_qk(sbase, qp, kp, t);
        att_issue_v(sbase, vp, t);
    }

    for (int it = 0; it < ntl; it++) {
        const int id = cta + it * GRID_P;
        const __half *qp, *kp, *vp, *o1p; __half* o2p; int hh;
        att_ptrs(id, qT, kT, v, o1T, o2T, qp, kp, vp, o1p, o2p, hh);
        const uint32_t ph = it & 1;

        // ---- S = Q.K^T ----
        MBAR_WAIT(sbase + 16, ph);
        if (wid == 0 && elect1()) {
            FENCE_ASYNC();
#pragma unroll
            for (int j = 0; j < 2; j++) {
                uint64_t qd = mkdesc(sbase + AS_Q + j * 16384u);
                uint64_t kd = mkdesc(sbase + AS_K + j * 32768u);
#pragma unroll
                for (int s = 0; s < 4; s++)
                    mma_ss_f16(tmem, qd + s * 2, kd + s * 2, IDESC_H256,
                               (j > 0 || s > 0) ? 1u : 0u);
            }
            TM_COMMIT(sbase + 32);
        }
        MBAR_WAIT(sbase + 32, ph);
        TM_FENCE_AFTER();

        // ---- softmax; P fp16-packed into cols 256..384; bn2 tables ----
        float* tg = (float*)(sm + AS_TBL + ph * 1024);
        tg[t] = g2[hh * DH + t] * INVF;
        tg[128 + t] = be2[hh * DH + t];

        uint32_t rs[32];
        float mx = -1e30f;
#pragma unroll
        for (int cc = 0; cc < 8; cc++) {
            TM_LD_X32(rs, tmem + cc * 32);
            TM_WAIT_LD();
#pragma unroll
            for (int i = 0; i < 32; i++) mx = fmaxf(mx, __uint_as_float(rs[i]));
        }
        float ssum = 0.f;
#pragma unroll
        for (int cc = 0; cc < 8; cc++) {
            TM_LD_X32(rs, tmem + cc * 32);
            TM_WAIT_LD();
            uint32_t pk[16];
#pragma unroll
            for (int i = 0; i < 32; i += 2) {
                float e0 = __expf(__uint_as_float(rs[i]) - mx);
                float e1 = __expf(__uint_as_float(rs[i + 1]) - mx);
                ssum += e0 + e1;
                __half2 hp = __floats2half2_rn(e0, e1);
                pk[i >> 1] = h2_bits(hp);
            }
            TM_ST_X16(tmem + 256 + cc * 16, pk);
        }
        TM_WAIT_ST();
        const float sinv = 1.f / ssum;
        TM_FENCE_BEFORE();
        __syncthreads();          // P + tables visible; all threads past epi(it-1)

        // ---- QK buffers free (S done): prefetch next tile's Q/K ----
        if (it + 1 < ntl) {
            const __half *qp2, *kp2, *vp2, *o1p2; __half* o2p2; int hh2;
            att_ptrs(id + GRID_P, qT, kT, v, o1T, o2T, qp2, kp2, vp2, o1p2, o2p2, hh2);
            att_issue_qk(sbase, qp2, kp2, t);
        }

        // ---- PV = P.V ----
        MBAR_WAIT(sbase + 24, ph);
        if (wid == 0 && elect1()) {
            TM_FENCE_AFTER();
            FENCE_ASYNC();
#pragma unroll
            for (int j = 0; j < 4; j++) {
                uint64_t vd = mkdesc(sbase + AS_V + j * 16384u);
#pragma unroll
                for (int s = 0; s < 4; s++)
                    mma_ts_f16(tmem + 384, tmem + 256 + j * 32 + s * 8,
                               vd + s * 2, IDESC_H128,
                               (j > 0 || s > 0) ? 1u : 0u);
            }
            TM_COMMIT(sbase + 40);
        }
        MBAR_WAIT(sbase + 40, ph);
        TM_FENCE_AFTER();

        // ---- V buffer free (PV done): prefetch next tile's V ----
        if (it + 1 < ntl) {
            const __half *qp2, *kp2, *vp2, *o1p2; __half* o2p2; int hh2;
            att_ptrs(id + GRID_P, qT, kT, v, o1T, o2T, qp2, kp2, vp2, o1p2, o2p2, hh2);
            att_issue_v(sbase, vp2, t);
        }

        // ---- epilogue: (O*sinv + o1h)*g2' + be2, relu -> o2T fp16 ----
        const float* g2s  = tg;
        const float* be2s = tg + 128;
        const __half* myo1 = o1p + (size_t)(wid * 32 + lane) * PP;
        __half* myo2       = o2p + (size_t)(wid * 32 + lane) * PP;
#pragma unroll
        for (int k = 0; k < 4; k++) {
            TM_LD_X32(rs, tmem + 384 + k * 32);
            TM_WAIT_LD();
#pragma unroll
            for (int i = 0; i < 32; i += 4) {
                int d = k * 32 + i;
                uint2 h4 = *(const uint2*)(myo1 + d);
                float2 r01 = __half22float2(*(__half2*)&h4.x);
                float2 r23 = __half22float2(*(__half2*)&h4.y);
                float o0 = fmaxf(fmaf(fmaf(__uint_as_float(rs[i + 0]), sinv, r01.x), g2s[d + 0], be2s[d + 0]), 0.f);
                float o1 = fmaxf(fmaf(fmaf(__uint_as_float(rs[i + 1]), sinv, r01.y), g2s[d + 1], be2s[d + 1]), 0.f);
                float o2 = fmaxf(fmaf(fmaf(__uint_as_float(rs[i + 2]), sinv, r23.x), g2s[d + 2], be2s[d + 2]), 0.f);
                float o3 = fmaxf(fmaf(fmaf(__uint_as_float(rs[i + 3]), sinv, r23.y), g2s[d + 3], be2s[d + 3]), 0.f);
                uint2 oh;
                *(__half2*)&oh.x = __floats2half2_rn(o0, o1);
                *(__half2*)&oh.y = __floats2half2_rn(o2, o3);
                *(uint2*)(myo2 + d) = oh;
            }
        }
        TM_FENCE_BEFORE();
    }
    __syncthreads();
    if (wid == 0) TM_DEALLOC(tmem, 512);

#else  // fp32 fallback
    for (int it = 0; it < ntl; it++) {
        const int id = cta + it * GRID_P;
        const int xt = id & 1, hy = (id >> 1) & 31, b = id >> 6;
        const int sp = hy >> 2, hh = hy & 3;
        const size_t qrow = (size_t)b * NN + sp * 256 + xt * 128;
        const __half* qp  = qT  + qrow * PP + hh * DH;
        const __half* kp  = kT  + ((size_t)b * NN + sp * 256) * PP + hh * DH;
        const __half* vp  = v   + ((size_t)b * PP + hh * DH) * NN + sp * 256;
        const __half* o1p = o1T + qrow * PP + hh * DH;
        __half* o2p       = o2T + qrow * PP + hh * DH;
        const int x = t;
        float sb[256];
        float mx = -1e30f;
        for (int y = 0; y < 256; y++) {
            float s = 0.f;
            for (int d = 0; d < DH; d++)
                s += __half2float(qp[(size_t)x * PP + d]) *
                     __half2float(kp[(size_t)y * PP + d]);
            sb[y] = s;
            mx = fmaxf(mx, s);
        }
        float ssum = 0.f;
        for (int y = 0; y < 256; y++) { sb[y] = __expf(sb[y] - mx); ssum += sb[y]; }
        float sinv = 1.f / ssum;
        for (int d = 0; d < DH; d++) {
            float o = 0.f;
            for (int y = 0; y < 256; y++)
                o += sb[y] * __half2float(vp[(size_t)d * NN + y]);
            float val = (o * sinv + __half2float(o1p[(size_t)x * PP + d]))
                        * (g2[hh * DH + d] * INVF) + be2[hh * DH + d];
            o2p[(size_t)x * PP + d] = __float2half_rn(fmaxf(val, 0.f));
        }
    }
#endif
}

// ---------------------------------------------------------------------------
extern "C" void kernel_launch(void* const* d_in, const int* in_sizes, int n_in,
                              void* d_out, int out_size)
{
    const float* x   = (const float*)d_in[0];
    const float* w1  = (const float*)d_in[1];
    const float* b1  = (const float*)d_in[2];
    const float* g1  = (const float*)d_in[3];
    const float* be1 = (const float*)d_in[4];
    const float* wq  = (const float*)d_in[5];
    const float* wk  = (const float*)d_in[6];
    const float* wv  = (const float*)d_in[7];
    const float* g2  = (const float*)d_in[8];
    const float* be2 = (const float*)d_in[9];
    const float* w3  = (const float*)d_in[10];
    const float* b3  = (const float*)d_in[11];
    const float* g3  = (const float*)d_in[12];
    const float* be3 = (const float*)d_in[13];
    float* out = (float*)d_out;

    __half *xT, *o1T, *qT, *kT, *vb, *o2T, *wr;
    cudaGetSymbolAddress((void**)&xT,  g_xT);
    cudaGetSymbolAddress((void**)&o1T, g_o1T);
    cudaGetSymbolAddress((void**)&qT,  g_qT);
    cudaGetSymbolAddress((void**)&kT,  g_kT);
    cudaGetSymbolAddress((void**)&vb,  g_v);
    cudaGetSymbolAddress((void**)&o2T, g_o2T);
    cudaGetSymbolAddress((void**)&wr,  g_wr);

    cudaFuncSetAttribute((const void*)tgp<0>, cudaFuncAttributeMaxDynamicSharedMemorySize, GSMEM);
    cudaFuncSetAttribute((const void*)tgp<1>, cudaFuncAttributeMaxDynamicSharedMemorySize, GSMEM);
    cudaFuncSetAttribute((const void*)tgp<2>, cudaFuncAttributeMaxDynamicSharedMemorySize, GSMEM);
    cudaFuncSetAttribute((const void*)attn_tc, cudaFuncAttributeMaxDynamicSharedMemorySize, ASMEM);

    // 0a) weights -> fp16
    round_w5<<<(N4_TOT + 255) / 256, 256>>>(w1, wq, wk, wv, w3, wr);
    // 0b) xT[b][hw][c] fp16
    transpose_k<<<dim3(64, 32, BB), 256>>>(x, xT, CIN, NN);
    // 1) conv1 -> o1T fp16
    tgp<0><<<GRID_P, 256, GSMEM>>>(wr + WR_W1, xT, o1T, nullptr, nullptr,
                                   nullptr, g1, be1, b1);
    // 2) fused qkv -> qT/kT/v fp16 (q pre-scaled)
    tgp<1><<<GRID_P, 256, GSMEM>>>(wr + WR_WQ, o1T, qT, kT, vb,
                                   nullptr, nullptr, nullptr, nullptr);
    // 3) persistent pipelined fp16 attention -> o2T fp16
    attn_tc<<<GRID_P, 128, ASMEM>>>(qT, kT, vb, o1T, g2, be2, o2T);
    // 4) conv3 -> out fp32 (bn3 + resid + relu)
    tgp<2><<<GRID_P, 256, GSMEM>>>(wr + WR_W3, o2T, out, nullptr, nullptr,
                                   x, g3, be3, b3);
}